// round 1
// baseline (speedup 1.0000x reference)
#include <cuda_runtime.h>
#include <math.h>
#include <stdint.h>

// Problem dims (fixed)
#define BB   8
#define NN   4096
#define CC   256
#define HH   8
#define DH   32
#define HW   64
#define NK   256
#define HID  1024
#define KPATCH 4096   // C * SR * SR

// ---------------- scratch (device globals; no allocation) ----------------
__device__ float g_h  [(size_t)BB*NN*CC];    // LN1 output
__device__ float g_q  [(size_t)BB*NN*CC];    // q projection
__device__ float g_hp [(size_t)BB*NK*KPATCH];// gathered patches for SR conv
__device__ float g_wt [(size_t)KPATCH*CC];   // transposed sr weights
__device__ float g_hs [(size_t)BB*NK*CC];    // SR output (+ LN in place)
__device__ float g_kv [(size_t)BB*NK*2*CC];  // kv projection
__device__ float g_o  [(size_t)BB*NN*CC];    // attention output
__device__ float g_x1 [(size_t)BB*NN*CC];    // x + proj(o)
__device__ float g_h2 [(size_t)BB*NN*CC];    // LN2 output
__device__ float g_m  [(size_t)BB*NN*HID];   // fc1 output
__device__ float g_mi [(size_t)BB*NN*HID];   // dwconv+gelu output

// ---------------- LayerNorm over last dim = 256, warp per row ----------------
__global__ void ln256(const float* __restrict__ x, const float* __restrict__ w,
                      const float* __restrict__ b, float* __restrict__ y,
                      int rows, float eps)
{
    int row  = blockIdx.x * 8 + (threadIdx.x >> 5);
    int lane = threadIdx.x & 31;
    if (row >= rows) return;
    const float* xr = x + (size_t)row * 256;
    float4 v0 = *reinterpret_cast<const float4*>(xr + lane * 8);
    float4 v1 = *reinterpret_cast<const float4*>(xr + lane * 8 + 4);
    float vals[8] = {v0.x, v0.y, v0.z, v0.w, v1.x, v1.y, v1.z, v1.w};
    float s = 0.f, sq = 0.f;
#pragma unroll
    for (int i = 0; i < 8; i++) { s += vals[i]; sq += vals[i] * vals[i]; }
#pragma unroll
    for (int o = 16; o > 0; o >>= 1) {
        s  += __shfl_xor_sync(0xffffffffu, s, o);
        sq += __shfl_xor_sync(0xffffffffu, sq, o);
    }
    float mean = s * (1.0f / 256.0f);
    float var  = sq * (1.0f / 256.0f) - mean * mean;
    float rs   = rsqrtf(var + eps);
    float* yr = y + (size_t)row * 256;
#pragma unroll
    for (int i = 0; i < 8; i++) {
        int c = lane * 8 + i;
        yr[c] = (vals[i] - mean) * rs * w[c] + b[c];
    }
}

// ---------------- SGEMM: C = A[M,K] @ B[K,N] + bias (+ res), 128x128x8 ----------------
__global__ void sgemm128(const float* __restrict__ A, const float* __restrict__ B,
                         const float* __restrict__ bias, const float* __restrict__ res,
                         float* __restrict__ C, int M, int N, int K)
{
    const int BM = 128, BN = 128, BK = 8;
    __shared__ float As[BK][BM];
    __shared__ float Bs[BK][BN];
    int bx = blockIdx.x, by = blockIdx.y;
    int tid = threadIdx.x;                 // 256 threads
    int tx = tid & 15, ty = tid >> 4;
    int aRow = tid >> 1;                   // 0..127
    int aCol = (tid & 1) << 2;             // 0 or 4
    int bRow = tid >> 5;                   // 0..7
    int bCol = (tid & 31) << 2;            // 0..124
    const float* Ab = A + (size_t)by * BM * K;
    const float* Bb = B + (size_t)bx * BN;

    float acc[8][8];
#pragma unroll
    for (int i = 0; i < 8; i++)
#pragma unroll
        for (int j = 0; j < 8; j++) acc[i][j] = 0.f;

    for (int k0 = 0; k0 < K; k0 += BK) {
        float4 a4 = *reinterpret_cast<const float4*>(Ab + (size_t)aRow * K + k0 + aCol);
        As[aCol + 0][aRow] = a4.x;
        As[aCol + 1][aRow] = a4.y;
        As[aCol + 2][aRow] = a4.z;
        As[aCol + 3][aRow] = a4.w;
        float4 b4 = *reinterpret_cast<const float4*>(Bb + (size_t)(k0 + bRow) * N + bCol);
        *reinterpret_cast<float4*>(&Bs[bRow][bCol]) = b4;
        __syncthreads();
#pragma unroll
        for (int k = 0; k < BK; k++) {
            float ar[8], br[8];
#pragma unroll
            for (int i = 0; i < 8; i++) ar[i] = As[k][ty * 8 + i];
#pragma unroll
            for (int j = 0; j < 8; j++) br[j] = Bs[k][tx * 8 + j];
#pragma unroll
            for (int i = 0; i < 8; i++)
#pragma unroll
                for (int j = 0; j < 8; j++) acc[i][j] += ar[i] * br[j];
        }
        __syncthreads();
    }

#pragma unroll
    for (int i = 0; i < 8; i++) {
        int row = by * BM + ty * 8 + i;
#pragma unroll
        for (int j = 0; j < 8; j++) {
            int col = bx * BN + tx * 8 + j;
            float v = acc[i][j] + bias[col];
            if (res) v += res[(size_t)row * N + col];
            C[(size_t)row * N + col] = v;
        }
    }
}

// ---------------- patch gather for SR conv: hp[b][nk][(ky*4+kx)*256+ci] ----------------
__global__ void patchify(const float* __restrict__ h, float* __restrict__ hp)
{
    size_t idx = (size_t)blockIdx.x * blockDim.x + threadIdx.x;  // B*NK*4096
    int ci = idx & 255;
    size_t t = idx >> 8;
    int ks = t & 15;  t >>= 4;
    int nk = t & 255; int b = t >> 8;
    int ky = ks >> 2, kx = ks & 3;
    int py = nk >> 4, px = nk & 15;
    int n = (py * 4 + ky) * HW + px * 4 + kx;
    hp[idx] = h[((size_t)b * NN + n) * CC + ci];
}

// ---------------- weight transpose: wt[(ky*4+kx)*256+ci][co] = sr_w[co][ci][ky][kx] ----
__global__ void wtrans(const float* __restrict__ srw, float* __restrict__ wt)
{
    int idx = blockIdx.x * blockDim.x + threadIdx.x;  // 4096*256
    int co = idx & 255;
    int r  = idx >> 8;       // ks*256 + ci
    int ks = r >> 8;
    int ci = r & 255;
    wt[idx] = srw[(size_t)co * KPATCH + ci * 16 + ks];
}

// ---------------- fused SR attention: per (b, h, 64-row q tile) ----------------
// smem: Qs[64][33] + Ks[256][33] + Vs[256][33] + S[64][257]
#define ATTN_SMEM_FLOATS (64*33 + 256*33 + 256*33 + 64*257)
__global__ void attn_kernel(const float* __restrict__ q, const float* __restrict__ kv,
                            const float* __restrict__ pos, const float* __restrict__ alpha,
                            float* __restrict__ o)
{
    extern __shared__ float sm[];
    float* Qs = sm;                  // 64*33
    float* Ks = Qs + 64 * 33;        // 256*33
    float* Vs = Ks + 256 * 33;       // 256*33
    float* S  = Vs + 256 * 33;       // 64*257

    int n0 = blockIdx.x * 64;
    int hh = blockIdx.y;
    int b  = blockIdx.z;
    int tid = threadIdx.x;           // 256

    // load K,V tiles [256 x 32]
    for (int idx = tid; idx < 256 * 32; idx += 256) {
        int m = idx >> 5, d = idx & 31;
        const float* kvrow = kv + ((size_t)b * NK + m) * (2 * CC);
        Ks[m * 33 + d] = kvrow[hh * DH + d];
        Vs[m * 33 + d] = kvrow[CC + hh * DH + d];
    }
    // load Q tile [64 x 32]
    for (int idx = tid; idx < 64 * 32; idx += 256) {
        int r = idx >> 5, d = idx & 31;
        Qs[r * 33 + d] = q[((size_t)b * NN + n0 + r) * CC + hh * DH + d];
    }
    __syncthreads();

    int warp = tid >> 5, lane = tid & 31;
    const float scale = 0.17677669529663687f;   // 1/sqrt(32)
    float a = alpha[0];

    // scores + softmax + blend; warp handles rows warp*8 .. warp*8+7
    for (int rr = 0; rr < 8; rr++) {
        int r = warp * 8 + rr;
        float qreg[32];
#pragma unroll
        for (int d = 0; d < 32; d++) qreg[d] = Qs[r * 33 + d];
        float sc[8];
#pragma unroll
        for (int cc = 0; cc < 8; cc++) {
            int c = cc * 32 + lane;
            float s = 0.f;
#pragma unroll
            for (int d = 0; d < 32; d++) s += qreg[d] * Ks[c * 33 + d];
            sc[cc] = s * scale;
        }
        float mx = sc[0];
#pragma unroll
        for (int cc = 1; cc < 8; cc++) mx = fmaxf(mx, sc[cc]);
#pragma unroll
        for (int off = 16; off > 0; off >>= 1)
            mx = fmaxf(mx, __shfl_xor_sync(0xffffffffu, mx, off));
        float sum = 0.f;
#pragma unroll
        for (int cc = 0; cc < 8; cc++) { sc[cc] = expf(sc[cc] - mx); sum += sc[cc]; }
#pragma unroll
        for (int off = 16; off > 0; off >>= 1)
            sum += __shfl_xor_sync(0xffffffffu, sum, off);
        float inv = (1.0f - a) / sum;
        const float* posr = pos + (((size_t)(b * HH + hh)) * NN + n0 + r) * NK;
#pragma unroll
        for (int cc = 0; cc < 8; cc++) {
            int c = cc * 32 + lane;
            S[r * 257 + c] = sc[cc] * inv + a * posr[c];
        }
    }
    __syncthreads();

    // AV: warp handles rows warp*8..+7, lane = d
    for (int rr = 0; rr < 8; rr++) {
        int r = warp * 8 + rr;
        float acc = 0.f;
#pragma unroll 8
        for (int c = 0; c < 256; c++) acc += S[r * 257 + c] * Vs[c * 33 + lane];
        o[((size_t)b * NN + n0 + r) * CC + hh * DH + lane] = acc;
    }
}

// ---------------- depthwise 3x3 (pad 1) + exact GELU ----------------
__global__ void dw_gelu(const float* __restrict__ m, const float* __restrict__ w,
                        const float* __restrict__ bias, float* __restrict__ mi)
{
    int y = blockIdx.x;
    int b = blockIdx.y;
    for (int idx = threadIdx.x; idx < HW * HID; idx += blockDim.x) {
        int x = idx >> 10;
        int c = idx & 1023;
        float acc = bias[c];
#pragma unroll
        for (int dy = -1; dy <= 1; dy++) {
            int yy = y + dy;
            if (yy < 0 || yy >= HW) continue;
#pragma unroll
            for (int dx = -1; dx <= 1; dx++) {
                int xx = x + dx;
                if (xx < 0 || xx >= HW) continue;
                acc += m[((size_t)b * NN + yy * HW + xx) * HID + c] *
                       w[c * 9 + (dy + 1) * 3 + (dx + 1)];
            }
        }
        float g = 0.5f * acc * (1.0f + erff(acc * 0.70710678118654752f));
        mi[((size_t)b * NN + y * HW + x) * HID + c] = g;
    }
}

// ---------------- launch ----------------
extern "C" void kernel_launch(void* const* d_in, const int* in_sizes, int n_in,
                              void* d_out, int out_size)
{
    const float* x      = (const float*)d_in[0];
    const float* pos2d  = (const float*)d_in[1];
    const float* ln1_w  = (const float*)d_in[2];
    const float* ln1_b  = (const float*)d_in[3];
    const float* q_w    = (const float*)d_in[4];
    const float* q_b    = (const float*)d_in[5];
    const float* kv_w   = (const float*)d_in[6];
    const float* kv_b   = (const float*)d_in[7];
    const float* sr_w   = (const float*)d_in[8];
    const float* sr_b   = (const float*)d_in[9];
    const float* srn_w  = (const float*)d_in[10];
    const float* srn_b  = (const float*)d_in[11];
    const float* alpha  = (const float*)d_in[12];
    const float* proj_w = (const float*)d_in[13];
    const float* proj_b = (const float*)d_in[14];
    const float* ln2_w  = (const float*)d_in[15];
    const float* ln2_b  = (const float*)d_in[16];
    const float* fc1_w  = (const float*)d_in[17];
    const float* fc1_b  = (const float*)d_in[18];
    const float* dw_w   = (const float*)d_in[19];
    const float* dw_b   = (const float*)d_in[20];
    const float* fc2_w  = (const float*)d_in[21];
    const float* fc2_b  = (const float*)d_in[22];
    float* out = (float*)d_out;

    float *h, *q, *hp, *wt, *hs, *kv, *o, *x1, *h2, *m, *mi;
    cudaGetSymbolAddress((void**)&h,  g_h);
    cudaGetSymbolAddress((void**)&q,  g_q);
    cudaGetSymbolAddress((void**)&hp, g_hp);
    cudaGetSymbolAddress((void**)&wt, g_wt);
    cudaGetSymbolAddress((void**)&hs, g_hs);
    cudaGetSymbolAddress((void**)&kv, g_kv);
    cudaGetSymbolAddress((void**)&o,  g_o);
    cudaGetSymbolAddress((void**)&x1, g_x1);
    cudaGetSymbolAddress((void**)&h2, g_h2);
    cudaGetSymbolAddress((void**)&m,  g_m);
    cudaGetSymbolAddress((void**)&mi, g_mi);

    const int ROWS = BB * NN;        // 32768
    const int ROWS_SR = BB * NK;     // 2048

    // 1. h = LN1(x)
    ln256<<<ROWS / 8, 256>>>(x, ln1_w, ln1_b, h, ROWS, 1e-6f);
    // 2. q = h @ q_w + q_b
    sgemm128<<<dim3(CC / 128, ROWS / 128), 256>>>(h, q_w, q_b, nullptr, q, ROWS, CC, CC);
    // 3. patch gather + 4. weight transpose
    patchify<<<(int)(((size_t)BB * NK * KPATCH) / 256), 256>>>(h, hp);
    wtrans<<<(KPATCH * CC) / 256, 256>>>(sr_w, wt);
    // 5. SR conv as GEMM: hs = hp @ wt + sr_b
    sgemm128<<<dim3(CC / 128, ROWS_SR / 128), 256>>>(hp, wt, sr_b, nullptr, hs, ROWS_SR, CC, KPATCH);
    // 6. srn LN (in place)
    ln256<<<ROWS_SR / 8, 256>>>(hs, srn_w, srn_b, hs, ROWS_SR, 1e-5f);
    // 7. kv = hs @ kv_w + kv_b
    sgemm128<<<dim3((2 * CC) / 128, ROWS_SR / 128), 256>>>(hs, kv_w, kv_b, nullptr, kv, ROWS_SR, 2 * CC, CC);
    // 8. fused attention
    static bool attn_cfg = false;
    if (!attn_cfg) {
        cudaFuncSetAttribute(attn_kernel, cudaFuncAttributeMaxDynamicSharedMemorySize,
                             ATTN_SMEM_FLOATS * (int)sizeof(float));
        attn_cfg = true;
    }
    attn_kernel<<<dim3(NN / 64, HH, BB), 256, ATTN_SMEM_FLOATS * sizeof(float)>>>(q, kv, pos2d, alpha, o);
    // 9. x1 = x + o @ proj_w + proj_b
    sgemm128<<<dim3(CC / 128, ROWS / 128), 256>>>(o, proj_w, proj_b, x, x1, ROWS, CC, CC);
    // 10. h2 = LN2(x1)
    ln256<<<ROWS / 8, 256>>>(x1, ln2_w, ln2_b, h2, ROWS, 1e-6f);
    // 11. m = h2 @ fc1_w + fc1_b
    sgemm128<<<dim3(HID / 128, ROWS / 128), 256>>>(h2, fc1_w, fc1_b, nullptr, m, ROWS, HID, CC);
    // 12. depthwise conv + gelu
    dw_gelu<<<dim3(HW, BB), 512>>>(m, dw_w, dw_b, mi);
    // 13. out = x1 + mi @ fc2_w + fc2_b
    sgemm128<<<dim3(CC / 128, ROWS / 128), 256>>>(mi, fc2_w, fc2_b, x1, out, ROWS, CC, HID);
}

// round 2
// speedup vs baseline: 1.1972x; 1.1972x over previous
#include <cuda_runtime.h>
#include <math.h>
#include <stdint.h>

// Problem dims (fixed)
#define BB   8
#define NN   4096
#define CC   256
#define HH   8
#define DH   32
#define HW   64
#define NK   256
#define HID  1024
#define KPATCH 4096   // C * SR * SR

// ---------------- scratch (device globals; no allocation) ----------------
__device__ float g_h  [(size_t)BB*NN*CC];    // LN1 output
__device__ float g_q  [(size_t)BB*NN*CC];    // q projection
__device__ float g_hp [(size_t)BB*NK*KPATCH];// gathered patches for SR conv
__device__ float g_wt [(size_t)KPATCH*CC];   // transposed sr weights
__device__ float g_hs [(size_t)BB*NK*CC];    // SR output (+ LN in place)
__device__ float g_kv [(size_t)BB*NK*2*CC];  // kv projection
__device__ float g_o  [(size_t)BB*NN*CC];    // attention output
__device__ float g_x1 [(size_t)BB*NN*CC];    // x + proj(o)
__device__ float g_h2 [(size_t)BB*NN*CC];    // LN2 output
__device__ float g_m  [(size_t)BB*NN*HID];   // fc1 output
__device__ float g_mi [(size_t)BB*NN*HID];   // dwconv+gelu output
__device__ float g_part[(size_t)8*BB*NK*CC]; // split-K partials for SR GEMM

// ---------------- LayerNorm over last dim = 256, warp per row ----------------
__global__ void ln256(const float* __restrict__ x, const float* __restrict__ w,
                      const float* __restrict__ b, float* __restrict__ y,
                      int rows, float eps)
{
    int row  = blockIdx.x * 8 + (threadIdx.x >> 5);
    int lane = threadIdx.x & 31;
    if (row >= rows) return;
    const float* xr = x + (size_t)row * 256;
    float4 v0 = *reinterpret_cast<const float4*>(xr + lane * 8);
    float4 v1 = *reinterpret_cast<const float4*>(xr + lane * 8 + 4);
    float vals[8] = {v0.x, v0.y, v0.z, v0.w, v1.x, v1.y, v1.z, v1.w};
    float s = 0.f, sq = 0.f;
#pragma unroll
    for (int i = 0; i < 8; i++) { s += vals[i]; sq += vals[i] * vals[i]; }
#pragma unroll
    for (int o = 16; o > 0; o >>= 1) {
        s  += __shfl_xor_sync(0xffffffffu, s, o);
        sq += __shfl_xor_sync(0xffffffffu, sq, o);
    }
    float mean = s * (1.0f / 256.0f);
    float var  = sq * (1.0f / 256.0f) - mean * mean;
    float rs   = rsqrtf(var + eps);
    float* yr = y + (size_t)row * 256;
#pragma unroll
    for (int i = 0; i < 8; i++) {
        int c = lane * 8 + i;
        yr[c] = (vals[i] - mean) * rs * w[c] + b[c];
    }
}

// ---------------- SGEMM: 128x128 tile, BK=16, double buffered ----------------
// C = A[M,K] @ B[K,N] (+bias) (+res)   — bias/res applied only if splitK==1.
// If splitK>1: block z handles K slice z, writes partial to C + z*M*N.
__global__ __launch_bounds__(256, 2)
void sgemm_db(const float* __restrict__ A, const float* __restrict__ B,
              const float* __restrict__ bias, const float* __restrict__ res,
              float* __restrict__ C, int M, int N, int K, int splitK)
{
    __shared__ float As[2][16 * 132];   // [k][m], padded to 132
    __shared__ float Bs[2][16 * 128];   // [k][n]

    const int t  = threadIdx.x;
    const int bx = blockIdx.x, by = blockIdx.y, bz = blockIdx.z;
    const int tx = t & 15, ty = t >> 4;

    int Keff = K / splitK;
    int kbase = bz * Keff;
    if (splitK > 1) C += (size_t)bz * M * N;

    const float* Ab = A + (size_t)by * 128 * K + kbase;
    const float* Bb = B + (size_t)kbase * N + (size_t)bx * 128;

    // loader thread mapping
    const int arow = t >> 2;             // 0..63  (also +64)
    const int ac0  = (t & 3) * 4;        // 0,4,8,12
    const int brow = t >> 5;             // 0..7   (also +8)
    const int bcol = (t & 31) * 4;       // 0..124

    float4 ra0, ra1, rb0, rb1;

    float acc[8][8];
#pragma unroll
    for (int i = 0; i < 8; i++)
#pragma unroll
        for (int j = 0; j < 8; j++) acc[i][j] = 0.f;

    const int nkb = Keff / 16;

    // prologue: load tile 0
    {
        ra0 = *reinterpret_cast<const float4*>(Ab + (size_t)arow * K + ac0);
        ra1 = *reinterpret_cast<const float4*>(Ab + (size_t)(arow + 64) * K + ac0);
        rb0 = *reinterpret_cast<const float4*>(Bb + (size_t)brow * N + bcol);
        rb1 = *reinterpret_cast<const float4*>(Bb + (size_t)(brow + 8) * N + bcol);
        As[0][(ac0 + 0) * 132 + arow] = ra0.x;
        As[0][(ac0 + 1) * 132 + arow] = ra0.y;
        As[0][(ac0 + 2) * 132 + arow] = ra0.z;
        As[0][(ac0 + 3) * 132 + arow] = ra0.w;
        As[0][(ac0 + 0) * 132 + arow + 64] = ra1.x;
        As[0][(ac0 + 1) * 132 + arow + 64] = ra1.y;
        As[0][(ac0 + 2) * 132 + arow + 64] = ra1.z;
        As[0][(ac0 + 3) * 132 + arow + 64] = ra1.w;
        *reinterpret_cast<float4*>(&Bs[0][brow * 128 + bcol]) = rb0;
        *reinterpret_cast<float4*>(&Bs[0][(brow + 8) * 128 + bcol]) = rb1;
    }
    __syncthreads();

    for (int kb = 0; kb < nkb; kb++) {
        int cur = kb & 1;
        if (kb + 1 < nkb) {
            int k0 = (kb + 1) * 16;
            ra0 = *reinterpret_cast<const float4*>(Ab + (size_t)arow * K + k0 + ac0);
            ra1 = *reinterpret_cast<const float4*>(Ab + (size_t)(arow + 64) * K + k0 + ac0);
            rb0 = *reinterpret_cast<const float4*>(Bb + (size_t)(k0 + brow) * N + bcol);
            rb1 = *reinterpret_cast<const float4*>(Bb + (size_t)(k0 + brow + 8) * N + bcol);
        }
#pragma unroll
        for (int k = 0; k < 16; k++) {
            float4 a0 = *reinterpret_cast<const float4*>(&As[cur][k * 132 + ty * 8]);
            float4 a1 = *reinterpret_cast<const float4*>(&As[cur][k * 132 + ty * 8 + 4]);
            float4 b0 = *reinterpret_cast<const float4*>(&Bs[cur][k * 128 + tx * 8]);
            float4 b1 = *reinterpret_cast<const float4*>(&Bs[cur][k * 128 + tx * 8 + 4]);
            float ar[8] = {a0.x, a0.y, a0.z, a0.w, a1.x, a1.y, a1.z, a1.w};
            float br[8] = {b0.x, b0.y, b0.z, b0.w, b1.x, b1.y, b1.z, b1.w};
#pragma unroll
            for (int i = 0; i < 8; i++)
#pragma unroll
                for (int j = 0; j < 8; j++) acc[i][j] += ar[i] * br[j];
        }
        if (kb + 1 < nkb) {
            int nxt = cur ^ 1;
            As[nxt][(ac0 + 0) * 132 + arow] = ra0.x;
            As[nxt][(ac0 + 1) * 132 + arow] = ra0.y;
            As[nxt][(ac0 + 2) * 132 + arow] = ra0.z;
            As[nxt][(ac0 + 3) * 132 + arow] = ra0.w;
            As[nxt][(ac0 + 0) * 132 + arow + 64] = ra1.x;
            As[nxt][(ac0 + 1) * 132 + arow + 64] = ra1.y;
            As[nxt][(ac0 + 2) * 132 + arow + 64] = ra1.z;
            As[nxt][(ac0 + 3) * 132 + arow + 64] = ra1.w;
            *reinterpret_cast<float4*>(&Bs[nxt][brow * 128 + bcol]) = rb0;
            *reinterpret_cast<float4*>(&Bs[nxt][(brow + 8) * 128 + bcol]) = rb1;
            __syncthreads();
        }
    }

    // epilogue
#pragma unroll
    for (int i = 0; i < 8; i++) {
        int row = by * 128 + ty * 8 + i;
        int col = bx * 128 + tx * 8;
        float* Cp = C + (size_t)row * N + col;
        float4 o0 = make_float4(acc[i][0], acc[i][1], acc[i][2], acc[i][3]);
        float4 o1 = make_float4(acc[i][4], acc[i][5], acc[i][6], acc[i][7]);
        if (splitK == 1) {
            float4 bi0 = *reinterpret_cast<const float4*>(bias + col);
            float4 bi1 = *reinterpret_cast<const float4*>(bias + col + 4);
            o0.x += bi0.x; o0.y += bi0.y; o0.z += bi0.z; o0.w += bi0.w;
            o1.x += bi1.x; o1.y += bi1.y; o1.z += bi1.z; o1.w += bi1.w;
            if (res) {
                const float* rp = res + (size_t)row * N + col;
                float4 r0 = *reinterpret_cast<const float4*>(rp);
                float4 r1 = *reinterpret_cast<const float4*>(rp + 4);
                o0.x += r0.x; o0.y += r0.y; o0.z += r0.z; o0.w += r0.w;
                o1.x += r1.x; o1.y += r1.y; o1.z += r1.z; o1.w += r1.w;
            }
        }
        *reinterpret_cast<float4*>(Cp)     = o0;
        *reinterpret_cast<float4*>(Cp + 4) = o1;
    }
}

// ---------------- split-K reduce: out = sum_z part[z] + bias ----------------
__global__ void reduceK(const float* __restrict__ part, const float* __restrict__ bias,
                        float* __restrict__ out, int MN, int N, int S)
{
    int idx = blockIdx.x * blockDim.x + threadIdx.x;
    if (idx >= MN) return;
    float s = bias[idx % N];
    for (int z = 0; z < S; z++) s += part[(size_t)z * MN + idx];
    out[idx] = s;
}

// ---------------- patch gather for SR conv: hp[b][nk][(ky*4+kx)*256+ci] ----------------
__global__ void patchify(const float* __restrict__ h, float* __restrict__ hp)
{
    size_t idx = (size_t)blockIdx.x * blockDim.x + threadIdx.x;  // B*NK*4096
    int ci = idx & 255;
    size_t t = idx >> 8;
    int ks = t & 15;  t >>= 4;
    int nk = t & 255; int b = t >> 8;
    int ky = ks >> 2, kx = ks & 3;
    int py = nk >> 4, px = nk & 15;
    int n = (py * 4 + ky) * HW + px * 4 + kx;
    hp[idx] = h[((size_t)b * NN + n) * CC + ci];
}

// ---------------- weight transpose: wt[(ky*4+kx)*256+ci][co] = sr_w[co][ci][ky][kx] ----
__global__ void wtrans(const float* __restrict__ srw, float* __restrict__ wt)
{
    int idx = blockIdx.x * blockDim.x + threadIdx.x;  // 4096*256
    int co = idx & 255;
    int r  = idx >> 8;       // ks*256 + ci
    int ks = r >> 8;
    int ci = r & 255;
    wt[idx] = srw[(size_t)co * KPATCH + ci * 16 + ks];
}

// ---------------- fused SR attention: per (b, h, 64-row q tile) ----------------
#define ATTN_SMEM_FLOATS (64*33 + 256*33 + 256*33 + 64*257)
__global__ void attn_kernel(const float* __restrict__ q, const float* __restrict__ kv,
                            const float* __restrict__ pos, const float* __restrict__ alpha,
                            float* __restrict__ o)
{
    extern __shared__ float sm[];
    float* Qs = sm;                  // 64*33
    float* Ks = Qs + 64 * 33;        // 256*33
    float* Vs = Ks + 256 * 33;       // 256*33
    float* S  = Vs + 256 * 33;       // 64*257

    int n0 = blockIdx.x * 64;
    int hh = blockIdx.y;
    int b  = blockIdx.z;
    int tid = threadIdx.x;           // 256

    for (int idx = tid; idx < 256 * 32; idx += 256) {
        int m = idx >> 5, d = idx & 31;
        const float* kvrow = kv + ((size_t)b * NK + m) * (2 * CC);
        Ks[m * 33 + d] = kvrow[hh * DH + d];
        Vs[m * 33 + d] = kvrow[CC + hh * DH + d];
    }
    for (int idx = tid; idx < 64 * 32; idx += 256) {
        int r = idx >> 5, d = idx & 31;
        Qs[r * 33 + d] = q[((size_t)b * NN + n0 + r) * CC + hh * DH + d];
    }
    __syncthreads();

    int warp = tid >> 5, lane = tid & 31;
    const float scale = 0.17677669529663687f;   // 1/sqrt(32)
    float a = alpha[0];

    for (int rr = 0; rr < 8; rr++) {
        int r = warp * 8 + rr;
        float qreg[32];
#pragma unroll
        for (int d = 0; d < 32; d++) qreg[d] = Qs[r * 33 + d];
        float sc[8];
#pragma unroll
        for (int cc = 0; cc < 8; cc++) {
            int c = cc * 32 + lane;
            float s = 0.f;
#pragma unroll
            for (int d = 0; d < 32; d++) s += qreg[d] * Ks[c * 33 + d];
            sc[cc] = s * scale;
        }
        float mx = sc[0];
#pragma unroll
        for (int cc = 1; cc < 8; cc++) mx = fmaxf(mx, sc[cc]);
#pragma unroll
        for (int off = 16; off > 0; off >>= 1)
            mx = fmaxf(mx, __shfl_xor_sync(0xffffffffu, mx, off));
        float sum = 0.f;
#pragma unroll
        for (int cc = 0; cc < 8; cc++) { sc[cc] = expf(sc[cc] - mx); sum += sc[cc]; }
#pragma unroll
        for (int off = 16; off > 0; off >>= 1)
            sum += __shfl_xor_sync(0xffffffffu, sum, off);
        float inv = (1.0f - a) / sum;
        const float* posr = pos + (((size_t)(b * HH + hh)) * NN + n0 + r) * NK;
#pragma unroll
        for (int cc = 0; cc < 8; cc++) {
            int c = cc * 32 + lane;
            S[r * 257 + c] = sc[cc] * inv + a * posr[c];
        }
    }
    __syncthreads();

    for (int rr = 0; rr < 8; rr++) {
        int r = warp * 8 + rr;
        float acc = 0.f;
#pragma unroll 8
        for (int c = 0; c < 256; c++) acc += S[r * 257 + c] * Vs[c * 33 + lane];
        o[((size_t)b * NN + n0 + r) * CC + hh * DH + lane] = acc;
    }
}

// ---------------- depthwise 3x3 (pad 1) + exact GELU, float4 over channels ----------------
__global__ void dw_gelu(const float* __restrict__ m, const float* __restrict__ w,
                        const float* __restrict__ bias, float* __restrict__ mi)
{
    int y = blockIdx.x;
    int b = blockIdx.y;
    for (int idx = threadIdx.x; idx < HW * (HID / 4); idx += blockDim.x) {
        int x  = idx >> 8;         // HID/4 = 256
        int c4 = idx & 255;
        int c  = c4 * 4;
        float4 acc = *reinterpret_cast<const float4*>(bias + c);
        // preload 9 taps x 4 channels of weights
        float wr[9][4];
#pragma unroll
        for (int tap = 0; tap < 9; tap++)
#pragma unroll
            for (int j = 0; j < 4; j++)
                wr[tap][j] = w[(c + j) * 9 + tap];
#pragma unroll
        for (int dy = -1; dy <= 1; dy++) {
            int yy = y + dy;
            if (yy < 0 || yy >= HW) continue;
#pragma unroll
            for (int dx = -1; dx <= 1; dx++) {
                int xx = x + dx;
                if (xx < 0 || xx >= HW) continue;
                int tap = (dy + 1) * 3 + (dx + 1);
                float4 v = *reinterpret_cast<const float4*>(
                    m + ((size_t)b * NN + yy * HW + xx) * HID + c);
                acc.x += v.x * wr[tap][0];
                acc.y += v.y * wr[tap][1];
                acc.z += v.z * wr[tap][2];
                acc.w += v.w * wr[tap][3];
            }
        }
        float4 g;
        g.x = 0.5f * acc.x * (1.0f + erff(acc.x * 0.70710678118654752f));
        g.y = 0.5f * acc.y * (1.0f + erff(acc.y * 0.70710678118654752f));
        g.z = 0.5f * acc.z * (1.0f + erff(acc.z * 0.70710678118654752f));
        g.w = 0.5f * acc.w * (1.0f + erff(acc.w * 0.70710678118654752f));
        *reinterpret_cast<float4*>(mi + ((size_t)b * NN + y * HW + x) * HID + c) = g;
    }
}

// ---------------- launch ----------------
extern "C" void kernel_launch(void* const* d_in, const int* in_sizes, int n_in,
                              void* d_out, int out_size)
{
    const float* x      = (const float*)d_in[0];
    const float* pos2d  = (const float*)d_in[1];
    const float* ln1_w  = (const float*)d_in[2];
    const float* ln1_b  = (const float*)d_in[3];
    const float* q_w    = (const float*)d_in[4];
    const float* q_b    = (const float*)d_in[5];
    const float* kv_w   = (const float*)d_in[6];
    const float* kv_b   = (const float*)d_in[7];
    const float* sr_w   = (const float*)d_in[8];
    const float* sr_b   = (const float*)d_in[9];
    const float* srn_w  = (const float*)d_in[10];
    const float* srn_b  = (const float*)d_in[11];
    const float* alpha  = (const float*)d_in[12];
    const float* proj_w = (const float*)d_in[13];
    const float* proj_b = (const float*)d_in[14];
    const float* ln2_w  = (const float*)d_in[15];
    const float* ln2_b  = (const float*)d_in[16];
    const float* fc1_w  = (const float*)d_in[17];
    const float* fc1_b  = (const float*)d_in[18];
    const float* dw_w   = (const float*)d_in[19];
    const float* dw_b   = (const float*)d_in[20];
    const float* fc2_w  = (const float*)d_in[21];
    const float* fc2_b  = (const float*)d_in[22];
    float* out = (float*)d_out;

    float *h, *q, *hp, *wt, *hs, *kv, *o, *x1, *h2, *m, *mi, *part;
    cudaGetSymbolAddress((void**)&h,  g_h);
    cudaGetSymbolAddress((void**)&q,  g_q);
    cudaGetSymbolAddress((void**)&hp, g_hp);
    cudaGetSymbolAddress((void**)&wt, g_wt);
    cudaGetSymbolAddress((void**)&hs, g_hs);
    cudaGetSymbolAddress((void**)&kv, g_kv);
    cudaGetSymbolAddress((void**)&o,  g_o);
    cudaGetSymbolAddress((void**)&x1, g_x1);
    cudaGetSymbolAddress((void**)&h2, g_h2);
    cudaGetSymbolAddress((void**)&m,  g_m);
    cudaGetSymbolAddress((void**)&mi, g_mi);
    cudaGetSymbolAddress((void**)&part, g_part);

    const int ROWS = BB * NN;        // 32768
    const int ROWS_SR = BB * NK;     // 2048

    // 1. h = LN1(x)
    ln256<<<ROWS / 8, 256>>>(x, ln1_w, ln1_b, h, ROWS, 1e-6f);
    // 2. q = h @ q_w + q_b
    sgemm_db<<<dim3(CC / 128, ROWS / 128), 256>>>(h, q_w, q_b, nullptr, q, ROWS, CC, CC, 1);
    // 3. patch gather + 4. weight transpose
    patchify<<<(int)(((size_t)BB * NK * KPATCH) / 256), 256>>>(h, hp);
    wtrans<<<(KPATCH * CC) / 256, 256>>>(sr_w, wt);
    // 5. SR conv as split-K GEMM: part[z] = hp @ wt (K slice z); hs = sum + sr_b
    sgemm_db<<<dim3(CC / 128, ROWS_SR / 128, 8), 256>>>(hp, wt, nullptr, nullptr, part,
                                                        ROWS_SR, CC, KPATCH, 8);
    reduceK<<<(ROWS_SR * CC + 255) / 256, 256>>>(part, sr_b, hs, ROWS_SR * CC, CC, 8);
    // 6. srn LN (in place)
    ln256<<<ROWS_SR / 8, 256>>>(hs, srn_w, srn_b, hs, ROWS_SR, 1e-5f);
    // 7. kv = hs @ kv_w + kv_b
    sgemm_db<<<dim3((2 * CC) / 128, ROWS_SR / 128), 256>>>(hs, kv_w, kv_b, nullptr, kv,
                                                           ROWS_SR, 2 * CC, CC, 1);
    // 8. fused attention
    static bool attn_cfg = false;
    if (!attn_cfg) {
        cudaFuncSetAttribute(attn_kernel, cudaFuncAttributeMaxDynamicSharedMemorySize,
                             ATTN_SMEM_FLOATS * (int)sizeof(float));
        attn_cfg = true;
    }
    attn_kernel<<<dim3(NN / 64, HH, BB), 256, ATTN_SMEM_FLOATS * sizeof(float)>>>(q, kv, pos2d, alpha, o);
    // 9. x1 = x + o @ proj_w + proj_b
    sgemm_db<<<dim3(CC / 128, ROWS / 128), 256>>>(o, proj_w, proj_b, x, x1, ROWS, CC, CC, 1);
    // 10. h2 = LN2(x1)
    ln256<<<ROWS / 8, 256>>>(x1, ln2_w, ln2_b, h2, ROWS, 1e-6f);
    // 11. m = h2 @ fc1_w + fc1_b
    sgemm_db<<<dim3(HID / 128, ROWS / 128), 256>>>(h2, fc1_w, fc1_b, nullptr, m, ROWS, HID, CC, 1);
    // 12. depthwise conv + gelu
    dw_gelu<<<dim3(HW, BB), 512>>>(m, dw_w, dw_b, mi);
    // 13. out = x1 + mi @ fc2_w + fc2_b
    sgemm_db<<<dim3(CC / 128, ROWS / 128), 256>>>(mi, fc2_w, fc2_b, x1, out, ROWS, CC, HID, 1);
}

// round 4
// speedup vs baseline: 1.6281x; 1.3599x over previous
#include <cuda_runtime.h>
#include <cuda_bf16.h>
#include <math.h>
#include <stdint.h>

// Problem dims (fixed)
#define BB   8
#define NN   4096
#define CC   256
#define HH   8
#define DH   32
#define HW   64
#define NK   256
#define HID  1024
#define KPATCH 4096   // C * SR * SR

// ---------------- scratch (device globals; no allocation) ----------------
__device__ __nv_bfloat16 g_h_hi [(size_t)BB*NN*CC];
__device__ __nv_bfloat16 g_h_lo [(size_t)BB*NN*CC];
__device__ __nv_bfloat16 g_hp_hi[(size_t)BB*NK*KPATCH];
__device__ __nv_bfloat16 g_hp_lo[(size_t)BB*NK*KPATCH];
__device__ __nv_bfloat16 g_wtT_hi[(size_t)CC*KPATCH];
__device__ __nv_bfloat16 g_wtT_lo[(size_t)CC*KPATCH];
__device__ float         g_hs   [(size_t)BB*NK*CC];
__device__ __nv_bfloat16 g_hs_hi[(size_t)BB*NK*CC];
__device__ __nv_bfloat16 g_hs_lo[(size_t)BB*NK*CC];
__device__ float         g_q    [(size_t)BB*NN*CC];
__device__ float         g_kv   [(size_t)BB*NK*2*CC];
__device__ __nv_bfloat16 g_o_hi [(size_t)BB*NN*CC];
__device__ __nv_bfloat16 g_o_lo [(size_t)BB*NN*CC];
__device__ float         g_x1   [(size_t)BB*NN*CC];
__device__ __nv_bfloat16 g_h2_hi[(size_t)BB*NN*CC];
__device__ __nv_bfloat16 g_h2_lo[(size_t)BB*NN*CC];
__device__ float         g_m    [(size_t)BB*NN*HID];
__device__ __nv_bfloat16 g_mi_hi[(size_t)BB*NN*HID];
__device__ __nv_bfloat16 g_mi_lo[(size_t)BB*NN*HID];
__device__ float         g_part [(size_t)4*BB*NK*CC];   // split-K partials
// transposed+split weights [N x K]
__device__ __nv_bfloat16 g_qT_hi [CC*CC],      g_qT_lo [CC*CC];
__device__ __nv_bfloat16 g_kvT_hi[2*CC*CC],    g_kvT_lo[2*CC*CC];
__device__ __nv_bfloat16 g_pjT_hi[CC*CC],      g_pjT_lo[CC*CC];
__device__ __nv_bfloat16 g_f1T_hi[HID*CC],     g_f1T_lo[HID*CC];
__device__ __nv_bfloat16 g_f2T_hi[CC*HID],     g_f2T_lo[CC*HID];

// ---------------- PTX helpers (all legal on base compute_103 target) ----------------
__device__ __forceinline__ uint32_t smem_u32(const void* p) {
    uint32_t a;
    asm("{ .reg .u64 t; cvta.to.shared.u64 t, %1; cvt.u32.u64 %0, t; }" : "=r"(a) : "l"(p));
    return a;
}

__device__ __forceinline__ void cpasync16(uint32_t dst, const void* src) {
    asm volatile("cp.async.cg.shared.global [%0], [%1], 16;" :: "r"(dst), "l"(src) : "memory");
}
__device__ __forceinline__ void cpcommit() {
    asm volatile("cp.async.commit_group;" ::: "memory");
}
template<int Ngrp> __device__ __forceinline__ void cpwait() {
    asm volatile("cp.async.wait_group %0;" :: "n"(Ngrp) : "memory");
}

__device__ __forceinline__ void ldm4(uint32_t* r, uint32_t addr) {
    asm volatile("ldmatrix.sync.aligned.m8n8.x4.shared.b16 {%0,%1,%2,%3}, [%4];"
                 : "=r"(r[0]), "=r"(r[1]), "=r"(r[2]), "=r"(r[3]) : "r"(addr));
}

__device__ __forceinline__ void mma16816(float* c, const uint32_t* a, const uint32_t* b) {
    asm volatile("mma.sync.aligned.m16n8k16.row.col.f32.bf16.bf16.f32 "
                 "{%0,%1,%2,%3}, {%4,%5,%6,%7}, {%8,%9}, {%0,%1,%2,%3};"
                 : "+f"(c[0]), "+f"(c[1]), "+f"(c[2]), "+f"(c[3])
                 : "r"(a[0]), "r"(a[1]), "r"(a[2]), "r"(a[3]), "r"(b[0]), "r"(b[1]));
}

// ---------------- split-bf16 tensor GEMM via mma.sync ----------------
// C[M,N] = A @ B^T (+bias)(+res).  A:[M,K] hi/lo, Bt:[N,K] hi/lo, all K-major.
// CTA tile 128x128, BK=32, 8 warps (2 along M x 4 along N), warp tile 64x32.
// smem per stage: Ahi|Alo|Bhi|Blo, each 128 rows x 40 bf16 (80B stride -> conflict-free ldmatrix).
#define GEMM_SMEM (2 * 40960)

__global__ __launch_bounds__(256)
void gemm_mma(const __nv_bfloat16* __restrict__ Ahi, const __nv_bfloat16* __restrict__ Alo,
              const __nv_bfloat16* __restrict__ Bhi, const __nv_bfloat16* __restrict__ Blo,
              const float* __restrict__ bias, const float* __restrict__ res,
              float* __restrict__ C, int M, int N, int K, int splitK)
{
    extern __shared__ char sm[];
    uint32_t sb = smem_u32(sm);
    const int tid  = threadIdx.x;
    const int warp = tid >> 5, lane = tid & 31;
    const int n0 = blockIdx.x * 128, m0 = blockIdx.y * 128;
    const int Keff  = K / splitK;
    const int kbase = blockIdx.z * Keff;
    if (splitK > 1) C += (size_t)blockIdx.z * M * N;
    const int nk = Keff / 32;
    const int wm0 = (warp >> 2) * 64, wn0 = (warp & 3) * 32;

    float c[4][4][4];
#pragma unroll
    for (int i = 0; i < 4; i++)
#pragma unroll
        for (int j = 0; j < 4; j++)
#pragma unroll
            for (int k = 0; k < 4; k++) c[i][j][k] = 0.f;

    const int lrow = tid >> 2;      // 0..63
    const int lq   = tid & 3;       // 16B quad within 32-col chunk

    auto load_stage = [&](int i, int s) {
        const int k0 = kbase + i * 32;
        const uint32_t st = sb + s * 40960;
#pragma unroll
        for (int e = 0; e < 2; e++) {
            int r = lrow + e * 64;
            cpasync16(st +         r * 80 + lq * 16, Ahi + (size_t)(m0 + r) * K + k0 + lq * 8);
            cpasync16(st + 10240 + r * 80 + lq * 16, Alo + (size_t)(m0 + r) * K + k0 + lq * 8);
            cpasync16(st + 20480 + r * 80 + lq * 16, Bhi + (size_t)(n0 + r) * K + k0 + lq * 8);
            cpasync16(st + 30720 + r * 80 + lq * 16, Blo + (size_t)(n0 + r) * K + k0 + lq * 8);
        }
        cpcommit();
    };

    auto compute_stage = [&](int s) {
        const uint32_t st = sb + s * 40960;
#pragma unroll
        for (int h = 0; h < 2; h++) {            // two k16 halves of BK=32
            uint32_t ah[4][4], al[4][4], bh[4][2], bl[4][2];
#pragma unroll
            for (int mt = 0; mt < 4; mt++) {
                int r = wm0 + mt * 16 + (lane & 15);
                uint32_t ad = st + r * 80 + h * 32 + (lane >> 4) * 16;
                ldm4(ah[mt], ad);
                ldm4(al[mt], ad + 10240);
            }
#pragma unroll
            for (int ng = 0; ng < 2; ng++) {
                int r = wn0 + ng * 16 + (lane & 15);
                uint32_t bd = st + 20480 + r * 80 + h * 32 + (lane >> 4) * 16;
                uint32_t t[4];
                ldm4(t, bd);
                bh[2*ng][0] = t[0]; bh[2*ng][1] = t[2];
                bh[2*ng+1][0] = t[1]; bh[2*ng+1][1] = t[3];
                ldm4(t, bd + 10240);
                bl[2*ng][0] = t[0]; bl[2*ng][1] = t[2];
                bl[2*ng+1][0] = t[1]; bl[2*ng+1][1] = t[3];
            }
#pragma unroll
            for (int mt = 0; mt < 4; mt++)
#pragma unroll
                for (int nt = 0; nt < 4; nt++) {
                    mma16816(c[mt][nt], ah[mt], bh[nt]);
                    mma16816(c[mt][nt], ah[mt], bl[nt]);
                    mma16816(c[mt][nt], al[mt], bh[nt]);
                }
        }
    };

    load_stage(0, 0);
    for (int i = 0; i < nk; i++) {
        if (i + 1 < nk) { load_stage(i + 1, (i + 1) & 1); cpwait<1>(); }
        else            { cpwait<0>(); }
        __syncthreads();
        compute_stage(i & 1);
        __syncthreads();
    }

    // epilogue: fragment -> global float2 stores
#pragma unroll
    for (int mt = 0; mt < 4; mt++)
#pragma unroll
        for (int nt = 0; nt < 4; nt++) {
            int row = m0 + wm0 + mt * 16 + (lane >> 2);
            int col = n0 + wn0 + nt * 8 + (lane & 3) * 2;
            float v0 = c[mt][nt][0], v1 = c[mt][nt][1];
            float v2 = c[mt][nt][2], v3 = c[mt][nt][3];
            if (splitK == 1) {
                float b0 = bias[col], b1 = bias[col + 1];
                v0 += b0; v1 += b1; v2 += b0; v3 += b1;
                if (res) {
                    const float* r0 = res + (size_t)row * N + col;
                    const float* r1 = res + (size_t)(row + 8) * N + col;
                    v0 += r0[0]; v1 += r0[1]; v2 += r1[0]; v3 += r1[1];
                }
            }
            *reinterpret_cast<float2*>(C + (size_t)row * N + col)       = make_float2(v0, v1);
            *reinterpret_cast<float2*>(C + (size_t)(row + 8) * N + col) = make_float2(v2, v3);
        }
}

// ---------------- split-K reduce: out = sum_z part[z] + bias ----------------
__global__ void reduceK(const float* __restrict__ part, const float* __restrict__ bias,
                        float* __restrict__ out, int MN, int N, int S)
{
    int idx = blockIdx.x * blockDim.x + threadIdx.x;
    if (idx >= MN) return;
    float s = bias[idx % N];
    for (int z = 0; z < S; z++) s += part[(size_t)z * MN + idx];
    out[idx] = s;
}

// ---------------- LayerNorm(256) -> bf16 hi/lo split ----------------
__global__ void ln256_split(const float* __restrict__ x, const float* __restrict__ w,
                            const float* __restrict__ b, __nv_bfloat16* __restrict__ yhi,
                            __nv_bfloat16* __restrict__ ylo, int rows, float eps)
{
    int row  = blockIdx.x * 8 + (threadIdx.x >> 5);
    int lane = threadIdx.x & 31;
    if (row >= rows) return;
    const float* xr = x + (size_t)row * 256;
    float4 v0 = *reinterpret_cast<const float4*>(xr + lane * 8);
    float4 v1 = *reinterpret_cast<const float4*>(xr + lane * 8 + 4);
    float vals[8] = {v0.x, v0.y, v0.z, v0.w, v1.x, v1.y, v1.z, v1.w};
    float s = 0.f, sq = 0.f;
#pragma unroll
    for (int i = 0; i < 8; i++) { s += vals[i]; sq += vals[i] * vals[i]; }
#pragma unroll
    for (int o = 16; o > 0; o >>= 1) {
        s  += __shfl_xor_sync(0xffffffffu, s, o);
        sq += __shfl_xor_sync(0xffffffffu, sq, o);
    }
    float mean = s * (1.0f / 256.0f);
    float var  = sq * (1.0f / 256.0f) - mean * mean;
    float rs   = rsqrtf(var + eps);
    __align__(16) __nv_bfloat16 hb[8];
    __align__(16) __nv_bfloat16 lb[8];
#pragma unroll
    for (int i = 0; i < 8; i++) {
        int c = lane * 8 + i;
        float v = (vals[i] - mean) * rs * w[c] + b[c];
        hb[i] = __float2bfloat16(v);
        lb[i] = __float2bfloat16(v - __bfloat162float(hb[i]));
    }
    *reinterpret_cast<uint4*>(yhi + (size_t)row * 256 + lane * 8) = *reinterpret_cast<uint4*>(hb);
    *reinterpret_cast<uint4*>(ylo + (size_t)row * 256 + lane * 8) = *reinterpret_cast<uint4*>(lb);
}

// ---------------- weight transpose + split: Bt[n][k] = B[k][n] ----------------
__global__ void wtsplit(const float* __restrict__ B, __nv_bfloat16* __restrict__ thi,
                        __nv_bfloat16* __restrict__ tlo, int K, int N)
{
    int idx = blockIdx.x * blockDim.x + threadIdx.x;
    if (idx >= N * K) return;
    int n = idx / K, k = idx - n * K;
    float v = B[(size_t)k * N + n];
    __nv_bfloat16 h = __float2bfloat16(v);
    thi[idx] = h;
    tlo[idx] = __float2bfloat16(v - __bfloat162float(h));
}

// sr_w [co][ci][ky][kx] -> wtT[co][(ky*4+kx)*256+ci], split
__global__ void wtrans_split(const float* __restrict__ srw, __nv_bfloat16* __restrict__ thi,
                             __nv_bfloat16* __restrict__ tlo)
{
    int idx = blockIdx.x * blockDim.x + threadIdx.x;   // CC * KPATCH
    int co = idx >> 12;
    int k  = idx & 4095;
    int ks = k >> 8, ci = k & 255;
    float v = srw[(size_t)co * KPATCH + ci * 16 + ks];
    __nv_bfloat16 h = __float2bfloat16(v);
    thi[idx] = h;
    tlo[idx] = __float2bfloat16(v - __bfloat162float(h));
}

// ---------------- patch gather (bf16, 2 elems per thread via uint) ----------------
__global__ void patchify_bf16(const uint32_t* __restrict__ hhi, const uint32_t* __restrict__ hlo,
                              uint32_t* __restrict__ phi, uint32_t* __restrict__ plo)
{
    size_t idx = (size_t)blockIdx.x * blockDim.x + threadIdx.x;  // B*NK*16*128
    int ci2 = idx & 127;
    size_t t = idx >> 7;
    int ks = t & 15; t >>= 4;
    int nk = t & 255; int b = (int)(t >> 8);
    int ky = ks >> 2, kx = ks & 3;
    int n = ((nk >> 4) * 4 + ky) * HW + (nk & 15) * 4 + kx;
    size_t src = ((size_t)b * NN + n) * 128 + ci2;
    phi[idx] = hhi[src];
    plo[idx] = hlo[src];
}

// ---------------- fused SR attention (outputs bf16 split) ----------------
#define ATTN_SMEM_FLOATS (64*33 + 256*33 + 256*33 + 64*257)
__global__ void attn_kernel(const float* __restrict__ q, const float* __restrict__ kv,
                            const float* __restrict__ pos, const float* __restrict__ alpha,
                            __nv_bfloat16* __restrict__ ohi, __nv_bfloat16* __restrict__ olo)
{
    extern __shared__ float smf[];
    float* Qs = smf;
    float* Ks = Qs + 64 * 33;
    float* Vs = Ks + 256 * 33;
    float* S  = Vs + 256 * 33;

    int n0 = blockIdx.x * 64;
    int hh = blockIdx.y;
    int b  = blockIdx.z;
    int tid = threadIdx.x;

    for (int idx = tid; idx < 256 * 32; idx += 256) {
        int m = idx >> 5, d = idx & 31;
        const float* kvrow = kv + ((size_t)b * NK + m) * (2 * CC);
        Ks[m * 33 + d] = kvrow[hh * DH + d];
        Vs[m * 33 + d] = kvrow[CC + hh * DH + d];
    }
    for (int idx = tid; idx < 64 * 32; idx += 256) {
        int r = idx >> 5, d = idx & 31;
        Qs[r * 33 + d] = q[((size_t)b * NN + n0 + r) * CC + hh * DH + d];
    }
    __syncthreads();

    int warp = tid >> 5, lane = tid & 31;
    const float scale = 0.17677669529663687f;
    float a = alpha[0];

    for (int rr = 0; rr < 8; rr++) {
        int r = warp * 8 + rr;
        float qreg[32];
#pragma unroll
        for (int d = 0; d < 32; d++) qreg[d] = Qs[r * 33 + d];
        float sc[8];
#pragma unroll
        for (int cc = 0; cc < 8; cc++) {
            int c = cc * 32 + lane;
            float s = 0.f;
#pragma unroll
            for (int d = 0; d < 32; d++) s += qreg[d] * Ks[c * 33 + d];
            sc[cc] = s * scale;
        }
        float mx = sc[0];
#pragma unroll
        for (int cc = 1; cc < 8; cc++) mx = fmaxf(mx, sc[cc]);
#pragma unroll
        for (int off = 16; off > 0; off >>= 1)
            mx = fmaxf(mx, __shfl_xor_sync(0xffffffffu, mx, off));
        float sum = 0.f;
#pragma unroll
        for (int cc = 0; cc < 8; cc++) { sc[cc] = expf(sc[cc] - mx); sum += sc[cc]; }
#pragma unroll
        for (int off = 16; off > 0; off >>= 1)
            sum += __shfl_xor_sync(0xffffffffu, sum, off);
        float inv = (1.0f - a) / sum;
        const float* posr = pos + (((size_t)(b * HH + hh)) * NN + n0 + r) * NK;
#pragma unroll
        for (int cc = 0; cc < 8; cc++) {
            int c = cc * 32 + lane;
            S[r * 257 + c] = sc[cc] * inv + a * posr[c];
        }
    }
    __syncthreads();

    for (int rr = 0; rr < 8; rr++) {
        int r = warp * 8 + rr;
        float acc = 0.f;
#pragma unroll 8
        for (int c = 0; c < 256; c++) acc += S[r * 257 + c] * Vs[c * 33 + lane];
        size_t off = ((size_t)b * NN + n0 + r) * CC + hh * DH + lane;
        __nv_bfloat16 hv = __float2bfloat16(acc);
        ohi[off] = hv;
        olo[off] = __float2bfloat16(acc - __bfloat162float(hv));
    }
}

// ---------------- depthwise 3x3 + exact GELU -> bf16 split ----------------
__global__ void dw_gelu(const float* __restrict__ m, const float* __restrict__ w,
                        const float* __restrict__ bias, __nv_bfloat16* __restrict__ mihi,
                        __nv_bfloat16* __restrict__ milo)
{
    int y = blockIdx.x;
    int b = blockIdx.y;
    for (int idx = threadIdx.x; idx < HW * (HID / 4); idx += blockDim.x) {
        int x  = idx >> 8;
        int c4 = idx & 255;
        int c  = c4 * 4;
        float4 acc = *reinterpret_cast<const float4*>(bias + c);
        float wr[9][4];
#pragma unroll
        for (int tap = 0; tap < 9; tap++)
#pragma unroll
            for (int j = 0; j < 4; j++)
                wr[tap][j] = w[(c + j) * 9 + tap];
#pragma unroll
        for (int dy = -1; dy <= 1; dy++) {
            int yy = y + dy;
            if (yy < 0 || yy >= HW) continue;
#pragma unroll
            for (int dx = -1; dx <= 1; dx++) {
                int xx = x + dx;
                if (xx < 0 || xx >= HW) continue;
                int tap = (dy + 1) * 3 + (dx + 1);
                float4 v = *reinterpret_cast<const float4*>(
                    m + ((size_t)b * NN + yy * HW + xx) * HID + c);
                acc.x += v.x * wr[tap][0];
                acc.y += v.y * wr[tap][1];
                acc.z += v.z * wr[tap][2];
                acc.w += v.w * wr[tap][3];
            }
        }
        float gv[4];
        gv[0] = 0.5f * acc.x * (1.0f + erff(acc.x * 0.70710678118654752f));
        gv[1] = 0.5f * acc.y * (1.0f + erff(acc.y * 0.70710678118654752f));
        gv[2] = 0.5f * acc.z * (1.0f + erff(acc.z * 0.70710678118654752f));
        gv[3] = 0.5f * acc.w * (1.0f + erff(acc.w * 0.70710678118654752f));
        __align__(8) __nv_bfloat16 hb[4];
        __align__(8) __nv_bfloat16 lb[4];
#pragma unroll
        for (int j = 0; j < 4; j++) {
            hb[j] = __float2bfloat16(gv[j]);
            lb[j] = __float2bfloat16(gv[j] - __bfloat162float(hb[j]));
        }
        size_t off = ((size_t)b * NN + y * HW + x) * HID + c;
        *reinterpret_cast<uint2*>(mihi + off) = *reinterpret_cast<uint2*>(hb);
        *reinterpret_cast<uint2*>(milo + off) = *reinterpret_cast<uint2*>(lb);
    }
}

// ---------------- launch ----------------
extern "C" void kernel_launch(void* const* d_in, const int* in_sizes, int n_in,
                              void* d_out, int out_size)
{
    const float* x      = (const float*)d_in[0];
    const float* pos2d  = (const float*)d_in[1];
    const float* ln1_w  = (const float*)d_in[2];
    const float* ln1_b  = (const float*)d_in[3];
    const float* q_w    = (const float*)d_in[4];
    const float* q_b    = (const float*)d_in[5];
    const float* kv_w   = (const float*)d_in[6];
    const float* kv_b   = (const float*)d_in[7];
    const float* sr_w   = (const float*)d_in[8];
    const float* sr_b   = (const float*)d_in[9];
    const float* srn_w  = (const float*)d_in[10];
    const float* srn_b  = (const float*)d_in[11];
    const float* alpha  = (const float*)d_in[12];
    const float* proj_w = (const float*)d_in[13];
    const float* proj_b = (const float*)d_in[14];
    const float* ln2_w  = (const float*)d_in[15];
    const float* ln2_b  = (const float*)d_in[16];
    const float* fc1_w  = (const float*)d_in[17];
    const float* fc1_b  = (const float*)d_in[18];
    const float* dw_w   = (const float*)d_in[19];
    const float* dw_b   = (const float*)d_in[20];
    const float* fc2_w  = (const float*)d_in[21];
    const float* fc2_b  = (const float*)d_in[22];
    float* out = (float*)d_out;

    __nv_bfloat16 *h_hi, *h_lo, *hp_hi, *hp_lo, *wtT_hi, *wtT_lo, *hs_hi, *hs_lo;
    __nv_bfloat16 *o_hi, *o_lo, *h2_hi, *h2_lo, *mi_hi, *mi_lo;
    __nv_bfloat16 *qT_hi, *qT_lo, *kvT_hi, *kvT_lo, *pjT_hi, *pjT_lo, *f1T_hi, *f1T_lo, *f2T_hi, *f2T_lo;
    float *hs, *q, *kv, *x1, *m, *part;
    cudaGetSymbolAddress((void**)&h_hi,  g_h_hi);   cudaGetSymbolAddress((void**)&h_lo,  g_h_lo);
    cudaGetSymbolAddress((void**)&hp_hi, g_hp_hi);  cudaGetSymbolAddress((void**)&hp_lo, g_hp_lo);
    cudaGetSymbolAddress((void**)&wtT_hi,g_wtT_hi); cudaGetSymbolAddress((void**)&wtT_lo,g_wtT_lo);
    cudaGetSymbolAddress((void**)&hs,    g_hs);
    cudaGetSymbolAddress((void**)&hs_hi, g_hs_hi);  cudaGetSymbolAddress((void**)&hs_lo, g_hs_lo);
    cudaGetSymbolAddress((void**)&q,     g_q);
    cudaGetSymbolAddress((void**)&kv,    g_kv);
    cudaGetSymbolAddress((void**)&o_hi,  g_o_hi);   cudaGetSymbolAddress((void**)&o_lo,  g_o_lo);
    cudaGetSymbolAddress((void**)&x1,    g_x1);
    cudaGetSymbolAddress((void**)&h2_hi, g_h2_hi);  cudaGetSymbolAddress((void**)&h2_lo, g_h2_lo);
    cudaGetSymbolAddress((void**)&m,     g_m);
    cudaGetSymbolAddress((void**)&mi_hi, g_mi_hi);  cudaGetSymbolAddress((void**)&mi_lo, g_mi_lo);
    cudaGetSymbolAddress((void**)&part,  g_part);
    cudaGetSymbolAddress((void**)&qT_hi, g_qT_hi);  cudaGetSymbolAddress((void**)&qT_lo, g_qT_lo);
    cudaGetSymbolAddress((void**)&kvT_hi,g_kvT_hi); cudaGetSymbolAddress((void**)&kvT_lo,g_kvT_lo);
    cudaGetSymbolAddress((void**)&pjT_hi,g_pjT_hi); cudaGetSymbolAddress((void**)&pjT_lo,g_pjT_lo);
    cudaGetSymbolAddress((void**)&f1T_hi,g_f1T_hi); cudaGetSymbolAddress((void**)&f1T_lo,g_f1T_lo);
    cudaGetSymbolAddress((void**)&f2T_hi,g_f2T_hi); cudaGetSymbolAddress((void**)&f2T_lo,g_f2T_lo);

    static bool cfg = false;
    if (!cfg) {
        cudaFuncSetAttribute(gemm_mma, cudaFuncAttributeMaxDynamicSharedMemorySize, GEMM_SMEM);
        cudaFuncSetAttribute(attn_kernel, cudaFuncAttributeMaxDynamicSharedMemorySize,
                             ATTN_SMEM_FLOATS * (int)sizeof(float));
        cfg = true;
    }

    const int ROWS = BB * NN;        // 32768
    const int ROWS_SR = BB * NK;     // 2048

    // 1. h = LN1(x) -> split
    ln256_split<<<ROWS / 8, 256>>>(x, ln1_w, ln1_b, h_hi, h_lo, ROWS, 1e-6f);
    // 2. weight prep (independent; interleaved for overlap)
    wtsplit<<<(CC * CC) / 256, 256>>>(q_w, qT_hi, qT_lo, CC, CC);
    wtrans_split<<<(CC * KPATCH) / 256, 256>>>(sr_w, wtT_hi, wtT_lo);
    wtsplit<<<(CC * 2 * CC) / 256, 256>>>(kv_w, kvT_hi, kvT_lo, CC, 2 * CC);
    wtsplit<<<(CC * CC) / 256, 256>>>(proj_w, pjT_hi, pjT_lo, CC, CC);
    wtsplit<<<(CC * HID) / 256, 256>>>(fc1_w, f1T_hi, f1T_lo, CC, HID);
    wtsplit<<<(HID * CC) / 256, 256>>>(fc2_w, f2T_hi, f2T_lo, HID, CC);
    // 3. q = h @ q_w + q_b
    gemm_mma<<<dim3(CC / 128, ROWS / 128), 256, GEMM_SMEM>>>(h_hi, h_lo, qT_hi, qT_lo,
                                                             q_b, nullptr, q, ROWS, CC, CC, 1);
    // 4. patch gather
    patchify_bf16<<<(int)(((size_t)BB * NK * 16 * 128) / 256), 256>>>(
        (const uint32_t*)h_hi, (const uint32_t*)h_lo, (uint32_t*)hp_hi, (uint32_t*)hp_lo);
    // 5. SR GEMM (split-K=4): part[z] = hp @ wt; hs = sum + sr_b
    gemm_mma<<<dim3(CC / 128, ROWS_SR / 128, 4), 256, GEMM_SMEM>>>(hp_hi, hp_lo, wtT_hi, wtT_lo,
                                                                   nullptr, nullptr, part,
                                                                   ROWS_SR, CC, KPATCH, 4);
    reduceK<<<(ROWS_SR * CC + 255) / 256, 256>>>(part, sr_b, hs, ROWS_SR * CC, CC, 4);
    // 6. srn LN -> split
    ln256_split<<<ROWS_SR / 8, 256>>>(hs, srn_w, srn_b, hs_hi, hs_lo, ROWS_SR, 1e-5f);
    // 7. kv = hs @ kv_w + kv_b
    gemm_mma<<<dim3((2 * CC) / 128, ROWS_SR / 128), 256, GEMM_SMEM>>>(hs_hi, hs_lo, kvT_hi, kvT_lo,
                                                                      kv_b, nullptr, kv, ROWS_SR, 2 * CC, CC, 1);
    // 8. fused attention -> o split
    attn_kernel<<<dim3(NN / 64, HH, BB), 256, ATTN_SMEM_FLOATS * sizeof(float)>>>(
        q, kv, pos2d, alpha, o_hi, o_lo);
    // 9. proj: x1 = x + o @ proj_w + proj_b
    gemm_mma<<<dim3(CC / 128, ROWS / 128), 256, GEMM_SMEM>>>(o_hi, o_lo, pjT_hi, pjT_lo,
                                                             proj_b, x, x1, ROWS, CC, CC, 1);
    // 10. h2 = LN2(x1) -> split
    ln256_split<<<ROWS / 8, 256>>>(x1, ln2_w, ln2_b, h2_hi, h2_lo, ROWS, 1e-6f);
    // 11. fc1: m = h2 @ fc1_w + fc1_b
    gemm_mma<<<dim3(HID / 128, ROWS / 128), 256, GEMM_SMEM>>>(h2_hi, h2_lo, f1T_hi, f1T_lo,
                                                              fc1_b, nullptr, m, ROWS, HID, CC, 1);
    // 12. depthwise conv + gelu -> mi split
    dw_gelu<<<dim3(HW, BB), 512>>>(m, dw_w, dw_b, mi_hi, mi_lo);
    // 13. fc2: out = x1 + mi @ fc2_w + fc2_b
    gemm_mma<<<dim3(CC / 128, ROWS / 128), 256, GEMM_SMEM>>>(mi_hi, mi_lo, f2T_hi, f2T_lo,
                                                             fc2_b, x1, out, ROWS, CC, HID, 1);
}

// round 5
// speedup vs baseline: 1.8937x; 1.1631x over previous
#include <cuda_runtime.h>
#include <cuda_fp16.h>
#include <math.h>
#include <stdint.h>

// Problem dims (fixed)
#define BB   8
#define NN   4096
#define CC   256
#define HH   8
#define DH   32
#define HW   64
#define NK   256
#define HID  1024
#define KPATCH 4096   // C * SR * SR

// ---------------- scratch (device globals; no allocation) ----------------
__device__ __half g_h_h [(size_t)BB*NN*CC];
__device__ __half g_hp_h[(size_t)BB*NK*KPATCH];
__device__ __half g_wtT [(size_t)CC*KPATCH];
__device__ float  g_hs  [(size_t)BB*NK*CC];
__device__ __half g_hs_h[(size_t)BB*NK*CC];
__device__ float  g_q   [(size_t)BB*NN*CC];
__device__ float  g_kv  [(size_t)BB*NK*2*CC];
__device__ __half g_o_h [(size_t)BB*NN*CC];
__device__ float  g_x1  [(size_t)BB*NN*CC];
__device__ __half g_h2_h[(size_t)BB*NN*CC];
__device__ __half g_m_h [(size_t)BB*NN*HID];
__device__ __half g_mi_h[(size_t)BB*NN*HID];
__device__ float  g_part[(size_t)8*BB*NK*CC];   // split-K partials
// transposed weights [N x K] fp16
__device__ __half g_qT [CC*CC];
__device__ __half g_kvT[2*CC*CC];
__device__ __half g_pjT[CC*CC];
__device__ __half g_f1T[HID*CC];
__device__ __half g_f2T[CC*HID];

// ---------------- PTX helpers (legal on base compute_103 target) ----------------
__device__ __forceinline__ uint32_t smem_u32(const void* p) {
    uint32_t a;
    asm("{ .reg .u64 t; cvta.to.shared.u64 t, %1; cvt.u32.u64 %0, t; }" : "=r"(a) : "l"(p));
    return a;
}
__device__ __forceinline__ void cpasync16(uint32_t dst, const void* src) {
    asm volatile("cp.async.cg.shared.global [%0], [%1], 16;" :: "r"(dst), "l"(src) : "memory");
}
__device__ __forceinline__ void cpcommit() {
    asm volatile("cp.async.commit_group;" ::: "memory");
}
template<int Ngrp> __device__ __forceinline__ void cpwait() {
    asm volatile("cp.async.wait_group %0;" :: "n"(Ngrp) : "memory");
}
__device__ __forceinline__ void ldm4(uint32_t* r, uint32_t addr) {
    asm volatile("ldmatrix.sync.aligned.m8n8.x4.shared.b16 {%0,%1,%2,%3}, [%4];"
                 : "=r"(r[0]), "=r"(r[1]), "=r"(r[2]), "=r"(r[3]) : "r"(addr));
}
__device__ __forceinline__ void mma16816h(float* c, const uint32_t* a, const uint32_t* b) {
    asm volatile("mma.sync.aligned.m16n8k16.row.col.f32.f16.f16.f32 "
                 "{%0,%1,%2,%3}, {%4,%5,%6,%7}, {%8,%9}, {%0,%1,%2,%3};"
                 : "+f"(c[0]), "+f"(c[1]), "+f"(c[2]), "+f"(c[3])
                 : "r"(a[0]), "r"(a[1]), "r"(a[2]), "r"(a[3]), "r"(b[0]), "r"(b[1]));
}

// ---------------- fp16 tensor GEMM via mma.sync ----------------
// C[M,N] = A @ B^T (+bias)(+res).  A:[M,K] fp16, Bt:[N,K] fp16, K-major.
// CTA tile 128x128, BK=32, 8 warps (2 M x 4 N), warp tile 64x32.
// smem per stage: A | B, each 128 rows x 80B stride (conflict-free ldmatrix).
#define GEMM_SMEM (2 * 20480)

__global__ __launch_bounds__(256, 2)
void gemm_h(const __half* __restrict__ A, const __half* __restrict__ Bt,
            const float* __restrict__ bias, const float* __restrict__ res,
            float* __restrict__ Cf, __half* __restrict__ Ch,
            int M, int N, int K, int splitK)
{
    extern __shared__ char sm[];
    uint32_t sb = smem_u32(sm);
    const int tid  = threadIdx.x;
    const int warp = tid >> 5, lane = tid & 31;
    const int n0 = blockIdx.x * 128, m0 = blockIdx.y * 128;
    const int Keff  = K / splitK;
    const int kbase = blockIdx.z * Keff;
    if (splitK > 1) Cf += (size_t)blockIdx.z * M * N;
    const int nk = Keff / 32;
    const int wm0 = (warp >> 2) * 64, wn0 = (warp & 3) * 32;

    float c[4][4][4];
#pragma unroll
    for (int i = 0; i < 4; i++)
#pragma unroll
        for (int j = 0; j < 4; j++)
#pragma unroll
            for (int k = 0; k < 4; k++) c[i][j][k] = 0.f;

    const int lrow = tid >> 2;      // 0..63
    const int lq   = tid & 3;

    auto load_stage = [&](int i, int s) {
        const int k0 = kbase + i * 32;
        const uint32_t st = sb + s * 20480;
#pragma unroll
        for (int e = 0; e < 2; e++) {
            int r = lrow + e * 64;
            cpasync16(st +         r * 80 + lq * 16, A  + (size_t)(m0 + r) * K + k0 + lq * 8);
            cpasync16(st + 10240 + r * 80 + lq * 16, Bt + (size_t)(n0 + r) * K + k0 + lq * 8);
        }
        cpcommit();
    };

    auto compute_stage = [&](int s) {
        const uint32_t st = sb + s * 20480;
#pragma unroll
        for (int h = 0; h < 2; h++) {            // two k16 halves of BK=32
            uint32_t a[4][4], bfr[4][2];
#pragma unroll
            for (int mt = 0; mt < 4; mt++) {
                int r = wm0 + mt * 16 + (lane & 15);
                ldm4(a[mt], st + r * 80 + h * 32 + (lane >> 4) * 16);
            }
#pragma unroll
            for (int ng = 0; ng < 2; ng++) {
                int r = wn0 + ng * 16 + (lane & 15);
                uint32_t t[4];
                ldm4(t, st + 10240 + r * 80 + h * 32 + (lane >> 4) * 16);
                bfr[2*ng][0] = t[0]; bfr[2*ng][1] = t[2];
                bfr[2*ng+1][0] = t[1]; bfr[2*ng+1][1] = t[3];
            }
#pragma unroll
            for (int mt = 0; mt < 4; mt++)
#pragma unroll
                for (int nt = 0; nt < 4; nt++)
                    mma16816h(c[mt][nt], a[mt], bfr[nt]);
        }
    };

    load_stage(0, 0);
    for (int i = 0; i < nk; i++) {
        if (i + 1 < nk) { load_stage(i + 1, (i + 1) & 1); cpwait<1>(); }
        else            { cpwait<0>(); }
        __syncthreads();
        compute_stage(i & 1);
        __syncthreads();
    }

    // epilogue
#pragma unroll
    for (int mt = 0; mt < 4; mt++)
#pragma unroll
        for (int nt = 0; nt < 4; nt++) {
            int row = m0 + wm0 + mt * 16 + (lane >> 2);
            int col = n0 + wn0 + nt * 8 + (lane & 3) * 2;
            float v0 = c[mt][nt][0], v1 = c[mt][nt][1];
            float v2 = c[mt][nt][2], v3 = c[mt][nt][3];
            if (splitK == 1) {
                float b0 = bias[col], b1 = bias[col + 1];
                v0 += b0; v1 += b1; v2 += b0; v3 += b1;
                if (res) {
                    const float* r0 = res + (size_t)row * N + col;
                    const float* r1 = res + (size_t)(row + 8) * N + col;
                    v0 += r0[0]; v1 += r0[1]; v2 += r1[0]; v3 += r1[1];
                }
            }
            if (Ch) {
                *reinterpret_cast<__half2*>(Ch + (size_t)row * N + col)       = __floats2half2_rn(v0, v1);
                *reinterpret_cast<__half2*>(Ch + (size_t)(row + 8) * N + col) = __floats2half2_rn(v2, v3);
            } else {
                *reinterpret_cast<float2*>(Cf + (size_t)row * N + col)       = make_float2(v0, v1);
                *reinterpret_cast<float2*>(Cf + (size_t)(row + 8) * N + col) = make_float2(v2, v3);
            }
        }
}

// ---------------- split-K reduce: out = sum_z part[z] + bias ----------------
__global__ void reduceK(const float* __restrict__ part, const float* __restrict__ bias,
                        float* __restrict__ out, int MN, int N, int S)
{
    int idx = blockIdx.x * blockDim.x + threadIdx.x;
    if (idx >= MN) return;
    float s = bias[idx % N];
    for (int z = 0; z < S; z++) s += part[(size_t)z * MN + idx];
    out[idx] = s;
}

// ---------------- LayerNorm(256) -> fp16 ----------------
__global__ void ln256_h(const float* __restrict__ x, const float* __restrict__ w,
                        const float* __restrict__ b, __half* __restrict__ y,
                        int rows, float eps)
{
    int row  = blockIdx.x * 8 + (threadIdx.x >> 5);
    int lane = threadIdx.x & 31;
    if (row >= rows) return;
    const float* xr = x + (size_t)row * 256;
    float4 v0 = *reinterpret_cast<const float4*>(xr + lane * 8);
    float4 v1 = *reinterpret_cast<const float4*>(xr + lane * 8 + 4);
    float vals[8] = {v0.x, v0.y, v0.z, v0.w, v1.x, v1.y, v1.z, v1.w};
    float s = 0.f, sq = 0.f;
#pragma unroll
    for (int i = 0; i < 8; i++) { s += vals[i]; sq += vals[i] * vals[i]; }
#pragma unroll
    for (int o = 16; o > 0; o >>= 1) {
        s  += __shfl_xor_sync(0xffffffffu, s, o);
        sq += __shfl_xor_sync(0xffffffffu, sq, o);
    }
    float mean = s * (1.0f / 256.0f);
    float var  = sq * (1.0f / 256.0f) - mean * mean;
    float rs   = rsqrtf(var + eps);
    __align__(16) __half hb[8];
#pragma unroll
    for (int i = 0; i < 8; i++) {
        int c = lane * 8 + i;
        hb[i] = __float2half_rn((vals[i] - mean) * rs * w[c] + b[c]);
    }
    *reinterpret_cast<uint4*>(y + (size_t)row * 256 + lane * 8) = *reinterpret_cast<uint4*>(hb);
}

// ---------------- weight transpose -> fp16: Bt[n][k] = B[k][n] ----------------
__global__ void wtsplit_h(const float* __restrict__ B, __half* __restrict__ t, int K, int N)
{
    int idx = blockIdx.x * blockDim.x + threadIdx.x;
    if (idx >= N * K) return;
    int n = idx / K, k = idx - n * K;
    t[idx] = __float2half_rn(B[(size_t)k * N + n]);
}

// sr_w [co][ci][ky][kx] -> wtT[co][(ky*4+kx)*256+ci]
__global__ void wtrans_h(const float* __restrict__ srw, __half* __restrict__ t)
{
    int idx = blockIdx.x * blockDim.x + threadIdx.x;   // CC * KPATCH
    int co = idx >> 12;
    int k  = idx & 4095;
    int ks = k >> 8, ci = k & 255;
    t[idx] = __float2half_rn(srw[(size_t)co * KPATCH + ci * 16 + ks]);
}

// ---------------- patch gather (fp16, 2 elems per thread via uint32) ----------------
__global__ void patchify_h(const uint32_t* __restrict__ h, uint32_t* __restrict__ hp)
{
    size_t idx = (size_t)blockIdx.x * blockDim.x + threadIdx.x;  // B*NK*16*128
    int ci2 = idx & 127;
    size_t t = idx >> 7;
    int ks = t & 15; t >>= 4;
    int nk = t & 255; int b = (int)(t >> 8);
    int ky = ks >> 2, kx = ks & 3;
    int n = ((nk >> 4) * 4 + ky) * HW + (nk & 15) * 4 + kx;
    hp[idx] = h[((size_t)b * NN + n) * 128 + ci2];
}

// ---------------- fused SR attention (outputs fp16) ----------------
#define ATTN_SMEM_FLOATS (64*33 + 256*33 + 256*33 + 64*257)
__global__ void attn_kernel(const float* __restrict__ q, const float* __restrict__ kv,
                            const float* __restrict__ pos, const float* __restrict__ alpha,
                            __half* __restrict__ o)
{
    extern __shared__ float smf[];
    float* Qs = smf;
    float* Ks = Qs + 64 * 33;
    float* Vs = Ks + 256 * 33;
    float* S  = Vs + 256 * 33;

    int n0 = blockIdx.x * 64;
    int hh = blockIdx.y;
    int b  = blockIdx.z;
    int tid = threadIdx.x;

    for (int idx = tid; idx < 256 * 32; idx += 256) {
        int m = idx >> 5, d = idx & 31;
        const float* kvrow = kv + ((size_t)b * NK + m) * (2 * CC);
        Ks[m * 33 + d] = kvrow[hh * DH + d];
        Vs[m * 33 + d] = kvrow[CC + hh * DH + d];
    }
    for (int idx = tid; idx < 64 * 32; idx += 256) {
        int r = idx >> 5, d = idx & 31;
        Qs[r * 33 + d] = q[((size_t)b * NN + n0 + r) * CC + hh * DH + d];
    }
    __syncthreads();

    int warp = tid >> 5, lane = tid & 31;
    const float scale = 0.17677669529663687f;
    float a = alpha[0];

    for (int rr = 0; rr < 8; rr++) {
        int r = warp * 8 + rr;
        float qreg[32];
#pragma unroll
        for (int d = 0; d < 32; d++) qreg[d] = Qs[r * 33 + d];
        float sc[8];
#pragma unroll
        for (int cc = 0; cc < 8; cc++) {
            int c = cc * 32 + lane;
            float s = 0.f;
#pragma unroll
            for (int d = 0; d < 32; d++) s += qreg[d] * Ks[c * 33 + d];
            sc[cc] = s * scale;
        }
        float mx = sc[0];
#pragma unroll
        for (int cc = 1; cc < 8; cc++) mx = fmaxf(mx, sc[cc]);
#pragma unroll
        for (int off = 16; off > 0; off >>= 1)
            mx = fmaxf(mx, __shfl_xor_sync(0xffffffffu, mx, off));
        float sum = 0.f;
#pragma unroll
        for (int cc = 0; cc < 8; cc++) { sc[cc] = expf(sc[cc] - mx); sum += sc[cc]; }
#pragma unroll
        for (int off = 16; off > 0; off >>= 1)
            sum += __shfl_xor_sync(0xffffffffu, sum, off);
        float inv = (1.0f - a) / sum;
        const float* posr = pos + (((size_t)(b * HH + hh)) * NN + n0 + r) * NK;
#pragma unroll
        for (int cc = 0; cc < 8; cc++) {
            int c = cc * 32 + lane;
            S[r * 257 + c] = sc[cc] * inv + a * posr[c];
        }
    }
    __syncthreads();

    for (int rr = 0; rr < 8; rr++) {
        int r = warp * 8 + rr;
        float acc = 0.f;
#pragma unroll 8
        for (int c = 0; c < 256; c++) acc += S[r * 257 + c] * Vs[c * 33 + lane];
        o[((size_t)b * NN + n0 + r) * CC + hh * DH + lane] = __float2half_rn(acc);
    }
}

// ---------------- depthwise 3x3 + exact GELU (fp16 in/out) ----------------
__global__ void dw_gelu(const __half* __restrict__ m, const float* __restrict__ w,
                        const float* __restrict__ bias, __half* __restrict__ mi)
{
    int y = blockIdx.x;
    int b = blockIdx.y;
    for (int idx = threadIdx.x; idx < HW * (HID / 4); idx += blockDim.x) {
        int x  = idx >> 8;
        int c4 = idx & 255;
        int c  = c4 * 4;
        float4 bi = *reinterpret_cast<const float4*>(bias + c);
        float acc[4] = {bi.x, bi.y, bi.z, bi.w};
        float wr[9][4];
#pragma unroll
        for (int tap = 0; tap < 9; tap++)
#pragma unroll
            for (int j = 0; j < 4; j++)
                wr[tap][j] = w[(c + j) * 9 + tap];
#pragma unroll
        for (int dy = -1; dy <= 1; dy++) {
            int yy = y + dy;
            if (yy < 0 || yy >= HW) continue;
#pragma unroll
            for (int dx = -1; dx <= 1; dx++) {
                int xx = x + dx;
                if (xx < 0 || xx >= HW) continue;
                int tap = (dy + 1) * 3 + (dx + 1);
                const __half2* p = reinterpret_cast<const __half2*>(
                    m + ((size_t)b * NN + yy * HW + xx) * HID + c);
                float2 f01 = __half22float2(p[0]);
                float2 f23 = __half22float2(p[1]);
                acc[0] += f01.x * wr[tap][0];
                acc[1] += f01.y * wr[tap][1];
                acc[2] += f23.x * wr[tap][2];
                acc[3] += f23.y * wr[tap][3];
            }
        }
        float gv[4];
#pragma unroll
        for (int j = 0; j < 4; j++)
            gv[j] = 0.5f * acc[j] * (1.0f + erff(acc[j] * 0.70710678118654752f));
        __half2 o01 = __floats2half2_rn(gv[0], gv[1]);
        __half2 o23 = __floats2half2_rn(gv[2], gv[3]);
        __half2* op = reinterpret_cast<__half2*>(mi + ((size_t)b * NN + y * HW + x) * HID + c);
        op[0] = o01;
        op[1] = o23;
    }
}

// ---------------- launch ----------------
extern "C" void kernel_launch(void* const* d_in, const int* in_sizes, int n_in,
                              void* d_out, int out_size)
{
    const float* x      = (const float*)d_in[0];
    const float* pos2d  = (const float*)d_in[1];
    const float* ln1_w  = (const float*)d_in[2];
    const float* ln1_b  = (const float*)d_in[3];
    const float* q_w    = (const float*)d_in[4];
    const float* q_b    = (const float*)d_in[5];
    const float* kv_w   = (const float*)d_in[6];
    const float* kv_b   = (const float*)d_in[7];
    const float* sr_w   = (const float*)d_in[8];
    const float* sr_b   = (const float*)d_in[9];
    const float* srn_w  = (const float*)d_in[10];
    const float* srn_b  = (const float*)d_in[11];
    const float* alpha  = (const float*)d_in[12];
    const float* proj_w = (const float*)d_in[13];
    const float* proj_b = (const float*)d_in[14];
    const float* ln2_w  = (const float*)d_in[15];
    const float* ln2_b  = (const float*)d_in[16];
    const float* fc1_w  = (const float*)d_in[17];
    const float* fc1_b  = (const float*)d_in[18];
    const float* dw_w   = (const float*)d_in[19];
    const float* dw_b   = (const float*)d_in[20];
    const float* fc2_w  = (const float*)d_in[21];
    const float* fc2_b  = (const float*)d_in[22];
    float* out = (float*)d_out;

    __half *h_h, *hp_h, *wtT, *hs_h, *o_h, *h2_h, *m_h, *mi_h;
    __half *qT, *kvT, *pjT, *f1T, *f2T;
    float *hs, *q, *kv, *x1, *part;
    cudaGetSymbolAddress((void**)&h_h,  g_h_h);
    cudaGetSymbolAddress((void**)&hp_h, g_hp_h);
    cudaGetSymbolAddress((void**)&wtT,  g_wtT);
    cudaGetSymbolAddress((void**)&hs,   g_hs);
    cudaGetSymbolAddress((void**)&hs_h, g_hs_h);
    cudaGetSymbolAddress((void**)&q,    g_q);
    cudaGetSymbolAddress((void**)&kv,   g_kv);
    cudaGetSymbolAddress((void**)&o_h,  g_o_h);
    cudaGetSymbolAddress((void**)&x1,   g_x1);
    cudaGetSymbolAddress((void**)&h2_h, g_h2_h);
    cudaGetSymbolAddress((void**)&m_h,  g_m_h);
    cudaGetSymbolAddress((void**)&mi_h, g_mi_h);
    cudaGetSymbolAddress((void**)&part, g_part);
    cudaGetSymbolAddress((void**)&qT,   g_qT);
    cudaGetSymbolAddress((void**)&kvT,  g_kvT);
    cudaGetSymbolAddress((void**)&pjT,  g_pjT);
    cudaGetSymbolAddress((void**)&f1T,  g_f1T);
    cudaGetSymbolAddress((void**)&f2T,  g_f2T);

    static bool cfg = false;
    if (!cfg) {
        cudaFuncSetAttribute(gemm_h, cudaFuncAttributeMaxDynamicSharedMemorySize, GEMM_SMEM);
        cudaFuncSetAttribute(attn_kernel, cudaFuncAttributeMaxDynamicSharedMemorySize,
                             ATTN_SMEM_FLOATS * (int)sizeof(float));
        cfg = true;
    }

    const int ROWS = BB * NN;        // 32768
    const int ROWS_SR = BB * NK;     // 2048

    // 1. h = LN1(x) -> fp16
    ln256_h<<<ROWS / 8, 256>>>(x, ln1_w, ln1_b, h_h, ROWS, 1e-6f);
    // 2. weight prep
    wtsplit_h<<<(CC * CC) / 256, 256>>>(q_w, qT, CC, CC);
    wtrans_h<<<(CC * KPATCH) / 256, 256>>>(sr_w, wtT);
    wtsplit_h<<<(CC * 2 * CC) / 256, 256>>>(kv_w, kvT, CC, 2 * CC);
    wtsplit_h<<<(CC * CC) / 256, 256>>>(proj_w, pjT, CC, CC);
    wtsplit_h<<<(CC * HID) / 256, 256>>>(fc1_w, f1T, CC, HID);
    wtsplit_h<<<(HID * CC) / 256, 256>>>(fc2_w, f2T, HID, CC);
    // 3. q = h @ q_w + q_b
    gemm_h<<<dim3(CC / 128, ROWS / 128), 256, GEMM_SMEM>>>(h_h, qT, q_b, nullptr,
                                                           q, nullptr, ROWS, CC, CC, 1);
    // 4. patch gather
    patchify_h<<<(int)(((size_t)BB * NK * 16 * 128) / 256), 256>>>(
        (const uint32_t*)h_h, (uint32_t*)hp_h);
    // 5. SR GEMM (split-K=8): part[z] = hp @ wt; hs = sum + sr_b
    gemm_h<<<dim3(CC / 128, ROWS_SR / 128, 8), 256, GEMM_SMEM>>>(hp_h, wtT, nullptr, nullptr,
                                                                 part, nullptr, ROWS_SR, CC, KPATCH, 8);
    reduceK<<<(ROWS_SR * CC + 255) / 256, 256>>>(part, sr_b, hs, ROWS_SR * CC, CC, 8);
    // 6. srn LN -> fp16
    ln256_h<<<ROWS_SR / 8, 256>>>(hs, srn_w, srn_b, hs_h, ROWS_SR, 1e-5f);
    // 7. kv = hs @ kv_w + kv_b
    gemm_h<<<dim3((2 * CC) / 128, ROWS_SR / 128), 256, GEMM_SMEM>>>(hs_h, kvT, kv_b, nullptr,
                                                                    kv, nullptr, ROWS_SR, 2 * CC, CC, 1);
    // 8. fused attention -> o fp16
    attn_kernel<<<dim3(NN / 64, HH, BB), 256, ATTN_SMEM_FLOATS * sizeof(float)>>>(
        q, kv, pos2d, alpha, o_h);
    // 9. proj: x1 = x + o @ proj_w + proj_b
    gemm_h<<<dim3(CC / 128, ROWS / 128), 256, GEMM_SMEM>>>(o_h, pjT, proj_b, x,
                                                           x1, nullptr, ROWS, CC, CC, 1);
    // 10. h2 = LN2(x1) -> fp16
    ln256_h<<<ROWS / 8, 256>>>(x1, ln2_w, ln2_b, h2_h, ROWS, 1e-6f);
    // 11. fc1: m = h2 @ fc1_w + fc1_b  (fp16 out)
    gemm_h<<<dim3(HID / 128, ROWS / 128), 256, GEMM_SMEM>>>(h2_h, f1T, fc1_b, nullptr,
                                                            nullptr, m_h, ROWS, HID, CC, 1);
    // 12. depthwise conv + gelu (fp16 in/out)
    dw_gelu<<<dim3(HW, BB), 512>>>(m_h, dw_w, dw_b, mi_h);
    // 13. fc2: out = x1 + mi @ fc2_w + fc2_b
    gemm_h<<<dim3(CC / 128, ROWS / 128), 256, GEMM_SMEM>>>(mi_h, f2T, fc2_b, x1,
                                                           out, nullptr, ROWS, CC, HID, 1);
}

// round 8
// speedup vs baseline: 4.0010x; 2.1128x over previous
#include <cuda_runtime.h>
#include <cuda_fp16.h>
#include <math.h>
#include <stdint.h>

// Problem dims (fixed)
#define BB   8
#define NN   4096
#define CC   256
#define HH   8
#define DH   32
#define HW   64
#define NK   256
#define HID  1024
#define KPATCH 4096   // C * SR * SR

// ---------------- scratch (device globals; no allocation) ----------------
__device__ __half g_h_h [(size_t)BB*NN*CC];
__device__ __half g_hp_h[(size_t)BB*NK*KPATCH];
__device__ __half g_wtT [(size_t)CC*KPATCH];
__device__ float  g_hs  [(size_t)BB*NK*CC];
__device__ __half g_hs_h[(size_t)BB*NK*CC];
__device__ __half g_q_h [(size_t)BB*NN*CC];
__device__ __half g_kv_h[(size_t)BB*NK*2*CC];
__device__ __half g_o_h [(size_t)BB*NN*CC];
__device__ float  g_x1  [(size_t)BB*NN*CC];
__device__ __half g_h2_h[(size_t)BB*NN*CC];
__device__ __half g_m_h [(size_t)BB*NN*HID];
__device__ __half g_mi_h[(size_t)BB*NN*HID];
__device__ float  g_part[(size_t)8*BB*NK*CC];   // split-K partials
// transposed weights [N x K] fp16
__device__ __half g_qT [CC*CC];
__device__ __half g_kvT[2*CC*CC];
__device__ __half g_pjT[CC*CC];
__device__ __half g_f1T[HID*CC];
__device__ __half g_f2T[CC*HID];

// ---------------- PTX helpers (legal on base compute_103 target) ----------------
__device__ __forceinline__ uint32_t smem_u32(const void* p) {
    uint32_t a;
    asm("{ .reg .u64 t; cvta.to.shared.u64 t, %1; cvt.u32.u64 %0, t; }" : "=r"(a) : "l"(p));
    return a;
}
__device__ __forceinline__ void cpasync16(uint32_t dst, const void* src) {
    asm volatile("cp.async.cg.shared.global [%0], [%1], 16;" :: "r"(dst), "l"(src) : "memory");
}
__device__ __forceinline__ void cpcommit() {
    asm volatile("cp.async.commit_group;" ::: "memory");
}
template<int Ngrp> __device__ __forceinline__ void cpwait() {
    asm volatile("cp.async.wait_group %0;" :: "n"(Ngrp) : "memory");
}
__device__ __forceinline__ void ldm4(uint32_t* r, uint32_t addr) {
    asm volatile("ldmatrix.sync.aligned.m8n8.x4.shared.b16 {%0,%1,%2,%3}, [%4];"
                 : "=r"(r[0]), "=r"(r[1]), "=r"(r[2]), "=r"(r[3]) : "r"(addr));
}
__device__ __forceinline__ void mma16816h(float* c, const uint32_t* a, const uint32_t* b) {
    asm volatile("mma.sync.aligned.m16n8k16.row.col.f32.f16.f16.f32 "
                 "{%0,%1,%2,%3}, {%4,%5,%6,%7}, {%8,%9}, {%0,%1,%2,%3};"
                 : "+f"(c[0]), "+f"(c[1]), "+f"(c[2]), "+f"(c[3])
                 : "r"(a[0]), "r"(a[1]), "r"(a[2]), "r"(a[3]), "r"(b[0]), "r"(b[1]));
}
__device__ __forceinline__ uint32_t packh2(float x, float y) {
    __half2 h = __floats2half2_rn(x, y);
    return *reinterpret_cast<uint32_t*>(&h);
}

// ---------------- fp16 tensor GEMM via mma.sync ----------------
// C[M,N] = A @ B^T (+bias)(+res).  A:[M,K] fp16, Bt:[N,K] fp16, K-major.
// CTA tile 128x128, BK=32, 8 warps (2 M x 4 N), warp tile 64x32.
#define GEMM_SMEM (2 * 20480)

__global__ __launch_bounds__(256, 2)
void gemm_h(const __half* __restrict__ A, const __half* __restrict__ Bt,
            const float* __restrict__ bias, const float* __restrict__ res,
            float* __restrict__ Cf, __half* __restrict__ Ch,
            int M, int N, int K, int splitK)
{
    extern __shared__ char sm[];
    uint32_t sb = smem_u32(sm);
    const int tid  = threadIdx.x;
    const int warp = tid >> 5, lane = tid & 31;
    const int n0 = blockIdx.x * 128, m0 = blockIdx.y * 128;
    const int Keff  = K / splitK;
    const int kbase = blockIdx.z * Keff;
    if (splitK > 1) Cf += (size_t)blockIdx.z * M * N;
    const int nk = Keff / 32;
    const int wm0 = (warp >> 2) * 64, wn0 = (warp & 3) * 32;

    float c[4][4][4];
#pragma unroll
    for (int i = 0; i < 4; i++)
#pragma unroll
        for (int j = 0; j < 4; j++)
#pragma unroll
            for (int k = 0; k < 4; k++) c[i][j][k] = 0.f;

    const int lrow = tid >> 2;
    const int lq   = tid & 3;

    auto load_stage = [&](int i, int s) {
        const int k0 = kbase + i * 32;
        const uint32_t st = sb + s * 20480;
#pragma unroll
        for (int e = 0; e < 2; e++) {
            int r = lrow + e * 64;
            cpasync16(st +         r * 80 + lq * 16, A  + (size_t)(m0 + r) * K + k0 + lq * 8);
            cpasync16(st + 10240 + r * 80 + lq * 16, Bt + (size_t)(n0 + r) * K + k0 + lq * 8);
        }
        cpcommit();
    };

    auto compute_stage = [&](int s) {
        const uint32_t st = sb + s * 20480;
#pragma unroll
        for (int h = 0; h < 2; h++) {
            uint32_t a[4][4], bfr[4][2];
#pragma unroll
            for (int mt = 0; mt < 4; mt++) {
                int r = wm0 + mt * 16 + (lane & 15);
                ldm4(a[mt], st + r * 80 + h * 32 + (lane >> 4) * 16);
            }
#pragma unroll
            for (int ng = 0; ng < 2; ng++) {
                int r = wn0 + ng * 16 + (lane & 15);
                uint32_t t[4];
                ldm4(t, st + 10240 + r * 80 + h * 32 + (lane >> 4) * 16);
                bfr[2*ng][0] = t[0]; bfr[2*ng][1] = t[2];
                bfr[2*ng+1][0] = t[1]; bfr[2*ng+1][1] = t[3];
            }
#pragma unroll
            for (int mt = 0; mt < 4; mt++)
#pragma unroll
                for (int nt = 0; nt < 4; nt++)
                    mma16816h(c[mt][nt], a[mt], bfr[nt]);
        }
    };

    load_stage(0, 0);
    for (int i = 0; i < nk; i++) {
        if (i + 1 < nk) { load_stage(i + 1, (i + 1) & 1); cpwait<1>(); }
        else            { cpwait<0>(); }
        __syncthreads();
        compute_stage(i & 1);
        __syncthreads();
    }

#pragma unroll
    for (int mt = 0; mt < 4; mt++)
#pragma unroll
        for (int nt = 0; nt < 4; nt++) {
            int row = m0 + wm0 + mt * 16 + (lane >> 2);
            int col = n0 + wn0 + nt * 8 + (lane & 3) * 2;
            float v0 = c[mt][nt][0], v1 = c[mt][nt][1];
            float v2 = c[mt][nt][2], v3 = c[mt][nt][3];
            if (splitK == 1) {
                float b0 = bias[col], b1 = bias[col + 1];
                v0 += b0; v1 += b1; v2 += b0; v3 += b1;
                if (res) {
                    const float* r0 = res + (size_t)row * N + col;
                    const float* r1 = res + (size_t)(row + 8) * N + col;
                    v0 += r0[0]; v1 += r0[1]; v2 += r1[0]; v3 += r1[1];
                }
            }
            if (Ch) {
                *reinterpret_cast<__half2*>(Ch + (size_t)row * N + col)       = __floats2half2_rn(v0, v1);
                *reinterpret_cast<__half2*>(Ch + (size_t)(row + 8) * N + col) = __floats2half2_rn(v2, v3);
            } else {
                *reinterpret_cast<float2*>(Cf + (size_t)row * N + col)       = make_float2(v0, v1);
                *reinterpret_cast<float2*>(Cf + (size_t)(row + 8) * N + col) = make_float2(v2, v3);
            }
        }
}

// ---------------- split-K reduce: out = sum_z part[z] + bias ----------------
__global__ void reduceK(const float* __restrict__ part, const float* __restrict__ bias,
                        float* __restrict__ out, int MN, int N, int S)
{
    int idx = blockIdx.x * blockDim.x + threadIdx.x;
    if (idx >= MN) return;
    float s = bias[idx % N];
    for (int z = 0; z < S; z++) s += part[(size_t)z * MN + idx];
    out[idx] = s;
}

// ---------------- LayerNorm(256) -> fp16 ----------------
__global__ void ln256_h(const float* __restrict__ x, const float* __restrict__ w,
                        const float* __restrict__ b, __half* __restrict__ y,
                        int rows, float eps)
{
    int row  = blockIdx.x * 8 + (threadIdx.x >> 5);
    int lane = threadIdx.x & 31;
    if (row >= rows) return;
    const float* xr = x + (size_t)row * 256;
    float4 v0 = *reinterpret_cast<const float4*>(xr + lane * 8);
    float4 v1 = *reinterpret_cast<const float4*>(xr + lane * 8 + 4);
    float vals[8] = {v0.x, v0.y, v0.z, v0.w, v1.x, v1.y, v1.z, v1.w};
    float s = 0.f, sq = 0.f;
#pragma unroll
    for (int i = 0; i < 8; i++) { s += vals[i]; sq += vals[i] * vals[i]; }
#pragma unroll
    for (int o = 16; o > 0; o >>= 1) {
        s  += __shfl_xor_sync(0xffffffffu, s, o);
        sq += __shfl_xor_sync(0xffffffffu, sq, o);
    }
    float mean = s * (1.0f / 256.0f);
    float var  = sq * (1.0f / 256.0f) - mean * mean;
    float rs   = rsqrtf(var + eps);
    __align__(16) __half hb[8];
#pragma unroll
    for (int i = 0; i < 8; i++) {
        int c = lane * 8 + i;
        hb[i] = __float2half_rn((vals[i] - mean) * rs * w[c] + b[c]);
    }
    *reinterpret_cast<uint4*>(y + (size_t)row * 256 + lane * 8) = *reinterpret_cast<uint4*>(hb);
}

// ---------------- all weight prep in ONE kernel ----------------
// ranges: qT 65536 | kvT 131072 | pjT 65536 | f1T 262144 | f2T 262144 | wtT 1048576
#define PREP_TOTAL (65536 + 131072 + 65536 + 262144 + 262144 + 1048576)
__global__ void prep_all(const float* __restrict__ qw,  const float* __restrict__ kvw,
                         const float* __restrict__ pjw, const float* __restrict__ f1w,
                         const float* __restrict__ f2w, const float* __restrict__ srw,
                         __half* __restrict__ qT,  __half* __restrict__ kvT,
                         __half* __restrict__ pjT, __half* __restrict__ f1T,
                         __half* __restrict__ f2T, __half* __restrict__ wtT)
{
    int idx = blockIdx.x * 256 + threadIdx.x;
    if (idx < 65536) {
        int n = idx >> 8, k = idx & 255;
        qT[idx] = __float2half_rn(qw[k * 256 + n]);
        return;
    }
    idx -= 65536;
    if (idx < 131072) {
        int n = idx >> 8, k = idx & 255;
        kvT[idx] = __float2half_rn(kvw[k * 512 + n]);
        return;
    }
    idx -= 131072;
    if (idx < 65536) {
        int n = idx >> 8, k = idx & 255;
        pjT[idx] = __float2half_rn(pjw[k * 256 + n]);
        return;
    }
    idx -= 65536;
    if (idx < 262144) {
        int n = idx >> 8, k = idx & 255;
        f1T[idx] = __float2half_rn(f1w[k * 1024 + n]);
        return;
    }
    idx -= 262144;
    if (idx < 262144) {
        int n = idx >> 10, k = idx & 1023;
        f2T[idx] = __float2half_rn(f2w[k * 256 + n]);
        return;
    }
    idx -= 262144;
    {   // wtT[co][(ky*4+kx)*256+ci] = srw[co][ci][ky][kx]
        int co = idx >> 12, k = idx & 4095;
        int ks = k >> 8, ci = k & 255;
        wtT[idx] = __float2half_rn(srw[(size_t)co * KPATCH + ci * 16 + ks]);
    }
}

// ---------------- patch gather (fp16, 2 elems per thread via uint32) ----------------
__global__ void patchify_h(const uint32_t* __restrict__ h, uint32_t* __restrict__ hp)
{
    size_t idx = (size_t)blockIdx.x * blockDim.x + threadIdx.x;
    int ci2 = idx & 127;
    size_t t = idx >> 7;
    int ks = t & 15; t >>= 4;
    int nk = t & 255; int b = (int)(t >> 8);
    int ky = ks >> 2, kx = ks & 3;
    int n = ((nk >> 4) * 4 + ky) * HW + (nk & 15) * 4 + kx;
    hp[idx] = h[((size_t)b * NN + n) * 128 + ci2];
}

// ---------------- tensor-core attention ----------------
// per CTA: (b, h, 128 q rows). 8 warps: S-phase warp tile 64x64 (2M x 4N slabs).
// smem: KT [256][40h] | QT [128][40h] | VT [32][264h] | Opart 128*4*32 f32 (also pmax/psum scratch)
#define AT_KT 0
#define AT_QT 20480
#define AT_VT 30720
#define AT_OP 47616
#define ATTN_SMEM (47616 + 65536)

__global__ __launch_bounds__(256, 1)
void attn_mma(const __half* __restrict__ qg, const __half* __restrict__ kvg,
              const float* __restrict__ pos, const float* __restrict__ alpha,
              __half* __restrict__ og)
{
    extern __shared__ char sm[];
    uint32_t sb = smem_u32(sm);
    const int tid = threadIdx.x, warp = tid >> 5, lane = tid & 31;
    const int n0 = blockIdx.x * 128, hh = blockIdx.y, b = blockIdx.z;

    // ---- loads: K -> KT (stride 80B), V -> VT transposed (stride 528B), Q -> QT ----
    {
        const __half* kb = kvg + ((size_t)b * NK) * 512 + hh * 32;
        for (int t = tid; t < 1024; t += 256) {
            int m = t >> 2, ch = t & 3;
            uint4 v = *reinterpret_cast<const uint4*>(kb + (size_t)m * 512 + ch * 8);
            *reinterpret_cast<uint4*>(sm + AT_KT + m * 80 + ch * 16) = v;
        }
        const __half* vb = kb + 256;
        for (int t = tid; t < 1024; t += 256) {
            int m = t >> 2, ch = t & 3;
            union { uint4 u; __half h[8]; } v;
            v.u = *reinterpret_cast<const uint4*>(vb + (size_t)m * 512 + ch * 8);
#pragma unroll
            for (int j = 0; j < 8; j++)
                *reinterpret_cast<__half*>(sm + AT_VT + (ch * 8 + j) * 528 + m * 2) = v.h[j];
        }
        const __half* qb = qg + ((size_t)b * NN + n0) * 256 + hh * 32;
        for (int t = tid; t < 512; t += 256) {
            int r = t >> 2, ch = t & 3;
            uint4 v = *reinterpret_cast<const uint4*>(qb + (size_t)r * 256 + ch * 8);
            *reinterpret_cast<uint4*>(sm + AT_QT + r * 80 + ch * 16) = v;
        }
    }
    __syncthreads();

    const int wm = (warp >> 2) * 64, wn = (warp & 3) * 64, slab = warp & 3;

    // ---- phase 1: S = Q @ K^T (fragments, raw; scale folded into exp) ----
    float c[4][8][4];
#pragma unroll
    for (int i = 0; i < 4; i++)
#pragma unroll
        for (int j = 0; j < 8; j++)
#pragma unroll
            for (int k = 0; k < 4; k++) c[i][j][k] = 0.f;

#pragma unroll
    for (int h = 0; h < 2; h++) {
        uint32_t a[4][4], bf[8][2];
#pragma unroll
        for (int mt = 0; mt < 4; mt++) {
            int r = wm + mt * 16 + (lane & 15);
            ldm4(a[mt], sb + AT_QT + r * 80 + h * 32 + (lane >> 4) * 16);
        }
#pragma unroll
        for (int ng = 0; ng < 4; ng++) {
            int r = wn + ng * 16 + (lane & 15);
            uint32_t t[4];
            ldm4(t, sb + AT_KT + r * 80 + h * 32 + (lane >> 4) * 16);
            bf[2*ng][0] = t[0]; bf[2*ng][1] = t[2];
            bf[2*ng+1][0] = t[1]; bf[2*ng+1][1] = t[3];
        }
#pragma unroll
        for (int mt = 0; mt < 4; mt++)
#pragma unroll
            for (int nt = 0; nt < 8; nt++)
                mma16816h(c[mt][nt], a[mt], bf[nt]);
    }

    // ---- phase 2: softmax on fragments ----
    const float scale = 0.17677669529663687f;   // 1/sqrt(32)
    float a_ = alpha[0];
    float* pmax = reinterpret_cast<float*>(sm + AT_OP);   // 512 floats
    float* psum = pmax + 512;                             // 512 floats

    // slab max per row
#pragma unroll
    for (int mt = 0; mt < 4; mt++) {
        float m1 = -1e30f, m2 = -1e30f;
#pragma unroll
        for (int nt = 0; nt < 8; nt++) {
            m1 = fmaxf(m1, fmaxf(c[mt][nt][0], c[mt][nt][1]));
            m2 = fmaxf(m2, fmaxf(c[mt][nt][2], c[mt][nt][3]));
        }
        m1 = fmaxf(m1, __shfl_xor_sync(0xffffffffu, m1, 1));
        m1 = fmaxf(m1, __shfl_xor_sync(0xffffffffu, m1, 2));
        m2 = fmaxf(m2, __shfl_xor_sync(0xffffffffu, m2, 1));
        m2 = fmaxf(m2, __shfl_xor_sync(0xffffffffu, m2, 2));
        if ((lane & 3) == 0) {
            int r1 = wm + mt * 16 + (lane >> 2);
            pmax[r1 * 4 + slab] = m1;
            pmax[(r1 + 8) * 4 + slab] = m2;
        }
    }
    __syncthreads();

    // exp + slab sums
#pragma unroll
    for (int mt = 0; mt < 4; mt++) {
        int r1 = wm + mt * 16 + (lane >> 2);
        float g1 = fmaxf(fmaxf(pmax[r1*4], pmax[r1*4+1]), fmaxf(pmax[r1*4+2], pmax[r1*4+3]));
        int r2 = r1 + 8;
        float g2 = fmaxf(fmaxf(pmax[r2*4], pmax[r2*4+1]), fmaxf(pmax[r2*4+2], pmax[r2*4+3]));
        float s1 = 0.f, s2 = 0.f;
#pragma unroll
        for (int nt = 0; nt < 8; nt++) {
            c[mt][nt][0] = expf((c[mt][nt][0] - g1) * scale); s1 += c[mt][nt][0];
            c[mt][nt][1] = expf((c[mt][nt][1] - g1) * scale); s1 += c[mt][nt][1];
            c[mt][nt][2] = expf((c[mt][nt][2] - g2) * scale); s2 += c[mt][nt][2];
            c[mt][nt][3] = expf((c[mt][nt][3] - g2) * scale); s2 += c[mt][nt][3];
        }
        s1 += __shfl_xor_sync(0xffffffffu, s1, 1);
        s1 += __shfl_xor_sync(0xffffffffu, s1, 2);
        s2 += __shfl_xor_sync(0xffffffffu, s2, 1);
        s2 += __shfl_xor_sync(0xffffffffu, s2, 2);
        if ((lane & 3) == 0) {
            psum[r1 * 4 + slab] = s1;
            psum[r2 * 4 + slab] = s2;
        }
    }
    __syncthreads();

    // normalize + blend pos + pack to A-fragments
    uint32_t af[4][4][4];
    const float* posb = pos + ((size_t)(b * HH + hh) * NN + n0) * NK;
#pragma unroll
    for (int mt = 0; mt < 4; mt++) {
        int r1 = wm + mt * 16 + (lane >> 2);
        int r2 = r1 + 8;
        float s1 = psum[r1*4] + psum[r1*4+1] + psum[r1*4+2] + psum[r1*4+3];
        float s2 = psum[r2*4] + psum[r2*4+1] + psum[r2*4+2] + psum[r2*4+3];
        float i1 = (1.0f - a_) / s1, i2 = (1.0f - a_) / s2;
        const float* p1 = posb + (size_t)r1 * NK + wn + (lane & 3) * 2;
        const float* p2 = posb + (size_t)r2 * NK + wn + (lane & 3) * 2;
#pragma unroll
        for (int nt = 0; nt < 8; nt++) {
            float2 q1 = *reinterpret_cast<const float2*>(p1 + nt * 8);
            float2 q2 = *reinterpret_cast<const float2*>(p2 + nt * 8);
            c[mt][nt][0] = c[mt][nt][0] * i1 + a_ * q1.x;
            c[mt][nt][1] = c[mt][nt][1] * i1 + a_ * q1.y;
            c[mt][nt][2] = c[mt][nt][2] * i2 + a_ * q2.x;
            c[mt][nt][3] = c[mt][nt][3] * i2 + a_ * q2.y;
        }
#pragma unroll
        for (int j = 0; j < 4; j++) {
            af[mt][j][0] = packh2(c[mt][2*j][0],   c[mt][2*j][1]);
            af[mt][j][1] = packh2(c[mt][2*j][2],   c[mt][2*j][3]);
            af[mt][j][2] = packh2(c[mt][2*j+1][0], c[mt][2*j+1][1]);
            af[mt][j][3] = packh2(c[mt][2*j+1][2], c[mt][2*j+1][3]);
        }
    }
    __syncthreads();   // psum reads done; Opart region reused below

    // ---- phase 3: O_partial = P_slab @ V_slab ----
    float oc[4][4][4];
#pragma unroll
    for (int i = 0; i < 4; i++)
#pragma unroll
        for (int j = 0; j < 4; j++)
#pragma unroll
            for (int k = 0; k < 4; k++) oc[i][j][k] = 0.f;

#pragma unroll
    for (int ks = 0; ks < 4; ks++) {
        uint32_t bv[4][2];
#pragma unroll
        for (int ng = 0; ng < 2; ng++) {
            int d = ng * 16 + (lane & 15);
            uint32_t t[4];
            ldm4(t, sb + AT_VT + d * 528 + (wn + ks * 16) * 2 + (lane >> 4) * 16);
            bv[2*ng][0] = t[0]; bv[2*ng][1] = t[2];
            bv[2*ng+1][0] = t[1]; bv[2*ng+1][1] = t[3];
        }
#pragma unroll
        for (int mt = 0; mt < 4; mt++)
#pragma unroll
            for (int nt = 0; nt < 4; nt++)
                mma16816h(oc[mt][nt], af[mt][ks], bv[nt]);
    }

    // write partials: Opart[row][slab][d]
    float* Op = reinterpret_cast<float*>(sm + AT_OP);
#pragma unroll
    for (int mt = 0; mt < 4; mt++)
#pragma unroll
        for (int nt = 0; nt < 4; nt++) {
            int r1 = wm + mt * 16 + (lane >> 2);
            int d  = nt * 8 + (lane & 3) * 2;
            *reinterpret_cast<float2*>(Op + ((r1 * 4 + slab) * 32 + d)) =
                make_float2(oc[mt][nt][0], oc[mt][nt][1]);
            *reinterpret_cast<float2*>(Op + (((r1 + 8) * 4 + slab) * 32 + d)) =
                make_float2(oc[mt][nt][2], oc[mt][nt][3]);
        }
    __syncthreads();

    // reduce 4 slabs + store fp16
    for (int t = tid; t < 4096; t += 256) {
        int r = t >> 5, d = t & 31;
        float s = Op[(r*4+0)*32+d] + Op[(r*4+1)*32+d] + Op[(r*4+2)*32+d] + Op[(r*4+3)*32+d];
        og[((size_t)b * NN + n0 + r) * 256 + hh * 32 + d] = __float2half_rn(s);
    }
}

// ---------------- depthwise 3x3 + exact GELU (fp16 in/out) ----------------
__global__ void dw_gelu(const __half* __restrict__ m, const float* __restrict__ w,
                        const float* __restrict__ bias, __half* __restrict__ mi)
{
    int y = blockIdx.x;
    int b = blockIdx.y;
    for (int idx = threadIdx.x; idx < HW * (HID / 4); idx += blockDim.x) {
        int x  = idx >> 8;
        int c4 = idx & 255;
        int c  = c4 * 4;
        float4 bi = *reinterpret_cast<const float4*>(bias + c);
        float acc[4] = {bi.x, bi.y, bi.z, bi.w};
        float wr[9][4];
#pragma unroll
        for (int tap = 0; tap < 9; tap++)
#pragma unroll
            for (int j = 0; j < 4; j++)
                wr[tap][j] = w[(c + j) * 9 + tap];
#pragma unroll
        for (int dy = -1; dy <= 1; dy++) {
            int yy = y + dy;
            if (yy < 0 || yy >= HW) continue;
#pragma unroll
            for (int dx = -1; dx <= 1; dx++) {
                int xx = x + dx;
                if (xx < 0 || xx >= HW) continue;
                int tap = (dy + 1) * 3 + (dx + 1);
                const __half2* p = reinterpret_cast<const __half2*>(
                    m + ((size_t)b * NN + yy * HW + xx) * HID + c);
                float2 f01 = __half22float2(p[0]);
                float2 f23 = __half22float2(p[1]);
                acc[0] += f01.x * wr[tap][0];
                acc[1] += f01.y * wr[tap][1];
                acc[2] += f23.x * wr[tap][2];
                acc[3] += f23.y * wr[tap][3];
            }
        }
        float gv[4];
#pragma unroll
        for (int j = 0; j < 4; j++)
            gv[j] = 0.5f * acc[j] * (1.0f + erff(acc[j] * 0.70710678118654752f));
        __half2* op = reinterpret_cast<__half2*>(mi + ((size_t)b * NN + y * HW + x) * HID + c);
        op[0] = __floats2half2_rn(gv[0], gv[1]);
        op[1] = __floats2half2_rn(gv[2], gv[3]);
    }
}

// ---------------- launch ----------------
extern "C" void kernel_launch(void* const* d_in, const int* in_sizes, int n_in,
                              void* d_out, int out_size)
{
    const float* x      = (const float*)d_in[0];
    const float* pos2d  = (const float*)d_in[1];
    const float* ln1_w  = (const float*)d_in[2];
    const float* ln1_b  = (const float*)d_in[3];
    const float* q_w    = (const float*)d_in[4];
    const float* q_b    = (const float*)d_in[5];
    const float* kv_w   = (const float*)d_in[6];
    const float* kv_b   = (const float*)d_in[7];
    const float* sr_w   = (const float*)d_in[8];
    const float* sr_b   = (const float*)d_in[9];
    const float* srn_w  = (const float*)d_in[10];
    const float* srn_b  = (const float*)d_in[11];
    const float* alpha  = (const float*)d_in[12];
    const float* proj_w = (const float*)d_in[13];
    const float* proj_b = (const float*)d_in[14];
    const float* ln2_w  = (const float*)d_in[15];
    const float* ln2_b  = (const float*)d_in[16];
    const float* fc1_w  = (const float*)d_in[17];
    const float* fc1_b  = (const float*)d_in[18];
    const float* dw_w   = (const float*)d_in[19];
    const float* dw_b   = (const float*)d_in[20];
    const float* fc2_w  = (const float*)d_in[21];
    const float* fc2_b  = (const float*)d_in[22];
    float* out = (float*)d_out;

    __half *h_h, *hp_h, *wtT, *hs_h, *q_h, *kv_h, *o_h, *h2_h, *m_h, *mi_h;
    __half *qT, *kvT, *pjT, *f1T, *f2T;
    float *hs, *x1, *part;
    cudaGetSymbolAddress((void**)&h_h,  g_h_h);
    cudaGetSymbolAddress((void**)&hp_h, g_hp_h);
    cudaGetSymbolAddress((void**)&wtT,  g_wtT);
    cudaGetSymbolAddress((void**)&hs,   g_hs);
    cudaGetSymbolAddress((void**)&hs_h, g_hs_h);
    cudaGetSymbolAddress((void**)&q_h,  g_q_h);
    cudaGetSymbolAddress((void**)&kv_h, g_kv_h);
    cudaGetSymbolAddress((void**)&o_h,  g_o_h);
    cudaGetSymbolAddress((void**)&x1,   g_x1);
    cudaGetSymbolAddress((void**)&h2_h, g_h2_h);
    cudaGetSymbolAddress((void**)&m_h,  g_m_h);
    cudaGetSymbolAddress((void**)&mi_h, g_mi_h);
    cudaGetSymbolAddress((void**)&part, g_part);
    cudaGetSymbolAddress((void**)&qT,   g_qT);
    cudaGetSymbolAddress((void**)&kvT,  g_kvT);
    cudaGetSymbolAddress((void**)&pjT,  g_pjT);
    cudaGetSymbolAddress((void**)&f1T,  g_f1T);
    cudaGetSymbolAddress((void**)&f2T,  g_f2T);

    static bool cfg = false;
    if (!cfg) {
        cudaFuncSetAttribute(gemm_h, cudaFuncAttributeMaxDynamicSharedMemorySize, GEMM_SMEM);
        cudaFuncSetAttribute(attn_mma, cudaFuncAttributeMaxDynamicSharedMemorySize, ATTN_SMEM);
        cfg = true;
    }

    const int ROWS = BB * NN;        // 32768
    const int ROWS_SR = BB * NK;     // 2048

    // 1. h = LN1(x) -> fp16
    ln256_h<<<ROWS / 8, 256>>>(x, ln1_w, ln1_b, h_h, ROWS, 1e-6f);
    // 2. patch gather
    patchify_h<<<(int)(((size_t)BB * NK * 16 * 128) / 256), 256>>>(
        (const uint32_t*)h_h, (uint32_t*)hp_h);
    // 3. all weight prep (one kernel)
    prep_all<<<PREP_TOTAL / 256, 256>>>(q_w, kv_w, proj_w, fc1_w, fc2_w, sr_w,
                                        qT, kvT, pjT, f1T, f2T, wtT);
    // 4. SR GEMM (split-K=8)
    gemm_h<<<dim3(CC / 128, ROWS_SR / 128, 8), 256, GEMM_SMEM>>>(hp_h, wtT, nullptr, nullptr,
                                                                 part, nullptr, ROWS_SR, CC, KPATCH, 8);
    // 5. reduce + bias
    reduceK<<<(ROWS_SR * CC + 255) / 256, 256>>>(part, sr_b, hs, ROWS_SR * CC, CC, 8);
    // 6. q = h @ q_w + q_b  (fp16 out)
    gemm_h<<<dim3(CC / 128, ROWS / 128), 256, GEMM_SMEM>>>(h_h, qT, q_b, nullptr,
                                                           nullptr, q_h, ROWS, CC, CC, 1);
    // 7. srn LN -> fp16
    ln256_h<<<ROWS_SR / 8, 256>>>(hs, srn_w, srn_b, hs_h, ROWS_SR, 1e-5f);
    // 8. kv = hs @ kv_w + kv_b (fp16 out)
    gemm_h<<<dim3((2 * CC) / 128, ROWS_SR / 128), 256, GEMM_SMEM>>>(hs_h, kvT, kv_b, nullptr,
                                                                    nullptr, kv_h, ROWS_SR, 2 * CC, CC, 1);
    // 9. tensor-core attention -> o fp16
    attn_mma<<<dim3(NN / 128, HH, BB), 256, ATTN_SMEM>>>(q_h, kv_h, pos2d, alpha, o_h);
    // 10. proj: x1 = x + o @ proj_w + proj_b
    gemm_h<<<dim3(CC / 128, ROWS / 128), 256, GEMM_SMEM>>>(o_h, pjT, proj_b, x,
                                                           x1, nullptr, ROWS, CC, CC, 1);
    // 11. h2 = LN2(x1) -> fp16
    ln256_h<<<ROWS / 8, 256>>>(x1, ln2_w, ln2_b, h2_h, ROWS, 1e-6f);
    // 12. fc1: m = h2 @ fc1_w + fc1_b (fp16 out)
    gemm_h<<<dim3(HID / 128, ROWS / 128), 256, GEMM_SMEM>>>(h2_h, f1T, fc1_b, nullptr,
                                                            nullptr, m_h, ROWS, HID, CC, 1);
    // 13. depthwise conv + gelu
    dw_gelu<<<dim3(HW, BB), 512>>>(m_h, dw_w, dw_b, mi_h);
    // 14. fc2: out = x1 + mi @ fc2_w + fc2_b
    gemm_h<<<dim3(CC / 128, ROWS / 128), 256, GEMM_SMEM>>>(mi_h, f2T, fc2_b, x1,
                                                           out, nullptr, ROWS, CC, HID, 1);
}

// round 9
// speedup vs baseline: 4.0529x; 1.0130x over previous
#include <cuda_runtime.h>
#include <cuda_fp16.h>
#include <math.h>
#include <stdint.h>

// Problem dims (fixed)
#define BB   8
#define NN   4096
#define CC   256
#define HH   8
#define DH   32
#define HW   64
#define NK   256
#define HID  1024
#define KPATCH 4096   // C * SR * SR

// ---------------- scratch (device globals; no allocation) ----------------
__device__ __half g_h_h [(size_t)BB*NN*CC];
__device__ __half g_hp_h[(size_t)BB*NK*KPATCH];
__device__ __half g_wtT [(size_t)CC*KPATCH];
__device__ float  g_hs  [(size_t)BB*NK*CC];
__device__ __half g_hs_h[(size_t)BB*NK*CC];
__device__ __half g_q_h [(size_t)BB*NN*CC];
__device__ __half g_kv_h[(size_t)BB*NK*2*CC];
__device__ __half g_o_h [(size_t)BB*NN*CC];
__device__ float  g_x1  [(size_t)BB*NN*CC];
__device__ __half g_h2_h[(size_t)BB*NN*CC];
__device__ __half g_m_h [(size_t)BB*NN*HID];
__device__ __half g_mi_h[(size_t)BB*NN*HID];
__device__ float  g_part[(size_t)8*BB*NK*CC];   // split-K partials
// transposed weights [N x K] fp16
__device__ __half g_qT [CC*CC];
__device__ __half g_kvT[2*CC*CC];
__device__ __half g_pjT[CC*CC];
__device__ __half g_f1T[HID*CC];
__device__ __half g_f2T[CC*HID];

// ---------------- PTX helpers (legal on base compute_103 target) ----------------
__device__ __forceinline__ uint32_t smem_u32(const void* p) {
    uint32_t a;
    asm("{ .reg .u64 t; cvta.to.shared.u64 t, %1; cvt.u32.u64 %0, t; }" : "=r"(a) : "l"(p));
    return a;
}
__device__ __forceinline__ void cpasync16(uint32_t dst, const void* src) {
    asm volatile("cp.async.cg.shared.global [%0], [%1], 16;" :: "r"(dst), "l"(src) : "memory");
}
__device__ __forceinline__ void cpcommit() {
    asm volatile("cp.async.commit_group;" ::: "memory");
}
template<int Ngrp> __device__ __forceinline__ void cpwait() {
    asm volatile("cp.async.wait_group %0;" :: "n"(Ngrp) : "memory");
}
__device__ __forceinline__ void ldm4(uint32_t* r, uint32_t addr) {
    asm volatile("ldmatrix.sync.aligned.m8n8.x4.shared.b16 {%0,%1,%2,%3}, [%4];"
                 : "=r"(r[0]), "=r"(r[1]), "=r"(r[2]), "=r"(r[3]) : "r"(addr));
}
__device__ __forceinline__ void mma16816h(float* c, const uint32_t* a, const uint32_t* b) {
    asm volatile("mma.sync.aligned.m16n8k16.row.col.f32.f16.f16.f32 "
                 "{%0,%1,%2,%3}, {%4,%5,%6,%7}, {%8,%9}, {%0,%1,%2,%3};"
                 : "+f"(c[0]), "+f"(c[1]), "+f"(c[2]), "+f"(c[3])
                 : "r"(a[0]), "r"(a[1]), "r"(a[2]), "r"(a[3]), "r"(b[0]), "r"(b[1]));
}
__device__ __forceinline__ uint32_t packh2(float x, float y) {
    __half2 h = __floats2half2_rn(x, y);
    return *reinterpret_cast<uint32_t*>(&h);
}

// ---------------- fp16 tensor GEMM via mma.sync, 3-stage pipeline ----------------
// C[M,N] = A @ B^T (+bias)(+res).  A:[M,K] fp16, Bt:[N,K] fp16, K-major.
// CTA tile 128x128, BK=32, 8 warps (2 M x 4 N), warp tile 64x32.
// 3 smem stages, ONE __syncthreads per K-iteration.
#define GEMM_SMEM (3 * 20480)

__global__ __launch_bounds__(256, 2)
void gemm_h(const __half* __restrict__ A, const __half* __restrict__ Bt,
            const float* __restrict__ bias, const float* __restrict__ res,
            float* __restrict__ Cf, __half* __restrict__ Ch,
            int M, int N, int K, int splitK)
{
    extern __shared__ char sm[];
    uint32_t sb = smem_u32(sm);
    const int tid  = threadIdx.x;
    const int warp = tid >> 5, lane = tid & 31;
    const int n0 = blockIdx.x * 128, m0 = blockIdx.y * 128;
    const int Keff  = K / splitK;
    const int kbase = blockIdx.z * Keff;
    if (splitK > 1) Cf += (size_t)blockIdx.z * M * N;
    const int nk = Keff / 32;
    const int wm0 = (warp >> 2) * 64, wn0 = (warp & 3) * 32;

    float c[4][4][4];
#pragma unroll
    for (int i = 0; i < 4; i++)
#pragma unroll
        for (int j = 0; j < 4; j++)
#pragma unroll
            for (int k = 0; k < 4; k++) c[i][j][k] = 0.f;

    const int lrow = tid >> 2;
    const int lq   = tid & 3;

    auto load_stage = [&](int i, int s) {
        const int k0 = kbase + i * 32;
        const uint32_t st = sb + s * 20480;
#pragma unroll
        for (int e = 0; e < 2; e++) {
            int r = lrow + e * 64;
            cpasync16(st +         r * 80 + lq * 16, A  + (size_t)(m0 + r) * K + k0 + lq * 8);
            cpasync16(st + 10240 + r * 80 + lq * 16, Bt + (size_t)(n0 + r) * K + k0 + lq * 8);
        }
        cpcommit();
    };

    auto compute_stage = [&](int s) {
        const uint32_t st = sb + s * 20480;
#pragma unroll
        for (int h = 0; h < 2; h++) {
            uint32_t a[4][4], bfr[4][2];
#pragma unroll
            for (int mt = 0; mt < 4; mt++) {
                int r = wm0 + mt * 16 + (lane & 15);
                ldm4(a[mt], st + r * 80 + h * 32 + (lane >> 4) * 16);
            }
#pragma unroll
            for (int ng = 0; ng < 2; ng++) {
                int r = wn0 + ng * 16 + (lane & 15);
                uint32_t t[4];
                ldm4(t, st + 10240 + r * 80 + h * 32 + (lane >> 4) * 16);
                bfr[2*ng][0] = t[0]; bfr[2*ng][1] = t[2];
                bfr[2*ng+1][0] = t[1]; bfr[2*ng+1][1] = t[3];
            }
#pragma unroll
            for (int mt = 0; mt < 4; mt++)
#pragma unroll
                for (int nt = 0; nt < 4; nt++)
                    mma16816h(c[mt][nt], a[mt], bfr[nt]);
        }
    };

    // prologue: stages 0,1 in flight (nk >= 8 for all shapes here)
    load_stage(0, 0);
    load_stage(1, 1);
    int stage = 0;
    for (int i = 0; i < nk; i++) {
        cpwait<1>();          // stage i resident (stage i+1 may be pending)
        __syncthreads();      // all warps done computing stage i-1 -> safe to refill it
        if (i + 2 < nk) {
            int s2 = stage + 2; if (s2 >= 3) s2 -= 3;
            load_stage(i + 2, s2);
        }
        compute_stage(stage);
        if (++stage == 3) stage = 0;
    }

#pragma unroll
    for (int mt = 0; mt < 4; mt++)
#pragma unroll
        for (int nt = 0; nt < 4; nt++) {
            int row = m0 + wm0 + mt * 16 + (lane >> 2);
            int col = n0 + wn0 + nt * 8 + (lane & 3) * 2;
            float v0 = c[mt][nt][0], v1 = c[mt][nt][1];
            float v2 = c[mt][nt][2], v3 = c[mt][nt][3];
            if (splitK == 1) {
                float b0 = bias[col], b1 = bias[col + 1];
                v0 += b0; v1 += b1; v2 += b0; v3 += b1;
                if (res) {
                    const float* r0 = res + (size_t)row * N + col;
                    const float* r1 = res + (size_t)(row + 8) * N + col;
                    v0 += r0[0]; v1 += r0[1]; v2 += r1[0]; v3 += r1[1];
                }
            }
            if (Ch) {
                *reinterpret_cast<__half2*>(Ch + (size_t)row * N + col)       = __floats2half2_rn(v0, v1);
                *reinterpret_cast<__half2*>(Ch + (size_t)(row + 8) * N + col) = __floats2half2_rn(v2, v3);
            } else {
                *reinterpret_cast<float2*>(Cf + (size_t)row * N + col)       = make_float2(v0, v1);
                *reinterpret_cast<float2*>(Cf + (size_t)(row + 8) * N + col) = make_float2(v2, v3);
            }
        }
}

// ---------------- split-K reduce (float4): out = sum_z part[z] + bias ----------------
__global__ void reduceK(const float* __restrict__ part, const float* __restrict__ bias,
                        float* __restrict__ out, int MN, int N, int S)
{
    int idx = (blockIdx.x * blockDim.x + threadIdx.x) * 4;
    if (idx >= MN) return;
    float4 s = *reinterpret_cast<const float4*>(bias + (idx & (N - 1)));
    for (int z = 0; z < S; z++) {
        float4 p = *reinterpret_cast<const float4*>(part + (size_t)z * MN + idx);
        s.x += p.x; s.y += p.y; s.z += p.z; s.w += p.w;
    }
    *reinterpret_cast<float4*>(out + idx) = s;
}

// ---------------- LayerNorm(256) -> fp16 ----------------
__global__ void ln256_h(const float* __restrict__ x, const float* __restrict__ w,
                        const float* __restrict__ b, __half* __restrict__ y,
                        int rows, float eps)
{
    int row  = blockIdx.x * 8 + (threadIdx.x >> 5);
    int lane = threadIdx.x & 31;
    if (row >= rows) return;
    const float* xr = x + (size_t)row * 256;
    float4 v0 = *reinterpret_cast<const float4*>(xr + lane * 8);
    float4 v1 = *reinterpret_cast<const float4*>(xr + lane * 8 + 4);
    float vals[8] = {v0.x, v0.y, v0.z, v0.w, v1.x, v1.y, v1.z, v1.w};
    float s = 0.f, sq = 0.f;
#pragma unroll
    for (int i = 0; i < 8; i++) { s += vals[i]; sq += vals[i] * vals[i]; }
#pragma unroll
    for (int o = 16; o > 0; o >>= 1) {
        s  += __shfl_xor_sync(0xffffffffu, s, o);
        sq += __shfl_xor_sync(0xffffffffu, sq, o);
    }
    float mean = s * (1.0f / 256.0f);
    float var  = sq * (1.0f / 256.0f) - mean * mean;
    float rs   = rsqrtf(var + eps);
    __align__(16) __half hb[8];
#pragma unroll
    for (int i = 0; i < 8; i++) {
        int c = lane * 8 + i;
        hb[i] = __float2half_rn((vals[i] - mean) * rs * w[c] + b[c]);
    }
    *reinterpret_cast<uint4*>(y + (size_t)row * 256 + lane * 8) = *reinterpret_cast<uint4*>(hb);
}

// ---------------- all weight prep in ONE kernel ----------------
// ranges: qT 65536 | kvT 131072 | pjT 65536 | f1T 262144 | f2T 262144 | wtT 1048576
#define PREP_TOTAL (65536 + 131072 + 65536 + 262144 + 262144 + 1048576)
__global__ void prep_all(const float* __restrict__ qw,  const float* __restrict__ kvw,
                         const float* __restrict__ pjw, const float* __restrict__ f1w,
                         const float* __restrict__ f2w, const float* __restrict__ srw,
                         __half* __restrict__ qT,  __half* __restrict__ kvT,
                         __half* __restrict__ pjT, __half* __restrict__ f1T,
                         __half* __restrict__ f2T, __half* __restrict__ wtT)
{
    int idx = blockIdx.x * 256 + threadIdx.x;
    if (idx < 65536) {
        int n = idx >> 8, k = idx & 255;
        qT[idx] = __float2half_rn(qw[k * 256 + n]);
        return;
    }
    idx -= 65536;
    if (idx < 131072) {
        int n = idx >> 8, k = idx & 255;
        kvT[idx] = __float2half_rn(kvw[k * 512 + n]);
        return;
    }
    idx -= 131072;
    if (idx < 65536) {
        int n = idx >> 8, k = idx & 255;
        pjT[idx] = __float2half_rn(pjw[k * 256 + n]);
        return;
    }
    idx -= 65536;
    if (idx < 262144) {
        int n = idx >> 8, k = idx & 255;
        f1T[idx] = __float2half_rn(f1w[k * 1024 + n]);
        return;
    }
    idx -= 262144;
    if (idx < 262144) {
        int n = idx >> 10, k = idx & 1023;
        f2T[idx] = __float2half_rn(f2w[k * 256 + n]);
        return;
    }
    idx -= 262144;
    {   // wtT[co][(ky*4+kx)*256+ci] = srw[co][ci][ky][kx]
        int co = idx >> 12, k = idx & 4095;
        int ks = k >> 8, ci = k & 255;
        wtT[idx] = __float2half_rn(srw[(size_t)co * KPATCH + ci * 16 + ks]);
    }
}

// ---------------- patch gather (fp16, 2 elems per thread via uint32) ----------------
__global__ void patchify_h(const uint32_t* __restrict__ h, uint32_t* __restrict__ hp)
{
    size_t idx = (size_t)blockIdx.x * blockDim.x + threadIdx.x;
    int ci2 = idx & 127;
    size_t t = idx >> 7;
    int ks = t & 15; t >>= 4;
    int nk = t & 255; int b = (int)(t >> 8);
    int ky = ks >> 2, kx = ks & 3;
    int n = ((nk >> 4) * 4 + ky) * HW + (nk & 15) * 4 + kx;
    hp[idx] = h[((size_t)b * NN + n) * 128 + ci2];
}

// ---------------- tensor-core attention ----------------
// per CTA: (b, h, 128 q rows). 8 warps: S-phase warp tile 64x64 (2M x 4N slabs).
// smem: KT [256][40h] | QT [128][40h] | VT [32][264h] | Opart 128*4*32 f32 (also pmax/psum scratch)
#define AT_KT 0
#define AT_QT 20480
#define AT_VT 30720
#define AT_OP 47616
#define ATTN_SMEM (47616 + 65536)

__global__ __launch_bounds__(256, 1)
void attn_mma(const __half* __restrict__ qg, const __half* __restrict__ kvg,
              const float* __restrict__ pos, const float* __restrict__ alpha,
              __half* __restrict__ og)
{
    extern __shared__ char sm[];
    uint32_t sb = smem_u32(sm);
    const int tid = threadIdx.x, warp = tid >> 5, lane = tid & 31;
    const int n0 = blockIdx.x * 128, hh = blockIdx.y, b = blockIdx.z;

    // ---- loads: K -> KT (stride 80B), V -> VT transposed (stride 528B), Q -> QT ----
    {
        const __half* kb = kvg + ((size_t)b * NK) * 512 + hh * 32;
        for (int t = tid; t < 1024; t += 256) {
            int m = t >> 2, ch = t & 3;
            uint4 v = *reinterpret_cast<const uint4*>(kb + (size_t)m * 512 + ch * 8);
            *reinterpret_cast<uint4*>(sm + AT_KT + m * 80 + ch * 16) = v;
        }
        const __half* vb = kb + 256;
        for (int t = tid; t < 1024; t += 256) {
            int m = t >> 2, ch = t & 3;
            union { uint4 u; __half h[8]; } v;
            v.u = *reinterpret_cast<const uint4*>(vb + (size_t)m * 512 + ch * 8);
#pragma unroll
            for (int j = 0; j < 8; j++)
                *reinterpret_cast<__half*>(sm + AT_VT + (ch * 8 + j) * 528 + m * 2) = v.h[j];
        }
        const __half* qb = qg + ((size_t)b * NN + n0) * 256 + hh * 32;
        for (int t = tid; t < 512; t += 256) {
            int r = t >> 2, ch = t & 3;
            uint4 v = *reinterpret_cast<const uint4*>(qb + (size_t)r * 256 + ch * 8);
            *reinterpret_cast<uint4*>(sm + AT_QT + r * 80 + ch * 16) = v;
        }
    }
    __syncthreads();

    const int wm = (warp >> 2) * 64, wn = (warp & 3) * 64, slab = warp & 3;

    // ---- phase 1: S = Q @ K^T (fragments, raw; scale folded into exp) ----
    float c[4][8][4];
#pragma unroll
    for (int i = 0; i < 4; i++)
#pragma unroll
        for (int j = 0; j < 8; j++)
#pragma unroll
            for (int k = 0; k < 4; k++) c[i][j][k] = 0.f;

#pragma unroll
    for (int h = 0; h < 2; h++) {
        uint32_t a[4][4], bf[8][2];
#pragma unroll
        for (int mt = 0; mt < 4; mt++) {
            int r = wm + mt * 16 + (lane & 15);
            ldm4(a[mt], sb + AT_QT + r * 80 + h * 32 + (lane >> 4) * 16);
        }
#pragma unroll
        for (int ng = 0; ng < 4; ng++) {
            int r = wn + ng * 16 + (lane & 15);
            uint32_t t[4];
            ldm4(t, sb + AT_KT + r * 80 + h * 32 + (lane >> 4) * 16);
            bf[2*ng][0] = t[0]; bf[2*ng][1] = t[2];
            bf[2*ng+1][0] = t[1]; bf[2*ng+1][1] = t[3];
        }
#pragma unroll
        for (int mt = 0; mt < 4; mt++)
#pragma unroll
            for (int nt = 0; nt < 8; nt++)
                mma16816h(c[mt][nt], a[mt], bf[nt]);
    }

    // ---- phase 2: softmax on fragments ----
    const float scale = 0.17677669529663687f;   // 1/sqrt(32)
    float a_ = alpha[0];
    float* pmax = reinterpret_cast<float*>(sm + AT_OP);   // 512 floats
    float* psum = pmax + 512;                             // 512 floats

    // slab max per row
#pragma unroll
    for (int mt = 0; mt < 4; mt++) {
        float m1 = -1e30f, m2 = -1e30f;
#pragma unroll
        for (int nt = 0; nt < 8; nt++) {
            m1 = fmaxf(m1, fmaxf(c[mt][nt][0], c[mt][nt][1]));
            m2 = fmaxf(m2, fmaxf(c[mt][nt][2], c[mt][nt][3]));
        }
        m1 = fmaxf(m1, __shfl_xor_sync(0xffffffffu, m1, 1));
        m1 = fmaxf(m1, __shfl_xor_sync(0xffffffffu, m1, 2));
        m2 = fmaxf(m2, __shfl_xor_sync(0xffffffffu, m2, 1));
        m2 = fmaxf(m2, __shfl_xor_sync(0xffffffffu, m2, 2));
        if ((lane & 3) == 0) {
            int r1 = wm + mt * 16 + (lane >> 2);
            pmax[r1 * 4 + slab] = m1;
            pmax[(r1 + 8) * 4 + slab] = m2;
        }
    }
    __syncthreads();

    // exp + slab sums
#pragma unroll
    for (int mt = 0; mt < 4; mt++) {
        int r1 = wm + mt * 16 + (lane >> 2);
        float g1 = fmaxf(fmaxf(pmax[r1*4], pmax[r1*4+1]), fmaxf(pmax[r1*4+2], pmax[r1*4+3]));
        int r2 = r1 + 8;
        float g2 = fmaxf(fmaxf(pmax[r2*4], pmax[r2*4+1]), fmaxf(pmax[r2*4+2], pmax[r2*4+3]));
        float s1 = 0.f, s2 = 0.f;
#pragma unroll
        for (int nt = 0; nt < 8; nt++) {
            c[mt][nt][0] = expf((c[mt][nt][0] - g1) * scale); s1 += c[mt][nt][0];
            c[mt][nt][1] = expf((c[mt][nt][1] - g1) * scale); s1 += c[mt][nt][1];
            c[mt][nt][2] = expf((c[mt][nt][2] - g2) * scale); s2 += c[mt][nt][2];
            c[mt][nt][3] = expf((c[mt][nt][3] - g2) * scale); s2 += c[mt][nt][3];
        }
        s1 += __shfl_xor_sync(0xffffffffu, s1, 1);
        s1 += __shfl_xor_sync(0xffffffffu, s1, 2);
        s2 += __shfl_xor_sync(0xffffffffu, s2, 1);
        s2 += __shfl_xor_sync(0xffffffffu, s2, 2);
        if ((lane & 3) == 0) {
            psum[r1 * 4 + slab] = s1;
            psum[r2 * 4 + slab] = s2;
        }
    }
    __syncthreads();

    // normalize + blend pos + pack to A-fragments
    uint32_t af[4][4][4];
    const float* posb = pos + ((size_t)(b * HH + hh) * NN + n0) * NK;
#pragma unroll
    for (int mt = 0; mt < 4; mt++) {
        int r1 = wm + mt * 16 + (lane >> 2);
        int r2 = r1 + 8;
        float s1 = psum[r1*4] + psum[r1*4+1] + psum[r1*4+2] + psum[r1*4+3];
        float s2 = psum[r2*4] + psum[r2*4+1] + psum[r2*4+2] + psum[r2*4+3];
        float i1 = (1.0f - a_) / s1, i2 = (1.0f - a_) / s2;
        const float* p1 = posb + (size_t)r1 * NK + wn + (lane & 3) * 2;
        const float* p2 = posb + (size_t)r2 * NK + wn + (lane & 3) * 2;
#pragma unroll
        for (int nt = 0; nt < 8; nt++) {
            float2 q1 = *reinterpret_cast<const float2*>(p1 + nt * 8);
            float2 q2 = *reinterpret_cast<const float2*>(p2 + nt * 8);
            c[mt][nt][0] = c[mt][nt][0] * i1 + a_ * q1.x;
            c[mt][nt][1] = c[mt][nt][1] * i1 + a_ * q1.y;
            c[mt][nt][2] = c[mt][nt][2] * i2 + a_ * q2.x;
            c[mt][nt][3] = c[mt][nt][3] * i2 + a_ * q2.y;
        }
#pragma unroll
        for (int j = 0; j < 4; j++) {
            af[mt][j][0] = packh2(c[mt][2*j][0],   c[mt][2*j][1]);
            af[mt][j][1] = packh2(c[mt][2*j][2],   c[mt][2*j][3]);
            af[mt][j][2] = packh2(c[mt][2*j+1][0], c[mt][2*j+1][1]);
            af[mt][j][3] = packh2(c[mt][2*j+1][2], c[mt][2*j+1][3]);
        }
    }
    __syncthreads();   // psum reads done; Opart region reused below

    // ---- phase 3: O_partial = P_slab @ V_slab ----
    float oc[4][4][4];
#pragma unroll
    for (int i = 0; i < 4; i++)
#pragma unroll
        for (int j = 0; j < 4; j++)
#pragma unroll
            for (int k = 0; k < 4; k++) oc[i][j][k] = 0.f;

#pragma unroll
    for (int ks = 0; ks < 4; ks++) {
        uint32_t bv[4][2];
#pragma unroll
        for (int ng = 0; ng < 2; ng++) {
            int d = ng * 16 + (lane & 15);
            uint32_t t[4];
            ldm4(t, sb + AT_VT + d * 528 + (wn + ks * 16) * 2 + (lane >> 4) * 16);
            bv[2*ng][0] = t[0]; bv[2*ng][1] = t[2];
            bv[2*ng+1][0] = t[1]; bv[2*ng+1][1] = t[3];
        }
#pragma unroll
        for (int mt = 0; mt < 4; mt++)
#pragma unroll
            for (int nt = 0; nt < 4; nt++)
                mma16816h(oc[mt][nt], af[mt][ks], bv[nt]);
    }

    // write partials: Opart[row][slab][d]
    float* Op = reinterpret_cast<float*>(sm + AT_OP);
#pragma unroll
    for (int mt = 0; mt < 4; mt++)
#pragma unroll
        for (int nt = 0; nt < 4; nt++) {
            int r1 = wm + mt * 16 + (lane >> 2);
            int d  = nt * 8 + (lane & 3) * 2;
            *reinterpret_cast<float2*>(Op + ((r1 * 4 + slab) * 32 + d)) =
                make_float2(oc[mt][nt][0], oc[mt][nt][1]);
            *reinterpret_cast<float2*>(Op + (((r1 + 8) * 4 + slab) * 32 + d)) =
                make_float2(oc[mt][nt][2], oc[mt][nt][3]);
        }
    __syncthreads();

    // reduce 4 slabs + store fp16
    for (int t = tid; t < 4096; t += 256) {
        int r = t >> 5, d = t & 31;
        float s = Op[(r*4+0)*32+d] + Op[(r*4+1)*32+d] + Op[(r*4+2)*32+d] + Op[(r*4+3)*32+d];
        og[((size_t)b * NN + n0 + r) * 256 + hh * 32 + d] = __float2half_rn(s);
    }
}

// ---------------- depthwise 3x3 + exact GELU (fp16 in/out) ----------------
__global__ void dw_gelu(const __half* __restrict__ m, const float* __restrict__ w,
                        const float* __restrict__ bias, __half* __restrict__ mi)
{
    int y = blockIdx.x;
    int b = blockIdx.y;
    for (int idx = threadIdx.x; idx < HW * (HID / 4); idx += blockDim.x) {
        int x  = idx >> 8;
        int c4 = idx & 255;
        int c  = c4 * 4;
        float4 bi = *reinterpret_cast<const float4*>(bias + c);
        float acc[4] = {bi.x, bi.y, bi.z, bi.w};
        float wr[9][4];
#pragma unroll
        for (int tap = 0; tap < 9; tap++)
#pragma unroll
            for (int j = 0; j < 4; j++)
                wr[tap][j] = w[(c + j) * 9 + tap];
#pragma unroll
        for (int dy = -1; dy <= 1; dy++) {
            int yy = y + dy;
            if (yy < 0 || yy >= HW) continue;
#pragma unroll
            for (int dx = -1; dx <= 1; dx++) {
                int xx = x + dx;
                if (xx < 0 || xx >= HW) continue;
                int tap = (dy + 1) * 3 + (dx + 1);
                const __half2* p = reinterpret_cast<const __half2*>(
                    m + ((size_t)b * NN + yy * HW + xx) * HID + c);
                float2 f01 = __half22float2(p[0]);
                float2 f23 = __half22float2(p[1]);
                acc[0] += f01.x * wr[tap][0];
                acc[1] += f01.y * wr[tap][1];
                acc[2] += f23.x * wr[tap][2];
                acc[3] += f23.y * wr[tap][3];
            }
        }
        float gv[4];
#pragma unroll
        for (int j = 0; j < 4; j++)
            gv[j] = 0.5f * acc[j] * (1.0f + erff(acc[j] * 0.70710678118654752f));
        __half2* op = reinterpret_cast<__half2*>(mi + ((size_t)b * NN + y * HW + x) * HID + c);
        op[0] = __floats2half2_rn(gv[0], gv[1]);
        op[1] = __floats2half2_rn(gv[2], gv[3]);
    }
}

// ---------------- launch ----------------
extern "C" void kernel_launch(void* const* d_in, const int* in_sizes, int n_in,
                              void* d_out, int out_size)
{
    const float* x      = (const float*)d_in[0];
    const float* pos2d  = (const float*)d_in[1];
    const float* ln1_w  = (const float*)d_in[2];
    const float* ln1_b  = (const float*)d_in[3];
    const float* q_w    = (const float*)d_in[4];
    const float* q_b    = (const float*)d_in[5];
    const float* kv_w   = (const float*)d_in[6];
    const float* kv_b   = (const float*)d_in[7];
    const float* sr_w   = (const float*)d_in[8];
    const float* sr_b   = (const float*)d_in[9];
    const float* srn_w  = (const float*)d_in[10];
    const float* srn_b  = (const float*)d_in[11];
    const float* alpha  = (const float*)d_in[12];
    const float* proj_w = (const float*)d_in[13];
    const float* proj_b = (const float*)d_in[14];
    const float* ln2_w  = (const float*)d_in[15];
    const float* ln2_b  = (const float*)d_in[16];
    const float* fc1_w  = (const float*)d_in[17];
    const float* fc1_b  = (const float*)d_in[18];
    const float* dw_w   = (const float*)d_in[19];
    const float* dw_b   = (const float*)d_in[20];
    const float* fc2_w  = (const float*)d_in[21];
    const float* fc2_b  = (const float*)d_in[22];
    float* out = (float*)d_out;

    __half *h_h, *hp_h, *wtT, *hs_h, *q_h, *kv_h, *o_h, *h2_h, *m_h, *mi_h;
    __half *qT, *kvT, *pjT, *f1T, *f2T;
    float *hs, *x1, *part;
    cudaGetSymbolAddress((void**)&h_h,  g_h_h);
    cudaGetSymbolAddress((void**)&hp_h, g_hp_h);
    cudaGetSymbolAddress((void**)&wtT,  g_wtT);
    cudaGetSymbolAddress((void**)&hs,   g_hs);
    cudaGetSymbolAddress((void**)&hs_h, g_hs_h);
    cudaGetSymbolAddress((void**)&q_h,  g_q_h);
    cudaGetSymbolAddress((void**)&kv_h, g_kv_h);
    cudaGetSymbolAddress((void**)&o_h,  g_o_h);
    cudaGetSymbolAddress((void**)&x1,   g_x1);
    cudaGetSymbolAddress((void**)&h2_h, g_h2_h);
    cudaGetSymbolAddress((void**)&m_h,  g_m_h);
    cudaGetSymbolAddress((void**)&mi_h, g_mi_h);
    cudaGetSymbolAddress((void**)&part, g_part);
    cudaGetSymbolAddress((void**)&qT,   g_qT);
    cudaGetSymbolAddress((void**)&kvT,  g_kvT);
    cudaGetSymbolAddress((void**)&pjT,  g_pjT);
    cudaGetSymbolAddress((void**)&f1T,  g_f1T);
    cudaGetSymbolAddress((void**)&f2T,  g_f2T);

    static bool cfg = false;
    if (!cfg) {
        cudaFuncSetAttribute(gemm_h, cudaFuncAttributeMaxDynamicSharedMemorySize, GEMM_SMEM);
        cudaFuncSetAttribute(attn_mma, cudaFuncAttributeMaxDynamicSharedMemorySize, ATTN_SMEM);
        cfg = true;
    }

    const int ROWS = BB * NN;        // 32768
    const int ROWS_SR = BB * NK;     // 2048

    // 1. h = LN1(x) -> fp16
    ln256_h<<<ROWS / 8, 256>>>(x, ln1_w, ln1_b, h_h, ROWS, 1e-6f);
    // 2. patch gather
    patchify_h<<<(int)(((size_t)BB * NK * 16 * 128) / 256), 256>>>(
        (const uint32_t*)h_h, (uint32_t*)hp_h);
    // 3. all weight prep (one kernel)
    prep_all<<<PREP_TOTAL / 256, 256>>>(q_w, kv_w, proj_w, fc1_w, fc2_w, sr_w,
                                        qT, kvT, pjT, f1T, f2T, wtT);
    // 4. SR GEMM (split-K=8)
    gemm_h<<<dim3(CC / 128, ROWS_SR / 128, 8), 256, GEMM_SMEM>>>(hp_h, wtT, nullptr, nullptr,
                                                                 part, nullptr, ROWS_SR, CC, KPATCH, 8);
    // 5. reduce + bias
    reduceK<<<(ROWS_SR * CC / 4 + 255) / 256, 256>>>(part, sr_b, hs, ROWS_SR * CC, CC, 8);
    // 6. q = h @ q_w + q_b  (fp16 out)
    gemm_h<<<dim3(CC / 128, ROWS / 128), 256, GEMM_SMEM>>>(h_h, qT, q_b, nullptr,
                                                           nullptr, q_h, ROWS, CC, CC, 1);
    // 7. srn LN -> fp16
    ln256_h<<<ROWS_SR / 8, 256>>>(hs, srn_w, srn_b, hs_h, ROWS_SR, 1e-5f);
    // 8. kv = hs @ kv_w + kv_b (fp16 out)
    gemm_h<<<dim3((2 * CC) / 128, ROWS_SR / 128), 256, GEMM_SMEM>>>(hs_h, kvT, kv_b, nullptr,
                                                                    nullptr, kv_h, ROWS_SR, 2 * CC, CC, 1);
    // 9. tensor-core attention -> o fp16
    attn_mma<<<dim3(NN / 128, HH, BB), 256, ATTN_SMEM>>>(q_h, kv_h, pos2d, alpha, o_h);
    // 10. proj: x1 = x + o @ proj_w + proj_b
    gemm_h<<<dim3(CC / 128, ROWS / 128), 256, GEMM_SMEM>>>(o_h, pjT, proj_b, x,
                                                           x1, nullptr, ROWS, CC, CC, 1);
    // 11. h2 = LN2(x1) -> fp16
    ln256_h<<<ROWS / 8, 256>>>(x1, ln2_w, ln2_b, h2_h, ROWS, 1e-6f);
    // 12. fc1: m = h2 @ fc1_w + fc1_b (fp16 out)
    gemm_h<<<dim3(HID / 128, ROWS / 128), 256, GEMM_SMEM>>>(h2_h, f1T, fc1_b, nullptr,
                                                            nullptr, m_h, ROWS, HID, CC, 1);
    // 13. depthwise conv + gelu
    dw_gelu<<<dim3(HW, BB), 512>>>(m_h, dw_w, dw_b, mi_h);
    // 14. fc2: out = x1 + mi @ fc2_w + fc2_b
    gemm_h<<<dim3(CC / 128, ROWS / 128), 256, GEMM_SMEM>>>(mi_h, f2T, fc2_b, x1,
                                                           out, nullptr, ROWS, CC, HID, 1);
}

// round 10
// speedup vs baseline: 4.0868x; 1.0084x over previous
#include <cuda_runtime.h>
#include <cuda_fp16.h>
#include <math.h>
#include <stdint.h>

// Problem dims (fixed)
#define BB   8
#define NN   4096
#define CC   256
#define HH   8
#define DH   32
#define HW   64
#define NK   256
#define HID  1024
#define KPATCH 4096   // C * SR * SR

// ---------------- scratch (device globals; no allocation) ----------------
__device__ __half g_h_h [(size_t)BB*NN*CC];
__device__ __half g_wtT [(size_t)CC*KPATCH];
__device__ float  g_hs  [(size_t)BB*NK*CC];
__device__ __half g_hs_h[(size_t)BB*NK*CC];
__device__ __half g_q_h [(size_t)BB*NN*CC];
__device__ __half g_kv_h[(size_t)BB*NK*2*CC];
__device__ __half g_o_h [(size_t)BB*NN*CC];
__device__ float  g_x1  [(size_t)BB*NN*CC];
__device__ __half g_h2_h[(size_t)BB*NN*CC];
__device__ __half g_m_h [(size_t)BB*NN*HID];
__device__ __half g_mi_h[(size_t)BB*NN*HID];
__device__ float  g_part[(size_t)8*BB*NK*CC];   // split-K partials
// transposed weights [N x K] fp16
__device__ __half g_qT [CC*CC];
__device__ __half g_kvT[2*CC*CC];
__device__ __half g_pjT[CC*CC];
__device__ __half g_f1T[HID*CC];
__device__ __half g_f2T[CC*HID];

// ---------------- PTX helpers (legal on base compute_103 target) ----------------
__device__ __forceinline__ uint32_t smem_u32(const void* p) {
    uint32_t a;
    asm("{ .reg .u64 t; cvta.to.shared.u64 t, %1; cvt.u32.u64 %0, t; }" : "=r"(a) : "l"(p));
    return a;
}
__device__ __forceinline__ void cpasync16(uint32_t dst, const void* src) {
    asm volatile("cp.async.cg.shared.global [%0], [%1], 16;" :: "r"(dst), "l"(src) : "memory");
}
__device__ __forceinline__ void cpcommit() {
    asm volatile("cp.async.commit_group;" ::: "memory");
}
template<int Ngrp> __device__ __forceinline__ void cpwait() {
    asm volatile("cp.async.wait_group %0;" :: "n"(Ngrp) : "memory");
}
__device__ __forceinline__ void ldm4(uint32_t* r, uint32_t addr) {
    asm volatile("ldmatrix.sync.aligned.m8n8.x4.shared.b16 {%0,%1,%2,%3}, [%4];"
                 : "=r"(r[0]), "=r"(r[1]), "=r"(r[2]), "=r"(r[3]) : "r"(addr));
}
__device__ __forceinline__ void mma16816h(float* c, const uint32_t* a, const uint32_t* b) {
    asm volatile("mma.sync.aligned.m16n8k16.row.col.f32.f16.f16.f32 "
                 "{%0,%1,%2,%3}, {%4,%5,%6,%7}, {%8,%9}, {%0,%1,%2,%3};"
                 : "+f"(c[0]), "+f"(c[1]), "+f"(c[2]), "+f"(c[3])
                 : "r"(a[0]), "r"(a[1]), "r"(a[2]), "r"(a[3]), "r"(b[0]), "r"(b[1]));
}
__device__ __forceinline__ uint32_t packh2(float x, float y) {
    __half2 h = __floats2half2_rn(x, y);
    return *reinterpret_cast<uint32_t*>(&h);
}

// ---------------- fp16 tensor GEMM via mma.sync, 3-stage pipeline ----------------
// C[M,N] = A @ B^T (+bias)(+res).  A:[M,K] fp16, Bt:[N,K] fp16, K-major.
// CTA tile 128x128, BK=32, 8 warps (2 M x 4 N), warp tile 64x32.
#define GEMM_SMEM (3 * 20480)

__global__ __launch_bounds__(256, 2)
void gemm_h(const __half* __restrict__ A, const __half* __restrict__ Bt,
            const float* __restrict__ bias, const float* __restrict__ res,
            float* __restrict__ Cf, __half* __restrict__ Ch,
            int M, int N, int K, int splitK)
{
    extern __shared__ char sm[];
    uint32_t sb = smem_u32(sm);
    const int tid  = threadIdx.x;
    const int warp = tid >> 5, lane = tid & 31;
    const int n0 = blockIdx.x * 128, m0 = blockIdx.y * 128;
    const int Keff  = K / splitK;
    const int kbase = blockIdx.z * Keff;
    if (splitK > 1) Cf += (size_t)blockIdx.z * M * N;
    const int nk = Keff / 32;
    const int wm0 = (warp >> 2) * 64, wn0 = (warp & 3) * 32;

    float c[4][4][4];
#pragma unroll
    for (int i = 0; i < 4; i++)
#pragma unroll
        for (int j = 0; j < 4; j++)
#pragma unroll
            for (int k = 0; k < 4; k++) c[i][j][k] = 0.f;

    const int lrow = tid >> 2;
    const int lq   = tid & 3;

    auto load_stage = [&](int i, int s) {
        const int k0 = kbase + i * 32;
        const uint32_t st = sb + s * 20480;
#pragma unroll
        for (int e = 0; e < 2; e++) {
            int r = lrow + e * 64;
            cpasync16(st +         r * 80 + lq * 16, A  + (size_t)(m0 + r) * K + k0 + lq * 8);
            cpasync16(st + 10240 + r * 80 + lq * 16, Bt + (size_t)(n0 + r) * K + k0 + lq * 8);
        }
        cpcommit();
    };

    auto compute_stage = [&](int s) {
        const uint32_t st = sb + s * 20480;
#pragma unroll
        for (int h = 0; h < 2; h++) {
            uint32_t a[4][4], bfr[4][2];
#pragma unroll
            for (int mt = 0; mt < 4; mt++) {
                int r = wm0 + mt * 16 + (lane & 15);
                ldm4(a[mt], st + r * 80 + h * 32 + (lane >> 4) * 16);
            }
#pragma unroll
            for (int ng = 0; ng < 2; ng++) {
                int r = wn0 + ng * 16 + (lane & 15);
                uint32_t t[4];
                ldm4(t, st + 10240 + r * 80 + h * 32 + (lane >> 4) * 16);
                bfr[2*ng][0] = t[0]; bfr[2*ng][1] = t[2];
                bfr[2*ng+1][0] = t[1]; bfr[2*ng+1][1] = t[3];
            }
#pragma unroll
            for (int mt = 0; mt < 4; mt++)
#pragma unroll
                for (int nt = 0; nt < 4; nt++)
                    mma16816h(c[mt][nt], a[mt], bfr[nt]);
        }
    };

    load_stage(0, 0);
    load_stage(1, 1);
    int stage = 0;
    for (int i = 0; i < nk; i++) {
        cpwait<1>();
        __syncthreads();
        if (i + 2 < nk) {
            int s2 = stage + 2; if (s2 >= 3) s2 -= 3;
            load_stage(i + 2, s2);
        }
        compute_stage(stage);
        if (++stage == 3) stage = 0;
    }

#pragma unroll
    for (int mt = 0; mt < 4; mt++)
#pragma unroll
        for (int nt = 0; nt < 4; nt++) {
            int row = m0 + wm0 + mt * 16 + (lane >> 2);
            int col = n0 + wn0 + nt * 8 + (lane & 3) * 2;
            float v0 = c[mt][nt][0], v1 = c[mt][nt][1];
            float v2 = c[mt][nt][2], v3 = c[mt][nt][3];
            if (splitK == 1) {
                float b0 = bias[col], b1 = bias[col + 1];
                v0 += b0; v1 += b1; v2 += b0; v3 += b1;
                if (res) {
                    const float* r0 = res + (size_t)row * N + col;
                    const float* r1 = res + (size_t)(row + 8) * N + col;
                    v0 += r0[0]; v1 += r0[1]; v2 += r1[0]; v3 += r1[1];
                }
            }
            if (Ch) {
                *reinterpret_cast<__half2*>(Ch + (size_t)row * N + col)       = __floats2half2_rn(v0, v1);
                *reinterpret_cast<__half2*>(Ch + (size_t)(row + 8) * N + col) = __floats2half2_rn(v2, v3);
            } else {
                *reinterpret_cast<float2*>(Cf + (size_t)row * N + col)       = make_float2(v0, v1);
                *reinterpret_cast<float2*>(Cf + (size_t)(row + 8) * N + col) = make_float2(v2, v3);
            }
        }
}

// ---------------- SR GEMM with IMPLICIT patch gather ----------------
// A is read directly from h [B*NN, 256] fp16 via the patch address permutation:
// logical A row = b*NK + nk, logical col k = ks*256 + ci,
//   n(nk,ks) = ((nk>>4)*4 + (ks>>2))*HW + (nk&15)*4 + (ks&3)
// Within a BK=32 chunk ks is constant (k0 is 32-aligned, 256-wide ci blocks).
__global__ __launch_bounds__(256, 2)
void gemm_sr(const __half* __restrict__ Ah, const __half* __restrict__ Bt,
             float* __restrict__ Cf, int M, int N, int K, int splitK)
{
    extern __shared__ char sm[];
    uint32_t sb = smem_u32(sm);
    const int tid  = threadIdx.x;
    const int warp = tid >> 5, lane = tid & 31;
    const int n0 = blockIdx.x * 128, m0 = blockIdx.y * 128;
    const int Keff  = K / splitK;
    const int kbase = blockIdx.z * Keff;
    Cf += (size_t)blockIdx.z * M * N;
    const int nk = Keff / 32;
    const int wm0 = (warp >> 2) * 64, wn0 = (warp & 3) * 32;

    float c[4][4][4];
#pragma unroll
    for (int i = 0; i < 4; i++)
#pragma unroll
        for (int j = 0; j < 4; j++)
#pragma unroll
            for (int k = 0; k < 4; k++) c[i][j][k] = 0.f;

    const int lrow = tid >> 2;
    const int lq   = tid & 3;

    auto load_stage = [&](int i, int s) {
        const int k0 = kbase + i * 32;
        const int ks = k0 >> 8;
        const int kc = (k0 & 255) + lq * 8;
        const int ky = ks >> 2, kx = ks & 3;
        const uint32_t st = sb + s * 20480;
#pragma unroll
        for (int e = 0; e < 2; e++) {
            int r = lrow + e * 64;
            int row = m0 + r;                       // b*NK + nk
            int bb = row >> 8, nkr = row & 255;
            int n = ((nkr >> 4) * 4 + ky) * HW + (nkr & 15) * 4 + kx;
            cpasync16(st +         r * 80 + lq * 16, Ah + ((size_t)bb * NN + n) * 256 + kc);
            cpasync16(st + 10240 + r * 80 + lq * 16, Bt + (size_t)(n0 + r) * K + k0 + lq * 8);
        }
        cpcommit();
    };

    auto compute_stage = [&](int s) {
        const uint32_t st = sb + s * 20480;
#pragma unroll
        for (int h = 0; h < 2; h++) {
            uint32_t a[4][4], bfr[4][2];
#pragma unroll
            for (int mt = 0; mt < 4; mt++) {
                int r = wm0 + mt * 16 + (lane & 15);
                ldm4(a[mt], st + r * 80 + h * 32 + (lane >> 4) * 16);
            }
#pragma unroll
            for (int ng = 0; ng < 2; ng++) {
                int r = wn0 + ng * 16 + (lane & 15);
                uint32_t t[4];
                ldm4(t, st + 10240 + r * 80 + h * 32 + (lane >> 4) * 16);
                bfr[2*ng][0] = t[0]; bfr[2*ng][1] = t[2];
                bfr[2*ng+1][0] = t[1]; bfr[2*ng+1][1] = t[3];
            }
#pragma unroll
            for (int mt = 0; mt < 4; mt++)
#pragma unroll
                for (int nt = 0; nt < 4; nt++)
                    mma16816h(c[mt][nt], a[mt], bfr[nt]);
        }
    };

    load_stage(0, 0);
    load_stage(1, 1);
    int stage = 0;
    for (int i = 0; i < nk; i++) {
        cpwait<1>();
        __syncthreads();
        if (i + 2 < nk) {
            int s2 = stage + 2; if (s2 >= 3) s2 -= 3;
            load_stage(i + 2, s2);
        }
        compute_stage(stage);
        if (++stage == 3) stage = 0;
    }

#pragma unroll
    for (int mt = 0; mt < 4; mt++)
#pragma unroll
        for (int nt = 0; nt < 4; nt++) {
            int row = m0 + wm0 + mt * 16 + (lane >> 2);
            int col = n0 + wn0 + nt * 8 + (lane & 3) * 2;
            *reinterpret_cast<float2*>(Cf + (size_t)row * N + col) =
                make_float2(c[mt][nt][0], c[mt][nt][1]);
            *reinterpret_cast<float2*>(Cf + (size_t)(row + 8) * N + col) =
                make_float2(c[mt][nt][2], c[mt][nt][3]);
        }
}

// ---------------- split-K reduce (float4): out = sum_z part[z] + bias ----------------
__global__ void reduceK(const float* __restrict__ part, const float* __restrict__ bias,
                        float* __restrict__ out, int MN, int N, int S)
{
    int idx = (blockIdx.x * blockDim.x + threadIdx.x) * 4;
    if (idx >= MN) return;
    float4 s = *reinterpret_cast<const float4*>(bias + (idx & (N - 1)));
    for (int z = 0; z < S; z++) {
        float4 p = *reinterpret_cast<const float4*>(part + (size_t)z * MN + idx);
        s.x += p.x; s.y += p.y; s.z += p.z; s.w += p.w;
    }
    *reinterpret_cast<float4*>(out + idx) = s;
}

// ---------------- LayerNorm(256) -> fp16 ----------------
__global__ void ln256_h(const float* __restrict__ x, const float* __restrict__ w,
                        const float* __restrict__ b, __half* __restrict__ y,
                        int rows, float eps)
{
    int row  = blockIdx.x * 8 + (threadIdx.x >> 5);
    int lane = threadIdx.x & 31;
    if (row >= rows) return;
    const float* xr = x + (size_t)row * 256;
    float4 v0 = *reinterpret_cast<const float4*>(xr + lane * 8);
    float4 v1 = *reinterpret_cast<const float4*>(xr + lane * 8 + 4);
    float vals[8] = {v0.x, v0.y, v0.z, v0.w, v1.x, v1.y, v1.z, v1.w};
    float s = 0.f, sq = 0.f;
#pragma unroll
    for (int i = 0; i < 8; i++) { s += vals[i]; sq += vals[i] * vals[i]; }
#pragma unroll
    for (int o = 16; o > 0; o >>= 1) {
        s  += __shfl_xor_sync(0xffffffffu, s, o);
        sq += __shfl_xor_sync(0xffffffffu, sq, o);
    }
    float mean = s * (1.0f / 256.0f);
    float var  = sq * (1.0f / 256.0f) - mean * mean;
    float rs   = rsqrtf(var + eps);
    __align__(16) __half hb[8];
#pragma unroll
    for (int i = 0; i < 8; i++) {
        int c = lane * 8 + i;
        hb[i] = __float2half_rn((vals[i] - mean) * rs * w[c] + b[c]);
    }
    *reinterpret_cast<uint4*>(y + (size_t)row * 256 + lane * 8) = *reinterpret_cast<uint4*>(hb);
}

// ---------------- all weight prep in ONE kernel ----------------
#define PREP_TOTAL (65536 + 131072 + 65536 + 262144 + 262144 + 1048576)
__global__ void prep_all(const float* __restrict__ qw,  const float* __restrict__ kvw,
                         const float* __restrict__ pjw, const float* __restrict__ f1w,
                         const float* __restrict__ f2w, const float* __restrict__ srw,
                         __half* __restrict__ qT,  __half* __restrict__ kvT,
                         __half* __restrict__ pjT, __half* __restrict__ f1T,
                         __half* __restrict__ f2T, __half* __restrict__ wtT)
{
    int idx = blockIdx.x * 256 + threadIdx.x;
    if (idx < 65536) {
        int n = idx >> 8, k = idx & 255;
        qT[idx] = __float2half_rn(qw[k * 256 + n]);
        return;
    }
    idx -= 65536;
    if (idx < 131072) {
        int n = idx >> 8, k = idx & 255;
        kvT[idx] = __float2half_rn(kvw[k * 512 + n]);
        return;
    }
    idx -= 131072;
    if (idx < 65536) {
        int n = idx >> 8, k = idx & 255;
        pjT[idx] = __float2half_rn(pjw[k * 256 + n]);
        return;
    }
    idx -= 65536;
    if (idx < 262144) {
        int n = idx >> 8, k = idx & 255;
        f1T[idx] = __float2half_rn(f1w[k * 1024 + n]);
        return;
    }
    idx -= 262144;
    if (idx < 262144) {
        int n = idx >> 10, k = idx & 1023;
        f2T[idx] = __float2half_rn(f2w[k * 256 + n]);
        return;
    }
    idx -= 262144;
    {   // wtT[co][(ky*4+kx)*256+ci] = srw[co][ci][ky][kx]
        int co = idx >> 12, k = idx & 4095;
        int ks = k >> 8, ci = k & 255;
        wtT[idx] = __float2half_rn(srw[(size_t)co * KPATCH + ci * 16 + ks]);
    }
}

// ---------------- tensor-core attention ----------------
#define AT_KT 0
#define AT_QT 20480
#define AT_VT 30720
#define AT_OP 47616
#define ATTN_SMEM (47616 + 65536)

__global__ __launch_bounds__(256, 1)
void attn_mma(const __half* __restrict__ qg, const __half* __restrict__ kvg,
              const float* __restrict__ pos, const float* __restrict__ alpha,
              __half* __restrict__ og)
{
    extern __shared__ char sm[];
    uint32_t sb = smem_u32(sm);
    const int tid = threadIdx.x, warp = tid >> 5, lane = tid & 31;
    const int n0 = blockIdx.x * 128, hh = blockIdx.y, b = blockIdx.z;

    {
        const __half* kb = kvg + ((size_t)b * NK) * 512 + hh * 32;
        for (int t = tid; t < 1024; t += 256) {
            int m = t >> 2, ch = t & 3;
            uint4 v = *reinterpret_cast<const uint4*>(kb + (size_t)m * 512 + ch * 8);
            *reinterpret_cast<uint4*>(sm + AT_KT + m * 80 + ch * 16) = v;
        }
        const __half* vb = kb + 256;
        for (int t = tid; t < 1024; t += 256) {
            int m = t >> 2, ch = t & 3;
            union { uint4 u; __half h[8]; } v;
            v.u = *reinterpret_cast<const uint4*>(vb + (size_t)m * 512 + ch * 8);
#pragma unroll
            for (int j = 0; j < 8; j++)
                *reinterpret_cast<__half*>(sm + AT_VT + (ch * 8 + j) * 528 + m * 2) = v.h[j];
        }
        const __half* qb = qg + ((size_t)b * NN + n0) * 256 + hh * 32;
        for (int t = tid; t < 512; t += 256) {
            int r = t >> 2, ch = t & 3;
            uint4 v = *reinterpret_cast<const uint4*>(qb + (size_t)r * 256 + ch * 8);
            *reinterpret_cast<uint4*>(sm + AT_QT + r * 80 + ch * 16) = v;
        }
    }
    __syncthreads();

    const int wm = (warp >> 2) * 64, wn = (warp & 3) * 64, slab = warp & 3;

    float c[4][8][4];
#pragma unroll
    for (int i = 0; i < 4; i++)
#pragma unroll
        for (int j = 0; j < 8; j++)
#pragma unroll
            for (int k = 0; k < 4; k++) c[i][j][k] = 0.f;

#pragma unroll
    for (int h = 0; h < 2; h++) {
        uint32_t a[4][4], bf[8][2];
#pragma unroll
        for (int mt = 0; mt < 4; mt++) {
            int r = wm + mt * 16 + (lane & 15);
            ldm4(a[mt], sb + AT_QT + r * 80 + h * 32 + (lane >> 4) * 16);
        }
#pragma unroll
        for (int ng = 0; ng < 4; ng++) {
            int r = wn + ng * 16 + (lane & 15);
            uint32_t t[4];
            ldm4(t, sb + AT_KT + r * 80 + h * 32 + (lane >> 4) * 16);
            bf[2*ng][0] = t[0]; bf[2*ng][1] = t[2];
            bf[2*ng+1][0] = t[1]; bf[2*ng+1][1] = t[3];
        }
#pragma unroll
        for (int mt = 0; mt < 4; mt++)
#pragma unroll
            for (int nt = 0; nt < 8; nt++)
                mma16816h(c[mt][nt], a[mt], bf[nt]);
    }

    const float scale = 0.17677669529663687f;
    float a_ = alpha[0];
    float* pmax = reinterpret_cast<float*>(sm + AT_OP);
    float* psum = pmax + 512;

#pragma unroll
    for (int mt = 0; mt < 4; mt++) {
        float m1 = -1e30f, m2 = -1e30f;
#pragma unroll
        for (int nt = 0; nt < 8; nt++) {
            m1 = fmaxf(m1, fmaxf(c[mt][nt][0], c[mt][nt][1]));
            m2 = fmaxf(m2, fmaxf(c[mt][nt][2], c[mt][nt][3]));
        }
        m1 = fmaxf(m1, __shfl_xor_sync(0xffffffffu, m1, 1));
        m1 = fmaxf(m1, __shfl_xor_sync(0xffffffffu, m1, 2));
        m2 = fmaxf(m2, __shfl_xor_sync(0xffffffffu, m2, 1));
        m2 = fmaxf(m2, __shfl_xor_sync(0xffffffffu, m2, 2));
        if ((lane & 3) == 0) {
            int r1 = wm + mt * 16 + (lane >> 2);
            pmax[r1 * 4 + slab] = m1;
            pmax[(r1 + 8) * 4 + slab] = m2;
        }
    }
    __syncthreads();

#pragma unroll
    for (int mt = 0; mt < 4; mt++) {
        int r1 = wm + mt * 16 + (lane >> 2);
        float g1 = fmaxf(fmaxf(pmax[r1*4], pmax[r1*4+1]), fmaxf(pmax[r1*4+2], pmax[r1*4+3]));
        int r2 = r1 + 8;
        float g2 = fmaxf(fmaxf(pmax[r2*4], pmax[r2*4+1]), fmaxf(pmax[r2*4+2], pmax[r2*4+3]));
        float s1 = 0.f, s2 = 0.f;
#pragma unroll
        for (int nt = 0; nt < 8; nt++) {
            c[mt][nt][0] = expf((c[mt][nt][0] - g1) * scale); s1 += c[mt][nt][0];
            c[mt][nt][1] = expf((c[mt][nt][1] - g1) * scale); s1 += c[mt][nt][1];
            c[mt][nt][2] = expf((c[mt][nt][2] - g2) * scale); s2 += c[mt][nt][2];
            c[mt][nt][3] = expf((c[mt][nt][3] - g2) * scale); s2 += c[mt][nt][3];
        }
        s1 += __shfl_xor_sync(0xffffffffu, s1, 1);
        s1 += __shfl_xor_sync(0xffffffffu, s1, 2);
        s2 += __shfl_xor_sync(0xffffffffu, s2, 1);
        s2 += __shfl_xor_sync(0xffffffffu, s2, 2);
        if ((lane & 3) == 0) {
            psum[r1 * 4 + slab] = s1;
            psum[r2 * 4 + slab] = s2;
        }
    }
    __syncthreads();

    uint32_t af[4][4][4];
    const float* posb = pos + ((size_t)(b * HH + hh) * NN + n0) * NK;
#pragma unroll
    for (int mt = 0; mt < 4; mt++) {
        int r1 = wm + mt * 16 + (lane >> 2);
        int r2 = r1 + 8;
        float s1 = psum[r1*4] + psum[r1*4+1] + psum[r1*4+2] + psum[r1*4+3];
        float s2 = psum[r2*4] + psum[r2*4+1] + psum[r2*4+2] + psum[r2*4+3];
        float i1 = (1.0f - a_) / s1, i2 = (1.0f - a_) / s2;
        const float* p1 = posb + (size_t)r1 * NK + wn + (lane & 3) * 2;
        const float* p2 = posb + (size_t)r2 * NK + wn + (lane & 3) * 2;
#pragma unroll
        for (int nt = 0; nt < 8; nt++) {
            float2 q1 = *reinterpret_cast<const float2*>(p1 + nt * 8);
            float2 q2 = *reinterpret_cast<const float2*>(p2 + nt * 8);
            c[mt][nt][0] = c[mt][nt][0] * i1 + a_ * q1.x;
            c[mt][nt][1] = c[mt][nt][1] * i1 + a_ * q1.y;
            c[mt][nt][2] = c[mt][nt][2] * i2 + a_ * q2.x;
            c[mt][nt][3] = c[mt][nt][3] * i2 + a_ * q2.y;
        }
#pragma unroll
        for (int j = 0; j < 4; j++) {
            af[mt][j][0] = packh2(c[mt][2*j][0],   c[mt][2*j][1]);
            af[mt][j][1] = packh2(c[mt][2*j][2],   c[mt][2*j][3]);
            af[mt][j][2] = packh2(c[mt][2*j+1][0], c[mt][2*j+1][1]);
            af[mt][j][3] = packh2(c[mt][2*j+1][2], c[mt][2*j+1][3]);
        }
    }
    __syncthreads();

    float oc[4][4][4];
#pragma unroll
    for (int i = 0; i < 4; i++)
#pragma unroll
        for (int j = 0; j < 4; j++)
#pragma unroll
            for (int k = 0; k < 4; k++) oc[i][j][k] = 0.f;

#pragma unroll
    for (int ks = 0; ks < 4; ks++) {
        uint32_t bv[4][2];
#pragma unroll
        for (int ng = 0; ng < 2; ng++) {
            int d = ng * 16 + (lane & 15);
            uint32_t t[4];
            ldm4(t, sb + AT_VT + d * 528 + (wn + ks * 16) * 2 + (lane >> 4) * 16);
            bv[2*ng][0] = t[0]; bv[2*ng][1] = t[2];
            bv[2*ng+1][0] = t[1]; bv[2*ng+1][1] = t[3];
        }
#pragma unroll
        for (int mt = 0; mt < 4; mt++)
#pragma unroll
            for (int nt = 0; nt < 4; nt++)
                mma16816h(oc[mt][nt], af[mt][ks], bv[nt]);
    }

    float* Op = reinterpret_cast<float*>(sm + AT_OP);
#pragma unroll
    for (int mt = 0; mt < 4; mt++)
#pragma unroll
        for (int nt = 0; nt < 4; nt++) {
            int r1 = wm + mt * 16 + (lane >> 2);
            int d  = nt * 8 + (lane & 3) * 2;
            *reinterpret_cast<float2*>(Op + ((r1 * 4 + slab) * 32 + d)) =
                make_float2(oc[mt][nt][0], oc[mt][nt][1]);
            *reinterpret_cast<float2*>(Op + (((r1 + 8) * 4 + slab) * 32 + d)) =
                make_float2(oc[mt][nt][2], oc[mt][nt][3]);
        }
    __syncthreads();

    for (int t = tid; t < 4096; t += 256) {
        int r = t >> 5, d = t & 31;
        float s = Op[(r*4+0)*32+d] + Op[(r*4+1)*32+d] + Op[(r*4+2)*32+d] + Op[(r*4+3)*32+d];
        og[((size_t)b * NN + n0 + r) * 256 + hh * 32 + d] = __float2half_rn(s);
    }
}

// ---------------- depthwise 3x3 + exact GELU (fp16 in/out) ----------------
__global__ void dw_gelu(const __half* __restrict__ m, const float* __restrict__ w,
                        const float* __restrict__ bias, __half* __restrict__ mi)
{
    int y = blockIdx.x;
    int b = blockIdx.y;
    for (int idx = threadIdx.x; idx < HW * (HID / 4); idx += blockDim.x) {
        int x  = idx >> 8;
        int c4 = idx & 255;
        int c  = c4 * 4;
        float4 bi = *reinterpret_cast<const float4*>(bias + c);
        float acc[4] = {bi.x, bi.y, bi.z, bi.w};
        float wr[9][4];
#pragma unroll
        for (int tap = 0; tap < 9; tap++)
#pragma unroll
            for (int j = 0; j < 4; j++)
                wr[tap][j] = w[(c + j) * 9 + tap];
#pragma unroll
        for (int dy = -1; dy <= 1; dy++) {
            int yy = y + dy;
            if (yy < 0 || yy >= HW) continue;
#pragma unroll
            for (int dx = -1; dx <= 1; dx++) {
                int xx = x + dx;
                if (xx < 0 || xx >= HW) continue;
                int tap = (dy + 1) * 3 + (dx + 1);
                const __half2* p = reinterpret_cast<const __half2*>(
                    m + ((size_t)b * NN + yy * HW + xx) * HID + c);
                float2 f01 = __half22float2(p[0]);
                float2 f23 = __half22float2(p[1]);
                acc[0] += f01.x * wr[tap][0];
                acc[1] += f01.y * wr[tap][1];
                acc[2] += f23.x * wr[tap][2];
                acc[3] += f23.y * wr[tap][3];
            }
        }
        float gv[4];
#pragma unroll
        for (int j = 0; j < 4; j++)
            gv[j] = 0.5f * acc[j] * (1.0f + erff(acc[j] * 0.70710678118654752f));
        __half2* op = reinterpret_cast<__half2*>(mi + ((size_t)b * NN + y * HW + x) * HID + c);
        op[0] = __floats2half2_rn(gv[0], gv[1]);
        op[1] = __floats2half2_rn(gv[2], gv[3]);
    }
}

// ---------------- launch ----------------
extern "C" void kernel_launch(void* const* d_in, const int* in_sizes, int n_in,
                              void* d_out, int out_size)
{
    const float* x      = (const float*)d_in[0];
    const float* pos2d  = (const float*)d_in[1];
    const float* ln1_w  = (const float*)d_in[2];
    const float* ln1_b  = (const float*)d_in[3];
    const float* q_w    = (const float*)d_in[4];
    const float* q_b    = (const float*)d_in[5];
    const float* kv_w   = (const float*)d_in[6];
    const float* kv_b   = (const float*)d_in[7];
    const float* sr_w   = (const float*)d_in[8];
    const float* sr_b   = (const float*)d_in[9];
    const float* srn_w  = (const float*)d_in[10];
    const float* srn_b  = (const float*)d_in[11];
    const float* alpha  = (const float*)d_in[12];
    const float* proj_w = (const float*)d_in[13];
    const float* proj_b = (const float*)d_in[14];
    const float* ln2_w  = (const float*)d_in[15];
    const float* ln2_b  = (const float*)d_in[16];
    const float* fc1_w  = (const float*)d_in[17];
    const float* fc1_b  = (const float*)d_in[18];
    const float* dw_w   = (const float*)d_in[19];
    const float* dw_b   = (const float*)d_in[20];
    const float* fc2_w  = (const float*)d_in[21];
    const float* fc2_b  = (const float*)d_in[22];
    float* out = (float*)d_out;

    __half *h_h, *wtT, *hs_h, *q_h, *kv_h, *o_h, *h2_h, *m_h, *mi_h;
    __half *qT, *kvT, *pjT, *f1T, *f2T;
    float *hs, *x1, *part;
    cudaGetSymbolAddress((void**)&h_h,  g_h_h);
    cudaGetSymbolAddress((void**)&wtT,  g_wtT);
    cudaGetSymbolAddress((void**)&hs,   g_hs);
    cudaGetSymbolAddress((void**)&hs_h, g_hs_h);
    cudaGetSymbolAddress((void**)&q_h,  g_q_h);
    cudaGetSymbolAddress((void**)&kv_h, g_kv_h);
    cudaGetSymbolAddress((void**)&o_h,  g_o_h);
    cudaGetSymbolAddress((void**)&x1,   g_x1);
    cudaGetSymbolAddress((void**)&h2_h, g_h2_h);
    cudaGetSymbolAddress((void**)&m_h,  g_m_h);
    cudaGetSymbolAddress((void**)&mi_h, g_mi_h);
    cudaGetSymbolAddress((void**)&part, g_part);
    cudaGetSymbolAddress((void**)&qT,   g_qT);
    cudaGetSymbolAddress((void**)&kvT,  g_kvT);
    cudaGetSymbolAddress((void**)&pjT,  g_pjT);
    cudaGetSymbolAddress((void**)&f1T,  g_f1T);
    cudaGetSymbolAddress((void**)&f2T,  g_f2T);

    static bool cfg = false;
    if (!cfg) {
        cudaFuncSetAttribute(gemm_h,  cudaFuncAttributeMaxDynamicSharedMemorySize, GEMM_SMEM);
        cudaFuncSetAttribute(gemm_sr, cudaFuncAttributeMaxDynamicSharedMemorySize, GEMM_SMEM);
        cudaFuncSetAttribute(attn_mma, cudaFuncAttributeMaxDynamicSharedMemorySize, ATTN_SMEM);
        cfg = true;
    }

    const int ROWS = BB * NN;        // 32768
    const int ROWS_SR = BB * NK;     // 2048

    // 1. h = LN1(x) -> fp16
    ln256_h<<<ROWS / 8, 256>>>(x, ln1_w, ln1_b, h_h, ROWS, 1e-6f);
    // 2. all weight prep (one kernel)
    prep_all<<<PREP_TOTAL / 256, 256>>>(q_w, kv_w, proj_w, fc1_w, fc2_w, sr_w,
                                        qT, kvT, pjT, f1T, f2T, wtT);
    // 3. SR GEMM with implicit patch gather (split-K=8)
    gemm_sr<<<dim3(CC / 128, ROWS_SR / 128, 8), 256, GEMM_SMEM>>>(h_h, wtT, part,
                                                                  ROWS_SR, CC, KPATCH, 8);
    // 4. reduce + bias
    reduceK<<<(ROWS_SR * CC / 4 + 255) / 256, 256>>>(part, sr_b, hs, ROWS_SR * CC, CC, 8);
    // 5. q = h @ q_w + q_b  (fp16 out)
    gemm_h<<<dim3(CC / 128, ROWS / 128), 256, GEMM_SMEM>>>(h_h, qT, q_b, nullptr,
                                                           nullptr, q_h, ROWS, CC, CC, 1);
    // 6. srn LN -> fp16
    ln256_h<<<ROWS_SR / 8, 256>>>(hs, srn_w, srn_b, hs_h, ROWS_SR, 1e-5f);
    // 7. kv = hs @ kv_w + kv_b (fp16 out)
    gemm_h<<<dim3((2 * CC) / 128, ROWS_SR / 128), 256, GEMM_SMEM>>>(hs_h, kvT, kv_b, nullptr,
                                                                    nullptr, kv_h, ROWS_SR, 2 * CC, CC, 1);
    // 8. tensor-core attention -> o fp16
    attn_mma<<<dim3(NN / 128, HH, BB), 256, ATTN_SMEM>>>(q_h, kv_h, pos2d, alpha, o_h);
    // 9. proj: x1 = x + o @ proj_w + proj_b
    gemm_h<<<dim3(CC / 128, ROWS / 128), 256, GEMM_SMEM>>>(o_h, pjT, proj_b, x,
                                                           x1, nullptr, ROWS, CC, CC, 1);
    // 10. h2 = LN2(x1) -> fp16
    ln256_h<<<ROWS / 8, 256>>>(x1, ln2_w, ln2_b, h2_h, ROWS, 1e-6f);
    // 11. fc1: m = h2 @ fc1_w + fc1_b (fp16 out)
    gemm_h<<<dim3(HID / 128, ROWS / 128), 256, GEMM_SMEM>>>(h2_h, f1T, fc1_b, nullptr,
                                                            nullptr, m_h, ROWS, HID, CC, 1);
    // 12. depthwise conv + gelu
    dw_gelu<<<dim3(HW, BB), 512>>>(m_h, dw_w, dw_b, mi_h);
    // 13. fc2: out = x1 + mi @ fc2_w + fc2_b
    gemm_h<<<dim3(CC / 128, ROWS / 128), 256, GEMM_SMEM>>>(mi_h, f2T, fc2_b, x1,
                                                           out, nullptr, ROWS, CC, HID, 1);
}

// round 12
// speedup vs baseline: 5.4027x; 1.3220x over previous
#include <cuda_runtime.h>
#include <cuda_fp16.h>
#include <math.h>
#include <stdint.h>

// Problem dims (fixed)
#define BB   8
#define NN   4096
#define CC   256
#define HH   8
#define DH   32
#define HW   64
#define NK   256
#define HID  1024
#define KPATCH 4096   // C * SR * SR

// ---------------- scratch (device globals; no allocation) ----------------
__device__ __half g_h_h [(size_t)BB*NN*CC];
__device__ __half g_wtT [(size_t)CC*KPATCH];
__device__ __half g_hs_h[(size_t)BB*NK*CC];
__device__ __half g_q_h [(size_t)BB*NN*CC];
__device__ __half g_kv_h[(size_t)BB*NK*2*CC];
__device__ __half g_o_h [(size_t)BB*NN*CC];
__device__ float  g_x1  [(size_t)BB*NN*CC];
__device__ __half g_h2_h[(size_t)BB*NN*CC];
__device__ __half g_m_h [(size_t)BB*NN*HID];
__device__ __half g_mi_h[(size_t)BB*NN*HID];
__device__ float  g_part[(size_t)8*BB*NK*CC];   // split-K partials
// transposed weights [N x K] fp16
__device__ __half g_qT [CC*CC];
__device__ __half g_kvT[2*CC*CC];
__device__ __half g_pjT[CC*CC];
__device__ __half g_f1T[HID*CC];
__device__ __half g_f2T[CC*HID];

// ---------------- PTX helpers (legal on base compute_103 target) ----------------
__device__ __forceinline__ uint32_t smem_u32(const void* p) {
    uint32_t a;
    asm("{ .reg .u64 t; cvta.to.shared.u64 t, %1; cvt.u32.u64 %0, t; }" : "=r"(a) : "l"(p));
    return a;
}
__device__ __forceinline__ void cpasync16(uint32_t dst, const void* src) {
    asm volatile("cp.async.cg.shared.global [%0], [%1], 16;" :: "r"(dst), "l"(src) : "memory");
}
__device__ __forceinline__ void cpcommit() {
    asm volatile("cp.async.commit_group;" ::: "memory");
}
template<int Ngrp> __device__ __forceinline__ void cpwait() {
    asm volatile("cp.async.wait_group %0;" :: "n"(Ngrp) : "memory");
}
__device__ __forceinline__ void ldm4(uint32_t* r, uint32_t addr) {
    asm volatile("ldmatrix.sync.aligned.m8n8.x4.shared.b16 {%0,%1,%2,%3}, [%4];"
                 : "=r"(r[0]), "=r"(r[1]), "=r"(r[2]), "=r"(r[3]) : "r"(addr));
}
__device__ __forceinline__ void mma16816h(float* c, const uint32_t* a, const uint32_t* b) {
    asm volatile("mma.sync.aligned.m16n8k16.row.col.f32.f16.f16.f32 "
                 "{%0,%1,%2,%3}, {%4,%5,%6,%7}, {%8,%9}, {%0,%1,%2,%3};"
                 : "+f"(c[0]), "+f"(c[1]), "+f"(c[2]), "+f"(c[3])
                 : "r"(a[0]), "r"(a[1]), "r"(a[2]), "r"(a[3]), "r"(b[0]), "r"(b[1]));
}
__device__ __forceinline__ uint32_t packh2(float x, float y) {
    __half2 h = __floats2half2_rn(x, y);
    return *reinterpret_cast<uint32_t*>(&h);
}

// ---------------- fp16 tensor GEMM via mma.sync, 3-stage pipeline ----------------
#define GEMM_SMEM (3 * 20480)

__global__ __launch_bounds__(256, 2)
void gemm_h(const __half* __restrict__ A, const __half* __restrict__ Bt,
            const float* __restrict__ bias, const float* __restrict__ res,
            float* __restrict__ Cf, __half* __restrict__ Ch,
            int M, int N, int K, int splitK)
{
    extern __shared__ char sm[];
    uint32_t sb = smem_u32(sm);
    const int tid  = threadIdx.x;
    const int warp = tid >> 5, lane = tid & 31;
    const int n0 = blockIdx.x * 128, m0 = blockIdx.y * 128;
    const int Keff  = K / splitK;
    const int kbase = blockIdx.z * Keff;
    if (splitK > 1) Cf += (size_t)blockIdx.z * M * N;
    const int nk = Keff / 32;
    const int wm0 = (warp >> 2) * 64, wn0 = (warp & 3) * 32;

    float c[4][4][4];
#pragma unroll
    for (int i = 0; i < 4; i++)
#pragma unroll
        for (int j = 0; j < 4; j++)
#pragma unroll
            for (int k = 0; k < 4; k++) c[i][j][k] = 0.f;

    const int lrow = tid >> 2;
    const int lq   = tid & 3;

    auto load_stage = [&](int i, int s) {
        const int k0 = kbase + i * 32;
        const uint32_t st = sb + s * 20480;
#pragma unroll
        for (int e = 0; e < 2; e++) {
            int r = lrow + e * 64;
            cpasync16(st +         r * 80 + lq * 16, A  + (size_t)(m0 + r) * K + k0 + lq * 8);
            cpasync16(st + 10240 + r * 80 + lq * 16, Bt + (size_t)(n0 + r) * K + k0 + lq * 8);
        }
        cpcommit();
    };

    auto compute_stage = [&](int s) {
        const uint32_t st = sb + s * 20480;
#pragma unroll
        for (int h = 0; h < 2; h++) {
            uint32_t a[4][4], bfr[4][2];
#pragma unroll
            for (int mt = 0; mt < 4; mt++) {
                int r = wm0 + mt * 16 + (lane & 15);
                ldm4(a[mt], st + r * 80 + h * 32 + (lane >> 4) * 16);
            }
#pragma unroll
            for (int ng = 0; ng < 2; ng++) {
                int r = wn0 + ng * 16 + (lane & 15);
                uint32_t t[4];
                ldm4(t, st + 10240 + r * 80 + h * 32 + (lane >> 4) * 16);
                bfr[2*ng][0] = t[0]; bfr[2*ng][1] = t[2];
                bfr[2*ng+1][0] = t[1]; bfr[2*ng+1][1] = t[3];
            }
#pragma unroll
            for (int mt = 0; mt < 4; mt++)
#pragma unroll
                for (int nt = 0; nt < 4; nt++)
                    mma16816h(c[mt][nt], a[mt], bfr[nt]);
        }
    };

    load_stage(0, 0);
    load_stage(1, 1);
    int stage = 0;
    for (int i = 0; i < nk; i++) {
        cpwait<1>();
        __syncthreads();
        if (i + 2 < nk) {
            int s2 = stage + 2; if (s2 >= 3) s2 -= 3;
            load_stage(i + 2, s2);
        }
        compute_stage(stage);
        if (++stage == 3) stage = 0;
    }

#pragma unroll
    for (int mt = 0; mt < 4; mt++)
#pragma unroll
        for (int nt = 0; nt < 4; nt++) {
            int row = m0 + wm0 + mt * 16 + (lane >> 2);
            int col = n0 + wn0 + nt * 8 + (lane & 3) * 2;
            float v0 = c[mt][nt][0], v1 = c[mt][nt][1];
            float v2 = c[mt][nt][2], v3 = c[mt][nt][3];
            if (splitK == 1) {
                float b0 = bias[col], b1 = bias[col + 1];
                v0 += b0; v1 += b1; v2 += b0; v3 += b1;
                if (res) {
                    const float* r0 = res + (size_t)row * N + col;
                    const float* r1 = res + (size_t)(row + 8) * N + col;
                    v0 += r0[0]; v1 += r0[1]; v2 += r1[0]; v3 += r1[1];
                }
            }
            if (Ch) {
                *reinterpret_cast<__half2*>(Ch + (size_t)row * N + col)       = __floats2half2_rn(v0, v1);
                *reinterpret_cast<__half2*>(Ch + (size_t)(row + 8) * N + col) = __floats2half2_rn(v2, v3);
            } else {
                *reinterpret_cast<float2*>(Cf + (size_t)row * N + col)       = make_float2(v0, v1);
                *reinterpret_cast<float2*>(Cf + (size_t)(row + 8) * N + col) = make_float2(v2, v3);
            }
        }
}

// ---------------- SR GEMM with IMPLICIT patch gather ----------------
__global__ __launch_bounds__(256, 2)
void gemm_sr(const __half* __restrict__ Ah, const __half* __restrict__ Bt,
             float* __restrict__ Cf, int M, int N, int K, int splitK)
{
    extern __shared__ char sm[];
    uint32_t sb = smem_u32(sm);
    const int tid  = threadIdx.x;
    const int warp = tid >> 5, lane = tid & 31;
    const int n0 = blockIdx.x * 128, m0 = blockIdx.y * 128;
    const int Keff  = K / splitK;
    const int kbase = blockIdx.z * Keff;
    Cf += (size_t)blockIdx.z * M * N;
    const int nk = Keff / 32;
    const int wm0 = (warp >> 2) * 64, wn0 = (warp & 3) * 32;

    float c[4][4][4];
#pragma unroll
    for (int i = 0; i < 4; i++)
#pragma unroll
        for (int j = 0; j < 4; j++)
#pragma unroll
            for (int k = 0; k < 4; k++) c[i][j][k] = 0.f;

    const int lrow = tid >> 2;
    const int lq   = tid & 3;

    auto load_stage = [&](int i, int s) {
        const int k0 = kbase + i * 32;
        const int ks = k0 >> 8;
        const int kc = (k0 & 255) + lq * 8;
        const int ky = ks >> 2, kx = ks & 3;
        const uint32_t st = sb + s * 20480;
#pragma unroll
        for (int e = 0; e < 2; e++) {
            int r = lrow + e * 64;
            int row = m0 + r;
            int bb = row >> 8, nkr = row & 255;
            int n = ((nkr >> 4) * 4 + ky) * HW + (nkr & 15) * 4 + kx;
            cpasync16(st +         r * 80 + lq * 16, Ah + ((size_t)bb * NN + n) * 256 + kc);
            cpasync16(st + 10240 + r * 80 + lq * 16, Bt + (size_t)(n0 + r) * K + k0 + lq * 8);
        }
        cpcommit();
    };

    auto compute_stage = [&](int s) {
        const uint32_t st = sb + s * 20480;
#pragma unroll
        for (int h = 0; h < 2; h++) {
            uint32_t a[4][4], bfr[4][2];
#pragma unroll
            for (int mt = 0; mt < 4; mt++) {
                int r = wm0 + mt * 16 + (lane & 15);
                ldm4(a[mt], st + r * 80 + h * 32 + (lane >> 4) * 16);
            }
#pragma unroll
            for (int ng = 0; ng < 2; ng++) {
                int r = wn0 + ng * 16 + (lane & 15);
                uint32_t t[4];
                ldm4(t, st + 10240 + r * 80 + h * 32 + (lane >> 4) * 16);
                bfr[2*ng][0] = t[0]; bfr[2*ng][1] = t[2];
                bfr[2*ng+1][0] = t[1]; bfr[2*ng+1][1] = t[3];
            }
#pragma unroll
            for (int mt = 0; mt < 4; mt++)
#pragma unroll
                for (int nt = 0; nt < 4; nt++)
                    mma16816h(c[mt][nt], a[mt], bfr[nt]);
        }
    };

    load_stage(0, 0);
    load_stage(1, 1);
    int stage = 0;
    for (int i = 0; i < nk; i++) {
        cpwait<1>();
        __syncthreads();
        if (i + 2 < nk) {
            int s2 = stage + 2; if (s2 >= 3) s2 -= 3;
            load_stage(i + 2, s2);
        }
        compute_stage(stage);
        if (++stage == 3) stage = 0;
    }

#pragma unroll
    for (int mt = 0; mt < 4; mt++)
#pragma unroll
        for (int nt = 0; nt < 4; nt++) {
            int row = m0 + wm0 + mt * 16 + (lane >> 2);
            int col = n0 + wn0 + nt * 8 + (lane & 3) * 2;
            *reinterpret_cast<float2*>(Cf + (size_t)row * N + col) =
                make_float2(c[mt][nt][0], c[mt][nt][1]);
            *reinterpret_cast<float2*>(Cf + (size_t)(row + 8) * N + col) =
                make_float2(c[mt][nt][2], c[mt][nt][3]);
        }
}

// ---------------- fused split-K reduce + bias + srn LayerNorm -> fp16 ----------------
// rows = 2048, warp per row. vals = sr_b + sum_z part[z]; then LN(srn) -> hs_h.
__global__ void reduce_ln(const float* __restrict__ part, const float* __restrict__ cbias,
                          const float* __restrict__ w, const float* __restrict__ b,
                          __half* __restrict__ y, int MN, float eps)
{
    int row  = blockIdx.x * 8 + (threadIdx.x >> 5);
    int lane = threadIdx.x & 31;
    int c0 = lane * 8;
    float vals[8];
    {
        float4 b0 = *reinterpret_cast<const float4*>(cbias + c0);
        float4 b1 = *reinterpret_cast<const float4*>(cbias + c0 + 4);
        vals[0] = b0.x; vals[1] = b0.y; vals[2] = b0.z; vals[3] = b0.w;
        vals[4] = b1.x; vals[5] = b1.y; vals[6] = b1.z; vals[7] = b1.w;
    }
    for (int z = 0; z < 8; z++) {
        const float* p = part + (size_t)z * MN + (size_t)row * 256 + c0;
        float4 p0 = *reinterpret_cast<const float4*>(p);
        float4 p1 = *reinterpret_cast<const float4*>(p + 4);
        vals[0] += p0.x; vals[1] += p0.y; vals[2] += p0.z; vals[3] += p0.w;
        vals[4] += p1.x; vals[5] += p1.y; vals[6] += p1.z; vals[7] += p1.w;
    }
    float s = 0.f, sq = 0.f;
#pragma unroll
    for (int i = 0; i < 8; i++) { s += vals[i]; sq += vals[i] * vals[i]; }
#pragma unroll
    for (int o = 16; o > 0; o >>= 1) {
        s  += __shfl_xor_sync(0xffffffffu, s, o);
        sq += __shfl_xor_sync(0xffffffffu, sq, o);
    }
    float mean = s * (1.0f / 256.0f);
    float var  = sq * (1.0f / 256.0f) - mean * mean;
    float rs   = rsqrtf(var + eps);
    __align__(16) __half hb[8];
#pragma unroll
    for (int i = 0; i < 8; i++) {
        int c = c0 + i;
        hb[i] = __float2half_rn((vals[i] - mean) * rs * w[c] + b[c]);
    }
    *reinterpret_cast<uint4*>(y + (size_t)row * 256 + c0) = *reinterpret_cast<uint4*>(hb);
}

// ---------------- LayerNorm(256) -> fp16 ----------------
__global__ void ln256_h(const float* __restrict__ x, const float* __restrict__ w,
                        const float* __restrict__ b, __half* __restrict__ y,
                        int rows, float eps)
{
    int row  = blockIdx.x * 8 + (threadIdx.x >> 5);
    int lane = threadIdx.x & 31;
    if (row >= rows) return;
    const float* xr = x + (size_t)row * 256;
    float4 v0 = *reinterpret_cast<const float4*>(xr + lane * 8);
    float4 v1 = *reinterpret_cast<const float4*>(xr + lane * 8 + 4);
    float vals[8] = {v0.x, v0.y, v0.z, v0.w, v1.x, v1.y, v1.z, v1.w};
    float s = 0.f, sq = 0.f;
#pragma unroll
    for (int i = 0; i < 8; i++) { s += vals[i]; sq += vals[i] * vals[i]; }
#pragma unroll
    for (int o = 16; o > 0; o >>= 1) {
        s  += __shfl_xor_sync(0xffffffffu, s, o);
        sq += __shfl_xor_sync(0xffffffffu, sq, o);
    }
    float mean = s * (1.0f / 256.0f);
    float var  = sq * (1.0f / 256.0f) - mean * mean;
    float rs   = rsqrtf(var + eps);
    __align__(16) __half hb[8];
#pragma unroll
    for (int i = 0; i < 8; i++) {
        int c = lane * 8 + i;
        hb[i] = __float2half_rn((vals[i] - mean) * rs * w[c] + b[c]);
    }
    *reinterpret_cast<uint4*>(y + (size_t)row * 256 + lane * 8) = *reinterpret_cast<uint4*>(hb);
}

// ---------------- all weight prep in ONE kernel ----------------
#define PREP_TOTAL (65536 + 131072 + 65536 + 262144 + 262144 + 1048576)
__global__ void prep_all(const float* __restrict__ qw,  const float* __restrict__ kvw,
                         const float* __restrict__ pjw, const float* __restrict__ f1w,
                         const float* __restrict__ f2w, const float* __restrict__ srw,
                         __half* __restrict__ qT,  __half* __restrict__ kvT,
                         __half* __restrict__ pjT, __half* __restrict__ f1T,
                         __half* __restrict__ f2T, __half* __restrict__ wtT)
{
    int idx = blockIdx.x * 256 + threadIdx.x;
    if (idx < 65536) {
        int n = idx >> 8, k = idx & 255;
        qT[idx] = __float2half_rn(qw[k * 256 + n]);
        return;
    }
    idx -= 65536;
    if (idx < 131072) {
        int n = idx >> 8, k = idx & 255;
        kvT[idx] = __float2half_rn(kvw[k * 512 + n]);
        return;
    }
    idx -= 131072;
    if (idx < 65536) {
        int n = idx >> 8, k = idx & 255;
        pjT[idx] = __float2half_rn(pjw[k * 256 + n]);
        return;
    }
    idx -= 65536;
    if (idx < 262144) {
        int n = idx >> 8, k = idx & 255;
        f1T[idx] = __float2half_rn(f1w[k * 1024 + n]);
        return;
    }
    idx -= 262144;
    if (idx < 262144) {
        int n = idx >> 10, k = idx & 1023;
        f2T[idx] = __float2half_rn(f2w[k * 256 + n]);
        return;
    }
    idx -= 262144;
    {
        int co = idx >> 12, k = idx & 4095;
        int ks = k >> 8, ci = k & 255;
        wtT[idx] = __float2half_rn(srw[(size_t)co * KPATCH + ci * 16 + ks]);
    }
}

// ---------------- tensor-core attention, 64 q-row tiles, 2 CTAs/SM ----------------
// per CTA: (b, h, 64 q rows). 8 warps: 2 warp-rows (32 q) x 4 k-slabs (64 k each).
// smem: KT [256][40h]=20480 | QT [64][40h]=5120 | VT [32][264h]=16896 | Opart 64*4*32 f32=32768
#define AT_KT 0
#define AT_QT 20480
#define AT_VT 25600
#define AT_OP 42496
#define ATTN_SMEM (42496 + 32768)

__global__ __launch_bounds__(256, 2)
void attn_mma(const __half* __restrict__ qg, const __half* __restrict__ kvg,
              const float* __restrict__ pos, const float* __restrict__ alpha,
              __half* __restrict__ og)
{
    extern __shared__ char sm[];
    uint32_t sb = smem_u32(sm);
    const int tid = threadIdx.x, warp = tid >> 5, lane = tid & 31;
    const int n0 = blockIdx.x * 64, hh = blockIdx.y, b = blockIdx.z;

    {
        const __half* kb = kvg + ((size_t)b * NK) * 512 + hh * 32;
        for (int t = tid; t < 1024; t += 256) {
            int m = t >> 2, ch = t & 3;
            uint4 v = *reinterpret_cast<const uint4*>(kb + (size_t)m * 512 + ch * 8);
            *reinterpret_cast<uint4*>(sm + AT_KT + m * 80 + ch * 16) = v;
        }
        const __half* vb = kb + 256;
        for (int t = tid; t < 1024; t += 256) {
            int m = t >> 2, ch = t & 3;
            union { uint4 u; __half h[8]; } v;
            v.u = *reinterpret_cast<const uint4*>(vb + (size_t)m * 512 + ch * 8);
#pragma unroll
            for (int j = 0; j < 8; j++)
                *reinterpret_cast<__half*>(sm + AT_VT + (ch * 8 + j) * 528 + m * 2) = v.h[j];
        }
        const __half* qb = qg + ((size_t)b * NN + n0) * 256 + hh * 32;
        for (int t = tid; t < 256; t += 256) {
            int r = t >> 2, ch = t & 3;
            uint4 v = *reinterpret_cast<const uint4*>(qb + (size_t)r * 256 + ch * 8);
            *reinterpret_cast<uint4*>(sm + AT_QT + r * 80 + ch * 16) = v;
        }
    }
    __syncthreads();

    const int wm = (warp >> 2) * 32, wn = (warp & 3) * 64, slab = warp & 3;

    // ---- phase 1: S = Q @ K^T ----
    float c[2][8][4];
#pragma unroll
    for (int i = 0; i < 2; i++)
#pragma unroll
        for (int j = 0; j < 8; j++)
#pragma unroll
            for (int k = 0; k < 4; k++) c[i][j][k] = 0.f;

#pragma unroll
    for (int h = 0; h < 2; h++) {
        uint32_t a[2][4], bf[8][2];
#pragma unroll
        for (int mt = 0; mt < 2; mt++) {
            int r = wm + mt * 16 + (lane & 15);
            ldm4(a[mt], sb + AT_QT + r * 80 + h * 32 + (lane >> 4) * 16);
        }
#pragma unroll
        for (int ng = 0; ng < 4; ng++) {
            int r = wn + ng * 16 + (lane & 15);
            uint32_t t[4];
            ldm4(t, sb + AT_KT + r * 80 + h * 32 + (lane >> 4) * 16);
            bf[2*ng][0] = t[0]; bf[2*ng][1] = t[2];
            bf[2*ng+1][0] = t[1]; bf[2*ng+1][1] = t[3];
        }
#pragma unroll
        for (int mt = 0; mt < 2; mt++)
#pragma unroll
            for (int nt = 0; nt < 8; nt++)
                mma16816h(c[mt][nt], a[mt], bf[nt]);
    }

    // ---- phase 2: softmax on fragments ----
    const float scale = 0.17677669529663687f;
    float a_ = alpha[0];
    float* pmax = reinterpret_cast<float*>(sm + AT_OP);   // 256 floats
    float* psum = pmax + 256;                             // 256 floats

#pragma unroll
    for (int mt = 0; mt < 2; mt++) {
        float m1 = -1e30f, m2 = -1e30f;
#pragma unroll
        for (int nt = 0; nt < 8; nt++) {
            m1 = fmaxf(m1, fmaxf(c[mt][nt][0], c[mt][nt][1]));
            m2 = fmaxf(m2, fmaxf(c[mt][nt][2], c[mt][nt][3]));
        }
        m1 = fmaxf(m1, __shfl_xor_sync(0xffffffffu, m1, 1));
        m1 = fmaxf(m1, __shfl_xor_sync(0xffffffffu, m1, 2));
        m2 = fmaxf(m2, __shfl_xor_sync(0xffffffffu, m2, 1));
        m2 = fmaxf(m2, __shfl_xor_sync(0xffffffffu, m2, 2));
        if ((lane & 3) == 0) {
            int r1 = wm + mt * 16 + (lane >> 2);
            pmax[r1 * 4 + slab] = m1;
            pmax[(r1 + 8) * 4 + slab] = m2;
        }
    }
    __syncthreads();

#pragma unroll
    for (int mt = 0; mt < 2; mt++) {
        int r1 = wm + mt * 16 + (lane >> 2);
        float g1 = fmaxf(fmaxf(pmax[r1*4], pmax[r1*4+1]), fmaxf(pmax[r1*4+2], pmax[r1*4+3]));
        int r2 = r1 + 8;
        float g2 = fmaxf(fmaxf(pmax[r2*4], pmax[r2*4+1]), fmaxf(pmax[r2*4+2], pmax[r2*4+3]));
        float s1 = 0.f, s2 = 0.f;
#pragma unroll
        for (int nt = 0; nt < 8; nt++) {
            c[mt][nt][0] = expf((c[mt][nt][0] - g1) * scale); s1 += c[mt][nt][0];
            c[mt][nt][1] = expf((c[mt][nt][1] - g1) * scale); s1 += c[mt][nt][1];
            c[mt][nt][2] = expf((c[mt][nt][2] - g2) * scale); s2 += c[mt][nt][2];
            c[mt][nt][3] = expf((c[mt][nt][3] - g2) * scale); s2 += c[mt][nt][3];
        }
        s1 += __shfl_xor_sync(0xffffffffu, s1, 1);
        s1 += __shfl_xor_sync(0xffffffffu, s1, 2);
        s2 += __shfl_xor_sync(0xffffffffu, s2, 1);
        s2 += __shfl_xor_sync(0xffffffffu, s2, 2);
        if ((lane & 3) == 0) {
            psum[r1 * 4 + slab] = s1;
            psum[r2 * 4 + slab] = s2;
        }
    }
    __syncthreads();

    // normalize + blend pos + pack to A-fragments
    uint32_t af[2][4][4];
    const float* posb = pos + ((size_t)(b * HH + hh) * NN + n0) * NK;
#pragma unroll
    for (int mt = 0; mt < 2; mt++) {
        int r1 = wm + mt * 16 + (lane >> 2);
        int r2 = r1 + 8;
        float s1 = psum[r1*4] + psum[r1*4+1] + psum[r1*4+2] + psum[r1*4+3];
        float s2 = psum[r2*4] + psum[r2*4+1] + psum[r2*4+2] + psum[r2*4+3];
        float i1 = (1.0f - a_) / s1, i2 = (1.0f - a_) / s2;
        const float* p1 = posb + (size_t)r1 * NK + wn + (lane & 3) * 2;
        const float* p2 = posb + (size_t)r2 * NK + wn + (lane & 3) * 2;
#pragma unroll
        for (int nt = 0; nt < 8; nt++) {
            float2 q1 = *reinterpret_cast<const float2*>(p1 + nt * 8);
            float2 q2 = *reinterpret_cast<const float2*>(p2 + nt * 8);
            c[mt][nt][0] = c[mt][nt][0] * i1 + a_ * q1.x;
            c[mt][nt][1] = c[mt][nt][1] * i1 + a_ * q1.y;
            c[mt][nt][2] = c[mt][nt][2] * i2 + a_ * q2.x;
            c[mt][nt][3] = c[mt][nt][3] * i2 + a_ * q2.y;
        }
#pragma unroll
        for (int j = 0; j < 4; j++) {
            af[mt][j][0] = packh2(c[mt][2*j][0],   c[mt][2*j][1]);
            af[mt][j][1] = packh2(c[mt][2*j][2],   c[mt][2*j][3]);
            af[mt][j][2] = packh2(c[mt][2*j+1][0], c[mt][2*j+1][1]);
            af[mt][j][3] = packh2(c[mt][2*j+1][2], c[mt][2*j+1][3]);
        }
    }
    __syncthreads();

    // ---- phase 3: O_partial = P_slab @ V_slab ----
    float oc[2][4][4];
#pragma unroll
    for (int i = 0; i < 2; i++)
#pragma unroll
        for (int j = 0; j < 4; j++)
#pragma unroll
            for (int k = 0; k < 4; k++) oc[i][j][k] = 0.f;

#pragma unroll
    for (int ks = 0; ks < 4; ks++) {
        uint32_t bv[4][2];
#pragma unroll
        for (int ng = 0; ng < 2; ng++) {
            int d = ng * 16 + (lane & 15);
            uint32_t t[4];
            ldm4(t, sb + AT_VT + d * 528 + (wn + ks * 16) * 2 + (lane >> 4) * 16);
            bv[2*ng][0] = t[0]; bv[2*ng][1] = t[2];
            bv[2*ng+1][0] = t[1]; bv[2*ng+1][1] = t[3];
        }
#pragma unroll
        for (int mt = 0; mt < 2; mt++)
#pragma unroll
            for (int nt = 0; nt < 4; nt++)
                mma16816h(oc[mt][nt], af[mt][ks], bv[nt]);
    }

    float* Op = reinterpret_cast<float*>(sm + AT_OP);
#pragma unroll
    for (int mt = 0; mt < 2; mt++)
#pragma unroll
        for (int nt = 0; nt < 4; nt++) {
            int r1 = wm + mt * 16 + (lane >> 2);
            int d  = nt * 8 + (lane & 3) * 2;
            *reinterpret_cast<float2*>(Op + ((r1 * 4 + slab) * 32 + d)) =
                make_float2(oc[mt][nt][0], oc[mt][nt][1]);
            *reinterpret_cast<float2*>(Op + (((r1 + 8) * 4 + slab) * 32 + d)) =
                make_float2(oc[mt][nt][2], oc[mt][nt][3]);
        }
    __syncthreads();

    for (int t = tid; t < 2048; t += 256) {
        int r = t >> 5, d = t & 31;
        float s = Op[(r*4+0)*32+d] + Op[(r*4+1)*32+d] + Op[(r*4+2)*32+d] + Op[(r*4+3)*32+d];
        og[((size_t)b * NN + n0 + r) * 256 + hh * 32 + d] = __float2half_rn(s);
    }
}

// ---------------- depthwise 3x3 + exact GELU (weights staged in smem) ----------------
__global__ void dw_gelu(const __half* __restrict__ m, const float* __restrict__ w,
                        const float* __restrict__ bias, __half* __restrict__ mi)
{
    __shared__ float wsm[HID * 9];
    __shared__ float bsm[HID];
    int y = blockIdx.x;
    int b = blockIdx.y;
    for (int i = threadIdx.x; i < HID * 9; i += blockDim.x) wsm[i] = w[i];
    for (int i = threadIdx.x; i < HID; i += blockDim.x) bsm[i] = bias[i];
    __syncthreads();

    for (int idx = threadIdx.x; idx < HW * (HID / 4); idx += blockDim.x) {
        int x  = idx >> 8;
        int c4 = idx & 255;
        int c  = c4 * 4;
        float acc[4] = {bsm[c], bsm[c+1], bsm[c+2], bsm[c+3]};
#pragma unroll
        for (int dy = -1; dy <= 1; dy++) {
            int yy = y + dy;
            if (yy < 0 || yy >= HW) continue;
#pragma unroll
            for (int dx = -1; dx <= 1; dx++) {
                int xx = x + dx;
                if (xx < 0 || xx >= HW) continue;
                int tap = (dy + 1) * 3 + (dx + 1);
                const __half2* p = reinterpret_cast<const __half2*>(
                    m + ((size_t)b * NN + yy * HW + xx) * HID + c);
                float2 f01 = __half22float2(p[0]);
                float2 f23 = __half22float2(p[1]);
                acc[0] += f01.x * wsm[(c + 0) * 9 + tap];
                acc[1] += f01.y * wsm[(c + 1) * 9 + tap];
                acc[2] += f23.x * wsm[(c + 2) * 9 + tap];
                acc[3] += f23.y * wsm[(c + 3) * 9 + tap];
            }
        }
        float gv[4];
#pragma unroll
        for (int j = 0; j < 4; j++)
            gv[j] = 0.5f * acc[j] * (1.0f + erff(acc[j] * 0.70710678118654752f));
        __half2* op = reinterpret_cast<__half2*>(mi + ((size_t)b * NN + y * HW + x) * HID + c);
        op[0] = __floats2half2_rn(gv[0], gv[1]);
        op[1] = __floats2half2_rn(gv[2], gv[3]);
    }
}

// ---------------- launch ----------------
extern "C" void kernel_launch(void* const* d_in, const int* in_sizes, int n_in,
                              void* d_out, int out_size)
{
    const float* x      = (const float*)d_in[0];
    const float* pos2d  = (const float*)d_in[1];
    const float* ln1_w  = (const float*)d_in[2];
    const float* ln1_b  = (const float*)d_in[3];
    const float* q_w    = (const float*)d_in[4];
    const float* q_b    = (const float*)d_in[5];
    const float* kv_w   = (const float*)d_in[6];
    const float* kv_b   = (const float*)d_in[7];
    const float* sr_w   = (const float*)d_in[8];
    const float* sr_b   = (const float*)d_in[9];
    const float* srn_w  = (const float*)d_in[10];
    const float* srn_b  = (const float*)d_in[11];
    const float* alpha  = (const float*)d_in[12];
    const float* proj_w = (const float*)d_in[13];
    const float* proj_b = (const float*)d_in[14];
    const float* ln2_w  = (const float*)d_in[15];
    const float* ln2_b  = (const float*)d_in[16];
    const float* fc1_w  = (const float*)d_in[17];
    const float* fc1_b  = (const float*)d_in[18];
    const float* dw_w   = (const float*)d_in[19];
    const float* dw_b   = (const float*)d_in[20];
    const float* fc2_w  = (const float*)d_in[21];
    const float* fc2_b  = (const float*)d_in[22];
    float* out = (float*)d_out;

    __half *h_h, *wtT, *hs_h, *q_h, *kv_h, *o_h, *h2_h, *m_h, *mi_h;
    __half *qT, *kvT, *pjT, *f1T, *f2T;
    float *x1, *part;
    cudaGetSymbolAddress((void**)&h_h,  g_h_h);
    cudaGetSymbolAddress((void**)&wtT,  g_wtT);
    cudaGetSymbolAddress((void**)&hs_h, g_hs_h);
    cudaGetSymbolAddress((void**)&q_h,  g_q_h);
    cudaGetSymbolAddress((void**)&kv_h, g_kv_h);
    cudaGetSymbolAddress((void**)&o_h,  g_o_h);
    cudaGetSymbolAddress((void**)&x1,   g_x1);
    cudaGetSymbolAddress((void**)&h2_h, g_h2_h);
    cudaGetSymbolAddress((void**)&m_h,  g_m_h);
    cudaGetSymbolAddress((void**)&mi_h, g_mi_h);
    cudaGetSymbolAddress((void**)&part, g_part);
    cudaGetSymbolAddress((void**)&qT,   g_qT);
    cudaGetSymbolAddress((void**)&kvT,  g_kvT);
    cudaGetSymbolAddress((void**)&pjT,  g_pjT);
    cudaGetSymbolAddress((void**)&f1T,  g_f1T);
    cudaGetSymbolAddress((void**)&f2T,  g_f2T);

    static bool cfg = false;
    if (!cfg) {
        cudaFuncSetAttribute(gemm_h,  cudaFuncAttributeMaxDynamicSharedMemorySize, GEMM_SMEM);
        cudaFuncSetAttribute(gemm_sr, cudaFuncAttributeMaxDynamicSharedMemorySize, GEMM_SMEM);
        cudaFuncSetAttribute(attn_mma, cudaFuncAttributeMaxDynamicSharedMemorySize, ATTN_SMEM);
        cfg = true;
    }

    const int ROWS = BB * NN;        // 32768
    const int ROWS_SR = BB * NK;     // 2048

    // 1. h = LN1(x) -> fp16
    ln256_h<<<ROWS / 8, 256>>>(x, ln1_w, ln1_b, h_h, ROWS, 1e-6f);
    // 2. all weight prep (one kernel)
    prep_all<<<PREP_TOTAL / 256, 256>>>(q_w, kv_w, proj_w, fc1_w, fc2_w, sr_w,
                                        qT, kvT, pjT, f1T, f2T, wtT);
    // 3. SR GEMM with implicit patch gather (split-K=8)
    gemm_sr<<<dim3(CC / 128, ROWS_SR / 128, 8), 256, GEMM_SMEM>>>(h_h, wtT, part,
                                                                  ROWS_SR, CC, KPATCH, 8);
    // 4. fused reduce + bias + srn LN -> fp16
    reduce_ln<<<ROWS_SR / 8, 256>>>(part, sr_b, srn_w, srn_b, hs_h, ROWS_SR * CC, 1e-5f);
    // 5. q = h @ q_w + q_b  (fp16 out)
    gemm_h<<<dim3(CC / 128, ROWS / 128), 256, GEMM_SMEM>>>(h_h, qT, q_b, nullptr,
                                                           nullptr, q_h, ROWS, CC, CC, 1);
    // 6. kv = hs @ kv_w + kv_b (fp16 out)
    gemm_h<<<dim3((2 * CC) / 128, ROWS_SR / 128), 256, GEMM_SMEM>>>(hs_h, kvT, kv_b, nullptr,
                                                                    nullptr, kv_h, ROWS_SR, 2 * CC, CC, 1);
    // 7. tensor-core attention (64-row tiles) -> o fp16
    attn_mma<<<dim3(NN / 64, HH, BB), 256, ATTN_SMEM>>>(q_h, kv_h, pos2d, alpha, o_h);
    // 8. proj: x1 = x + o @ proj_w + proj_b
    gemm_h<<<dim3(CC / 128, ROWS / 128), 256, GEMM_SMEM>>>(o_h, pjT, proj_b, x,
                                                           x1, nullptr, ROWS, CC, CC, 1);
    // 9. h2 = LN2(x1) -> fp16
    ln256_h<<<ROWS / 8, 256>>>(x1, ln2_w, ln2_b, h2_h, ROWS, 1e-6f);
    // 10. fc1: m = h2 @ fc1_w + fc1_b (fp16 out)
    gemm_h<<<dim3(HID / 128, ROWS / 128), 256, GEMM_SMEM>>>(h2_h, f1T, fc1_b, nullptr,
                                                            nullptr, m_h, ROWS, HID, CC, 1);
    // 11. depthwise conv + gelu
    dw_gelu<<<dim3(HW, BB), 512>>>(m_h, dw_w, dw_b, mi_h);
    // 12. fc2: out = x1 + mi @ fc2_w + fc2_b
    gemm_h<<<dim3(CC / 128, ROWS / 128), 256, GEMM_SMEM>>>(mi_h, f2T, fc2_b, x1,
                                                           out, nullptr, ROWS, CC, HID, 1);
}